// round 12
// baseline (speedup 1.0000x reference)
#include <cuda_runtime.h>
#include <cuda_bf16.h>
#include <math.h>
#include <float.h>
#include <stdint.h>

#define N_TOK 2048
#define HID   2048
#define HQ    16
#define D     128
#define NC    64
#define KS    32
#define STRIDE 32
#define BSZ   32
#define TOPK  8
#define WIN   512
#define SCALE 0.08838834764831845f  /* 1/sqrt(128) */
#define NEGF  -1e30f

// ---------------- scratch (device globals) ---------------------------------
__device__ float g_q   [N_TOK*HQ*D];
__device__ float g_k   [N_TOK*D];
__device__ float g_v   [N_TOK*D];
__device__ float g_ck  [NC*D];
__device__ float g_ckT [D*NC];
__device__ float g_cv  [NC*D];
__device__ float g_blks[N_TOK*NC];
__device__ int   g_topk[N_TOK*TOPK];
__device__ float g_cmp [N_TOK*HQ*D];
__device__ float g_sp  [N_TOK*HQ*D];
__device__ float g_sw  [N_TOK*HQ*D];
__device__ float g_gate[N_TOK*HQ*3];
__device__ float g_part [8 * N_TOK * 128];
__device__ float g_partG[8 * N_TOK * 48];

// ---------------- tf32 helpers ----------------------------------------------
__device__ __forceinline__ uint32_t f2tf32(float f) {
    uint32_t u;
    asm("cvt.rna.tf32.f32 %0, %1;" : "=r"(u) : "f"(f));
    return u;
}
__device__ __forceinline__ void mma_tf32(float* c, const uint32_t* a,
                                         uint32_t b0, uint32_t b1) {
    asm volatile(
        "mma.sync.aligned.m16n8k8.row.col.f32.tf32.tf32.f32 "
        "{%0,%1,%2,%3}, {%4,%5,%6,%7}, {%8,%9}, {%0,%1,%2,%3};"
        : "+f"(c[0]), "+f"(c[1]), "+f"(c[2]), "+f"(c[3])
        : "r"(a[0]), "r"(a[1]), "r"(a[2]), "r"(a[3]), "r"(b0), "r"(b1));
}

// ---------------- tf32 GEMM: C[rows,M]=A[rows,K]@B[K,M] ----------------------
template<int TERMS>
__global__ void __launch_bounds__(256, 2)
gemm_kernel(const float* __restrict__ A, const float* __restrict__ B,
            float* __restrict__ C, float* __restrict__ Cpart, int K, int M)
{
    extern __shared__ uint2 sm[];
    uint2* AsH = sm;
    uint2* BsH = sm + 2048;
    uint2* AsL = sm + 4096;
    uint2* BsL = sm + 6144;

    const int tid = threadIdx.x;
    const int wid = tid >> 5, lane = tid & 31;
    const int row0 = blockIdx.y * 128, col0 = blockIdx.x * 128;
    const int wr = (wid & 1) * 64, wc = (wid >> 1) * 32;
    const int g = lane >> 2, tg = lane & 3;
    const int S = gridDim.z, Kc = K / S, kbeg = blockIdx.z * Kc;

    const int arow = tid >> 1, akb = (tid & 1) * 8;
    const int bkrow = tid >> 4, bcol = (tid & 15) * 8;
    const bool bval0 = (col0 + bcol + 4) <= M;
    const bool bval1 = (col0 + bcol + 8) <= M;

    const float* Ag = A + (size_t)(row0 + arow) * K + akb;
    const float* Bg = B + (size_t)bkrow * M + col0 + bcol;

    float acc[4][4][4];
#pragma unroll
    for (int mt = 0; mt < 4; mt++)
#pragma unroll
        for (int ni = 0; ni < 4; ni++)
#pragma unroll
            for (int r = 0; r < 4; r++) acc[mt][ni][r] = 0.f;

    float av[8], bb[8];

    auto loadG = [&](int k0) {
        float4 t0 = *(const float4*)(Ag + k0);
        float4 t1 = *(const float4*)(Ag + k0 + 4);
        av[0]=t0.x; av[1]=t0.y; av[2]=t0.z; av[3]=t0.w;
        av[4]=t1.x; av[5]=t1.y; av[6]=t1.z; av[7]=t1.w;
        const float* bp = Bg + (size_t)k0 * M;
        float4 u0 = bval0 ? *(const float4*)bp       : make_float4(0,0,0,0);
        float4 u1 = bval1 ? *(const float4*)(bp + 4) : make_float4(0,0,0,0);
        bb[0]=u0.x; bb[1]=u0.y; bb[2]=u0.z; bb[3]=u0.w;
        bb[4]=u1.x; bb[5]=u1.y; bb[6]=u1.z; bb[7]=u1.w;
    };

    auto storeS = [&](int st) {
        const int sbase = st << 10;
#pragma unroll
        for (int u = 0; u < 8; u++) {
            int k = akb + u;
            int p = ((k >> 3) << 2) | (k & 3);
            int c = (k >> 2) & 1;
            int ph = p ^ ((arow & 3) << 1);
            uint32_t hi = f2tf32(av[u]);
            ((uint32_t*)&AsH[sbase + (arow << 3) + ph])[c] = hi;
            if (TERMS == 3) {
                uint32_t lo = f2tf32(av[u] - __uint_as_float(hi));
                ((uint32_t*)&AsL[sbase + (arow << 3) + ph])[c] = lo;
            }
        }
        {
            int k = bkrow;
            int p = ((k >> 3) << 2) | (k & 3);
            int c = (k >> 2) & 1;
#pragma unroll
            for (int u = 0; u < 8; u++) {
                int col = bcol + u;
                int ph = p ^ ((col & 3) << 1);
                uint32_t hi = f2tf32(bb[u]);
                ((uint32_t*)&BsH[sbase + (col << 3) + ph])[c] = hi;
                if (TERMS == 3) {
                    uint32_t lo = f2tf32(bb[u] - __uint_as_float(hi));
                    ((uint32_t*)&BsL[sbase + (col << 3) + ph])[c] = lo;
                }
            }
        }
    };

    auto compute = [&](int st) {
        const int sbase = st << 10;
#pragma unroll
        for (int hb = 0; hb < 2; hb++) {
            const int ph = (hb * 4 + tg) ^ ((g & 3) << 1);
            uint32_t afH[4][4];
            uint2 bH[4];
#pragma unroll
            for (int mt = 0; mt < 4; mt++) {
                int r = wr + mt * 16 + g;
                uint2 p0 = AsH[sbase + (r << 3) + ph];
                uint2 p1 = AsH[sbase + ((r + 8) << 3) + ph];
                afH[mt][0] = p0.x; afH[mt][1] = p1.x;
                afH[mt][2] = p0.y; afH[mt][3] = p1.y;
            }
#pragma unroll
            for (int ni = 0; ni < 4; ni++) {
                int cc = wc + ni * 8 + g;
                bH[ni] = BsH[sbase + (cc << 3) + ph];
            }
#pragma unroll
            for (int ni = 0; ni < 4; ni++)
#pragma unroll
                for (int mt = 0; mt < 4; mt++)
                    mma_tf32(acc[mt][ni], afH[mt], bH[ni].x, bH[ni].y);
            if (TERMS == 3) {
                uint2 bL[4];
#pragma unroll
                for (int ni = 0; ni < 4; ni++) {
                    int cc = wc + ni * 8 + g;
                    bL[ni] = BsL[sbase + (cc << 3) + ph];
                }
#pragma unroll
                for (int ni = 0; ni < 4; ni++)
#pragma unroll
                    for (int mt = 0; mt < 4; mt++)
                        mma_tf32(acc[mt][ni], afH[mt], bL[ni].x, bL[ni].y);
#pragma unroll
                for (int mt = 0; mt < 4; mt++) {
                    int r = wr + mt * 16 + g;
                    uint2 p0 = AsL[sbase + (r << 3) + ph];
                    uint2 p1 = AsL[sbase + ((r + 8) << 3) + ph];
                    uint32_t afL[4] = {p0.x, p1.x, p0.y, p1.y};
#pragma unroll
                    for (int ni = 0; ni < 4; ni++)
                        mma_tf32(acc[mt][ni], afL, bH[ni].x, bH[ni].y);
                }
            }
        }
    };

    loadG(kbeg);
    storeS(0);
    __syncthreads();

    const int nIter = Kc >> 4;
    for (int it = 0; it < nIter; it++) {
        int st = it & 1;
        bool hasNext = (it + 1 < nIter);
        if (hasNext) loadG(kbeg + (it + 1) * 16);
        compute(st);
        if (hasNext) storeS(st ^ 1);
        __syncthreads();
    }

    float* Cout = (S == 1) ? C : (Cpart + (size_t)blockIdx.z * N_TOK * M);
#pragma unroll
    for (int mt = 0; mt < 4; mt++) {
#pragma unroll
        for (int ni = 0; ni < 4; ni++) {
            int r = row0 + wr + mt * 16 + g;
            int c = col0 + wc + ni * 8 + tg * 2;
            if (c + 2 <= M) {
                *(float2*)&Cout[(size_t)r * M + c] =
                    make_float2(acc[mt][ni][0], acc[mt][ni][1]);
                *(float2*)&Cout[(size_t)(r + 8) * M + c] =
                    make_float2(acc[mt][ni][2], acc[mt][ni][3]);
            }
        }
    }
}

// ---------------- fused output GEMM: out = (g0*cmp+g1*sp+g2*sw) @ Wo --------
// gateS holds PRE-SIGMOIDED gates [n][h][3]. A-dims fixed: rows=2048, K=2048.
__global__ void __launch_bounds__(256, 2)
gemm_out_kernel(const float* __restrict__ cmp, const float* __restrict__ sp,
                const float* __restrict__ sw, const float* __restrict__ gateS,
                const float* __restrict__ B, float* __restrict__ C)
{
    const int K = HID, M = HID;
    extern __shared__ uint2 sm[];
    uint2* AsH = sm;
    uint2* BsH = sm + 2048;

    const int tid = threadIdx.x;
    const int wid = tid >> 5, lane = tid & 31;
    const int row0 = blockIdx.y * 128, col0 = blockIdx.x * 128;
    const int wr = (wid & 1) * 64, wc = (wid >> 1) * 32;
    const int g = lane >> 2, tg = lane & 3;

    const int arow = tid >> 1, akb = (tid & 1) * 8;
    const int bkrow = tid >> 4, bcol = (tid & 15) * 8;

    const size_t abase = (size_t)(row0 + arow) * K + akb;
    const float* Bg = B + (size_t)bkrow * M + col0 + bcol;
    const float* gsrow = gateS + (size_t)(row0 + arow) * (HQ*3);

    float acc[4][4][4];
#pragma unroll
    for (int mt = 0; mt < 4; mt++)
#pragma unroll
        for (int ni = 0; ni < 4; ni++)
#pragma unroll
            for (int r = 0; r < 4; r++) acc[mt][ni][r] = 0.f;

    float av[8], bb[8];

    auto loadG = [&](int k0) {
        int col = akb + k0;
        int h = col >> 7;
        float g0 = gsrow[h*3+0], g1 = gsrow[h*3+1], g2 = gsrow[h*3+2];
        size_t ia = abase + k0;
        float4 c0 = *(const float4*)(cmp + ia), c1 = *(const float4*)(cmp + ia + 4);
        float4 s0 = *(const float4*)(sp  + ia), s1 = *(const float4*)(sp  + ia + 4);
        float4 w0 = *(const float4*)(sw  + ia), w1 = *(const float4*)(sw  + ia + 4);
        av[0] = g0*c0.x + g1*s0.x + g2*w0.x;
        av[1] = g0*c0.y + g1*s0.y + g2*w0.y;
        av[2] = g0*c0.z + g1*s0.z + g2*w0.z;
        av[3] = g0*c0.w + g1*s0.w + g2*w0.w;
        av[4] = g0*c1.x + g1*s1.x + g2*w1.x;
        av[5] = g0*c1.y + g1*s1.y + g2*w1.y;
        av[6] = g0*c1.z + g1*s1.z + g2*w1.z;
        av[7] = g0*c1.w + g1*s1.w + g2*w1.w;
        const float* bp = Bg + (size_t)k0 * M;
        float4 u0 = *(const float4*)bp;
        float4 u1 = *(const float4*)(bp + 4);
        bb[0]=u0.x; bb[1]=u0.y; bb[2]=u0.z; bb[3]=u0.w;
        bb[4]=u1.x; bb[5]=u1.y; bb[6]=u1.z; bb[7]=u1.w;
    };

    auto storeS = [&](int st) {
        const int sbase = st << 10;
#pragma unroll
        for (int u = 0; u < 8; u++) {
            int k = akb + u;
            int p = ((k >> 3) << 2) | (k & 3);
            int c = (k >> 2) & 1;
            int ph = p ^ ((arow & 3) << 1);
            ((uint32_t*)&AsH[sbase + (arow << 3) + ph])[c] = f2tf32(av[u]);
        }
        {
            int k = bkrow;
            int p = ((k >> 3) << 2) | (k & 3);
            int c = (k >> 2) & 1;
#pragma unroll
            for (int u = 0; u < 8; u++) {
                int col = bcol + u;
                int ph = p ^ ((col & 3) << 1);
                ((uint32_t*)&BsH[sbase + (col << 3) + ph])[c] = f2tf32(bb[u]);
            }
        }
    };

    auto compute = [&](int st) {
        const int sbase = st << 10;
#pragma unroll
        for (int hb = 0; hb < 2; hb++) {
            const int ph = (hb * 4 + tg) ^ ((g & 3) << 1);
            uint32_t afH[4][4];
            uint2 bH[4];
#pragma unroll
            for (int mt = 0; mt < 4; mt++) {
                int r = wr + mt * 16 + g;
                uint2 p0 = AsH[sbase + (r << 3) + ph];
                uint2 p1 = AsH[sbase + ((r + 8) << 3) + ph];
                afH[mt][0] = p0.x; afH[mt][1] = p1.x;
                afH[mt][2] = p0.y; afH[mt][3] = p1.y;
            }
#pragma unroll
            for (int ni = 0; ni < 4; ni++) {
                int cc = wc + ni * 8 + g;
                bH[ni] = BsH[sbase + (cc << 3) + ph];
            }
#pragma unroll
            for (int ni = 0; ni < 4; ni++)
#pragma unroll
                for (int mt = 0; mt < 4; mt++)
                    mma_tf32(acc[mt][ni], afH[mt], bH[ni].x, bH[ni].y);
        }
    };

    loadG(0);
    storeS(0);
    __syncthreads();

    const int nIter = K >> 4;
    for (int it = 0; it < nIter; it++) {
        int st = it & 1;
        bool hasNext = (it + 1 < nIter);
        if (hasNext) loadG((it + 1) * 16);
        compute(st);
        if (hasNext) storeS(st ^ 1);
        __syncthreads();
    }

#pragma unroll
    for (int mt = 0; mt < 4; mt++) {
#pragma unroll
        for (int ni = 0; ni < 4; ni++) {
            int r = row0 + wr + mt * 16 + g;
            int c = col0 + wc + ni * 8 + tg * 2;
            *(float2*)&C[(size_t)r * M + c] =
                make_float2(acc[mt][ni][0], acc[mt][ni][1]);
            *(float2*)&C[(size_t)(r + 8) * M + c] =
                make_float2(acc[mt][ni][2], acc[mt][ni][3]);
        }
    }
}

__global__ void splitk_reduce_kernel(const float* __restrict__ part,
                                     float* __restrict__ out, int len, int S)
{
    int i = blockIdx.x * 256 + threadIdx.x;
    if (i >= len) return;
    float s = 0.f;
    for (int z = 0; z < S; z++) s += part[(size_t)z * len + i];
    out[i] = s;
}

// ---------------- sigmoid of gates (in place) -------------------------------
__global__ void sigmoid_kernel(float* __restrict__ gbuf, int len)
{
    int i = blockIdx.x * 256 + threadIdx.x;
    if (i >= len) return;
    gbuf[i] = 1.f / (1.f + __expf(-gbuf[i]));
}

// ---------------- compressed k/v (pre-RoPE) --------------------------------
__global__ void compress_kernel(const float* __restrict__ k,
                                const float* __restrict__ v,
                                const float* __restrict__ pe,
                                float* __restrict__ ck,
                                float* __restrict__ cv)
{
    int m = blockIdx.x;
    int d = threadIdx.x;
    float sk = 0.f, sv = 0.f;
#pragma unroll 8
    for (int i = 0; i < KS; i++) {
        sk += k[(m*KS + i)*D + d] + pe[i*D + d];
        sv += v[(m*KS + i)*D + d];
    }
    ck[m*D + d] = sk * (1.f/KS);
    cv[m*D + d] = sv * (1.f/KS);
}

// ---------------- RoPE (in place) ------------------------------------------
__global__ void rope_kernel(float* __restrict__ x, int heads, int pos_stride)
{
    int row = blockIdx.x;
    int d   = threadIdx.x;
    float inv = powf(10000.f, -(float)d / 64.f);
    float ang = (float)(row * pos_stride) * inv;
    float c = cosf(ang), s = sinf(ang);
    for (int h = 0; h < heads; h++) {
        float* p = x + ((size_t)row*heads + h) * D;
        float x1 = p[d], x2 = p[d + 64];
        p[d]      = x1 * c - x2 * s;
        p[d + 64] = x2 * c + x1 * s;
    }
}

// ---------------- ck transpose ----------------------------------------------
__global__ void transpose_ck_kernel(const float* __restrict__ ck,
                                    float* __restrict__ ckT)
{
    int i = blockIdx.x * 256 + threadIdx.x;
    int m = i >> 7, d = i & 127;
    ckT[d*NC + m] = ck[m*D + d];
}

// ---------------- cmp softmax / mask / block-score --------------------------
__global__ void cmp_softmax_kernel(float* __restrict__ sc,
                                   float* __restrict__ blks)
{
    int n = blockIdx.x;
    __shared__ float pcs[HQ][NC];
    int tid = threadIdx.x;

    float* base = sc + (size_t)n * HQ * NC;
    {
        int h = tid >> 4, m4 = (tid & 15) * 4;
        float4 vv = *(float4*)&base[h*NC + m4];
        float s[4] = {vv.x, vv.y, vv.z, vv.w};
#pragma unroll
        for (int u = 0; u < 4; u++) {
            int m = m4 + u;
            bool valid = (n >= m*STRIDE + KS - 1);
            s[u] = valid ? s[u] * SCALE : NEGF;
        }
        pcs[h][m4+0] = s[0]; pcs[h][m4+1] = s[1];
        pcs[h][m4+2] = s[2]; pcs[h][m4+3] = s[3];
    }
    __syncthreads();

    {
        int w = tid >> 5, l = tid & 31;
        for (int h = w; h < HQ; h += 8) {
            float a = pcs[h][l], b = pcs[h][l + 32];
            float mx = fmaxf(a, b);
#pragma unroll
            for (int o = 16; o > 0; o >>= 1) mx = fmaxf(mx, __shfl_xor_sync(0xffffffff, mx, o));
            float ea = __expf(a - mx), eb = __expf(b - mx);
            float s = ea + eb;
#pragma unroll
            for (int o = 16; o > 0; o >>= 1) s += __shfl_xor_sync(0xffffffff, s, o);
            float inv = 1.f / s;
            bool va = (n >= l*STRIDE + KS - 1);
            bool vb = (n >= (l+32)*STRIDE + KS - 1);
            pcs[h][l]      = va ? ea * inv : 0.f;
            pcs[h][l + 32] = vb ? eb * inv : 0.f;
        }
    }
    __syncthreads();

    for (int m = tid; m < NC; m += 256) {
        float s = 0.f;
        for (int h = 0; h < HQ; h++) s += pcs[h][m];
        blks[(size_t)n*NC + m] = s;
    }
    {
        int h = tid >> 4, m4 = (tid & 15) * 4;
        *(float4*)&base[h*NC + m4] =
            make_float4(pcs[h][m4], pcs[h][m4+1], pcs[h][m4+2], pcs[h][m4+3]);
    }
}

// ---------------- top-k selection ------------------------------------------
__global__ void topk_kernel(const float* __restrict__ blks, int* __restrict__ topk)
{
    int n = blockIdx.x * blockDim.x + threadIdx.x;
    if (n >= N_TOK) return;
    float sel[NC];
    int tb = n / BSZ;
    for (int m = 0; m < NC; m++) {
        float s = blks[(size_t)n*NC + m];
        if (m > tb) s = NEGF;
        if (m < 1 || (m <= tb && m > tb - 2)) s = 1e30f;
        sel[m] = s;
    }
    for (int j = 0; j < TOPK; j++) {
        int bi = 0; float bv = sel[0];
        for (int m = 1; m < NC; m++) if (sel[m] > bv) { bv = sel[m]; bi = m; }
        topk[n*TOPK + j] = bi;
        sel[bi] = -FLT_MAX;
    }
}

// ============ sel attention (SIMT, dual K/V buffers, 4 syncs/tile) ==========
#define KVP 132

__device__ __forceinline__ void attn_softmax_update(
    float* sc, float* mS, float* lS, float* fS, int tid)
{
    int h = tid >> 4, t = tid & 15;
    float4 sv = *(float4*)&sc[h*64 + t*4];
    float pm = fmaxf(fmaxf(sv.x, sv.y), fmaxf(sv.z, sv.w));
#pragma unroll
    for (int o = 1; o < 16; o <<= 1) pm = fmaxf(pm, __shfl_xor_sync(0xffffffff, pm, o));
    float mOld = mS[h];
    float mNew = fmaxf(mOld, pm);
    float4 p;
    p.x = __expf(sv.x - mNew); p.y = __expf(sv.y - mNew);
    p.z = __expf(sv.z - mNew); p.w = __expf(sv.w - mNew);
    *(float4*)&sc[h*64 + t*4] = p;
    float ps = p.x + p.y + p.z + p.w;
#pragma unroll
    for (int o = 1; o < 16; o <<= 1) ps += __shfl_xor_sync(0xffffffff, ps, o);
    if (t == 0) {
        float f = __expf(mOld - mNew);
        fS[h] = f;
        lS[h] = lS[h] * f + ps;
        mS[h] = mNew;
    }
}

__global__ void __launch_bounds__(256, 2)
sel_attn_kernel(const float* __restrict__ q, const float* __restrict__ k,
                const float* __restrict__ v, const int* __restrict__ topk,
                float* __restrict__ out)
{
    extern __shared__ float smem_sel[];
    float* qs = smem_sel;                  // HQ*D = 2048
    float* kb = qs + HQ*D;                 // 64*KVP
    float* vb = kb + 64*KVP;               // 64*KVP
    float* sc = vb + 64*KVP;               // HQ*64
    float* mS = sc + HQ*64;                // 16
    float* lS = mS + HQ;                   // 16
    float* fS = lS + HQ;                   // 16
    int*  posA = (int*)(fS + HQ);          // 256

    int n = blockIdx.x;
    int tid = threadIdx.x;

    for (int e = tid; e < HQ*D/4; e += 256)
        ((float4*)qs)[e] = ((const float4*)(q + (size_t)n*HQ*D))[e];
    if (tid < HQ) { mS[tid] = -FLT_MAX; lS[tid] = 0.f; }
    posA[tid] = topk[n*TOPK + (tid >> 5)] * BSZ + (tid & 31);

    int h  = tid >> 4;
    int d0 = (tid & 15) * 8;
    float acc[8];
#pragma unroll
    for (int i = 0; i < 8; i++) acc[i] = 0.f;
    __syncthreads();

    for (int t0 = 0; t0 < TOPK*BSZ; t0 += 64) {
        // gather K AND V tiles together (better MLP, fewer syncs)
        for (int e = tid; e < 64*32; e += 256) {
            int row = e >> 5, c = e & 31;
            size_t pos = (size_t)posA[t0 + row];
            *(float4*)&kb[row*KVP + c*4] = ((const float4*)(k + pos*D))[c];
            *(float4*)&vb[row*KVP + c*4] = ((const float4*)(v + pos*D))[c];
        }
        __syncthreads();
        {
            int jj = tid & 63;
            int hb = (tid >> 6) * 4;
            bool valid = posA[t0 + jj] <= n;
            if (valid) {
                const float4* kr = (const float4*)(kb + jj*KVP);
                const float4* q0 = (const float4*)(qs + (hb+0)*D);
                const float4* q1 = (const float4*)(qs + (hb+1)*D);
                const float4* q2 = (const float4*)(qs + (hb+2)*D);
                const float4* q3 = (const float4*)(qs + (hb+3)*D);
                float s0=0.f,s1=0.f,s2=0.f,s3=0.f;
#pragma unroll
                for (int c = 0; c < 32; c++) {
                    float4 kk = kr[c];
                    float4 a;
                    a = q0[c]; s0 += a.x*kk.x + a.y*kk.y + a.z*kk.z + a.w*kk.w;
                    a = q1[c]; s1 += a.x*kk.x + a.y*kk.y + a.z*kk.z + a.w*kk.w;
                    a = q2[c]; s2 += a.x*kk.x + a.y*kk.y + a.z*kk.z + a.w*kk.w;
                    a = q3[c]; s3 += a.x*kk.x + a.y*kk.y + a.z*kk.z + a.w*kk.w;
                }
                sc[(hb+0)*64+jj]=s0*SCALE; sc[(hb+1)*64+jj]=s1*SCALE;
                sc[(hb+2)*64+jj]=s2*SCALE; sc[(hb+3)*64+jj]=s3*SCALE;
            } else {
                sc[(hb+0)*64+jj]=NEGF; sc[(hb+1)*64+jj]=NEGF;
                sc[(hb+2)*64+jj]=NEGF; sc[(hb+3)*64+jj]=NEGF;
            }
        }
        __syncthreads();
        attn_softmax_update(sc, mS, lS, fS, tid);
        __syncthreads();
        {
            float f = fS[h];
#pragma unroll
            for (int i = 0; i < 8; i++) acc[i] *= f;
            const float* scp = sc + h*64;
            for (int j = 0; j < 64; j++) {
                float p = scp[j];
                float4 v0 = *(const float4*)&vb[j*KVP + d0];
                float4 v1 = *(const float4*)&vb[j*KVP + d0 + 4];
                acc[0] += p*v0.x; acc[1] += p*v0.y; acc[2] += p*v0.z; acc[3] += p*v0.w;
                acc[4] += p*v1.x; acc[5] += p*v1.y; acc[6] += p*v1.z; acc[7] += p*v1.w;
            }
        }
        __syncthreads();
    }
    float inv = 1.f / lS[h];
    float4 o0 = make_float4(acc[0]*inv, acc[1]*inv, acc[2]*inv, acc[3]*inv);
    float4 o1 = make_float4(acc[4]*inv, acc[5]*inv, acc[6]*inv, acc[7]*inv);
    *(float4*)&out[((size_t)n*HQ + h)*D + d0]     = o0;
    *(float4*)&out[((size_t)n*HQ + h)*D + d0 + 4] = o1;
}

// ================= window attention via 1-term tf32 tensor cores ============
__global__ void __launch_bounds__(256, 2)
win_mma_kernel(const float* __restrict__ q, const float* __restrict__ k,
               const float* __restrict__ v, float* __restrict__ out)
{
    extern __shared__ uint2 smw[];
    uint2* Qh = smw;
    uint2* Bh = smw + 4096;
    uint2* Ph = smw + 8192;
    float* stats = (float*)(smw + 10240);
    float* mS   = stats;
    float* lS   = stats + 64;
    float* fS   = stats + 128;
    float* pmax = stats + 192;
    float* psum = stats + 320;

    const int tid = threadIdx.x;
    const int wid = tid >> 5, lane = tid & 31;
    const int g = lane >> 2, tg = lane & 3;
    const int qtile0 = blockIdx.x * 64;
    const int h = blockIdx.y;

    for (int e = tid; e < 64*32; e += 256) {
        int row = e >> 5, c4 = e & 31;
        float4 vq = *(const float4*)&q[(((size_t)(qtile0 + row))*HQ + h)*D + c4*4];
        float qv[4] = {vq.x, vq.y, vq.z, vq.w};
#pragma unroll
        for (int u = 0; u < 4; u++) {
            int d = c4*4 + u;
            int ch = d >> 4, kk = d & 15;
            int p = ((kk >> 3) << 2) | (kk & 3);
            int cc = (kk >> 2) & 1;
            int ph = p ^ ((row & 3) << 1);
            ((uint32_t*)&Qh[ch*512 + (row << 3) + ph])[cc] = f2tf32(qv[u]);
        }
    }
    if (tid < 64) { mS[tid] = -3.0e38f; lS[tid] = 0.f; }

    const int mtS = wid & 3, cg = wid >> 2;
    const int mtP = wid & 3, dh = wid >> 2;

    float oacc[8][4];
#pragma unroll
    for (int ni = 0; ni < 8; ni++)
#pragma unroll
        for (int r = 0; r < 4; r++) oacc[ni][r] = 0.f;

    int klo = qtile0 - WIN; if (klo < 0) klo = 0;
    __syncthreads();

    for (int kt = klo; kt < qtile0 + 64; kt += 64) {
        for (int e = tid; e < 64*32; e += 256) {
            int key = e >> 5, c4 = e & 31;
            float4 vk = *(const float4*)&k[((size_t)(kt + key))*D + c4*4];
            float kv4[4] = {vk.x, vk.y, vk.z, vk.w};
#pragma unroll
            for (int u = 0; u < 4; u++) {
                int d = c4*4 + u;
                int ch = d >> 4, kk = d & 15;
                int p = ((kk >> 3) << 2) | (kk & 3);
                int cc = (kk >> 2) & 1;
                int ph = p ^ ((key & 3) << 1);
                ((uint32_t*)&Bh[ch*512 + (key << 3) + ph])[cc] = f2tf32(kv4[u]);
            }
        }
        __syncthreads();

        float sacc[4][4];
#pragma unroll
        for (int ni = 0; ni < 4; ni++)
#pragma unroll
            for (int r = 0; r < 4; r++) sacc[ni][r] = 0.f;

#pragma unroll
        for (int ch = 0; ch < 8; ch++) {
#pragma unroll
            for (int hb = 0; hb < 2; hb++) {
                const int ph = (hb*4 + tg) ^ ((g & 3) << 1);
                int r = mtS*16 + g;
                uint2 a0 = Qh[ch*512 + (r << 3) + ph];
                uint2 a1 = Qh[ch*512 + ((r + 8) << 3) + ph];
                uint32_t afH[4] = {a0.x, a1.x, a0.y, a1.y};
#pragma unroll
                for (int ni = 0; ni < 4; ni++) {
                    int col = cg*32 + ni*8 + g;
                    uint2 bH = Bh[ch*512 + (col << 3) + ph];
                    mma_tf32(sacc[ni], afH, bH.x, bH.y);
                }
            }
        }

        const int rA = qtile0 + mtS*16 + g;
        const int rB = rA + 8;
        float m1 = -3.0e38f, m2 = -3.0e38f;
#pragma unroll
        for (int ni = 0; ni < 4; ni++) {
            int key0 = kt + cg*32 + ni*8 + tg*2;
#pragma unroll
            for (int i = 0; i < 4; i++) {
                int key = key0 + (i & 1);
                int qp = (i < 2) ? rA : rB;
                float s = sacc[ni][i] * SCALE;
                bool valid = (key <= qp) && (key >= qp - WIN);
                s = valid ? s : NEGF;
                sacc[ni][i] = s;
                if (i < 2) m1 = fmaxf(m1, s); else m2 = fmaxf(m2, s);
            }
        }
#pragma unroll
        for (int o = 1; o < 4; o <<= 1) {
            m1 = fmaxf(m1, __shfl_xor_sync(0xffffffff, m1, o));
            m2 = fmaxf(m2, __shfl_xor_sync(0xffffffff, m2, o));
        }
        int rlA = mtS*16 + g, rlB = rlA + 8;
        if (tg == 0) { pmax[rlA*2 + cg] = m1; pmax[rlB*2 + cg] = m2; }
        __syncthreads();

        float mnA = fmaxf(mS[rlA], fmaxf(pmax[rlA*2], pmax[rlA*2+1]));
        float mnB = fmaxf(mS[rlB], fmaxf(pmax[rlB*2], pmax[rlB*2+1]));
        float sumA = 0.f, sumB = 0.f;
#pragma unroll
        for (int ni = 0; ni < 4; ni++) {
#pragma unroll
            for (int i = 0; i < 4; i++) {
                float s = sacc[ni][i];
                float mn = (i < 2) ? mnA : mnB;
                float p = (s <= -1e29f) ? 0.f : __expf(s - mn);
                if (i < 2) sumA += p; else sumB += p;
                int cloc = cg*32 + ni*8 + tg*2 + (i & 1);
                int ch = cloc >> 4, kk = cloc & 15;
                int pp = ((kk >> 3) << 2) | (kk & 3);
                int cc = (kk >> 2) & 1;
                int rl = (i < 2) ? rlA : rlB;
                int ph = pp ^ ((rl & 3) << 1);
                ((uint32_t*)&Ph[ch*512 + (rl << 3) + ph])[cc] = f2tf32(p);
            }
        }
#pragma unroll
        for (int o = 1; o < 4; o <<= 1) {
            sumA += __shfl_xor_sync(0xffffffff, sumA, o);
            sumB += __shfl_xor_sync(0xffffffff, sumB, o);
        }
        if (tg == 0) { psum[rlA*2 + cg] = sumA; psum[rlB*2 + cg] = sumB; }

        for (int e = tid; e < 64*32; e += 256) {
            int key = e >> 5, c4 = e & 31;
            float4 vv = *(const float4*)&v[((size_t)(kt + key))*D + c4*4];
            float v4[4] = {vv.x, vv.y, vv.z, vv.w};
            int chv = key >> 4, kkv = key & 15;
            int pv = ((kkv >> 3) << 2) | (kkv & 3);
            int ccv = (kkv >> 2) & 1;
#pragma unroll
            for (int u = 0; u < 4; u++) {
                int d = c4*4 + u;
                int phv = pv ^ ((d & 3) << 1);
                ((uint32_t*)&Bh[chv*1024 + (d << 3) + phv])[ccv] = f2tf32(v4[u]);
            }
        }
        __syncthreads();

        if (tid < 64) {
            float mo = mS[tid];
            float mn = fmaxf(mo, fmaxf(pmax[tid*2], pmax[tid*2+1]));
            float f = __expf(mo - mn);
            lS[tid] = lS[tid] * f + psum[tid*2] + psum[tid*2+1];
            mS[tid] = mn;
            fS[tid] = f;
        }
        __syncthreads();

        {
            int rl1 = mtP*16 + g, rl2 = rl1 + 8;
            float f1 = fS[rl1], f2 = fS[rl2];
#pragma unroll
            for (int ni = 0; ni < 8; ni++) {
                oacc[ni][0] *= f1; oacc[ni][1] *= f1;
                oacc[ni][2] *= f2; oacc[ni][3] *= f2;
            }
#pragma unroll
            for (int ch = 0; ch < 4; ch++) {
#pragma unroll
                for (int hb = 0; hb < 2; hb++) {
                    const int ph = (hb*4 + tg) ^ ((g & 3) << 1);
                    int r = mtP*16 + g;
                    uint2 a0 = Ph[ch*512 + (r << 3) + ph];
                    uint2 a1 = Ph[ch*512 + ((r + 8) << 3) + ph];
                    uint32_t afH[4] = {a0.x, a1.x, a0.y, a1.y};
#pragma unroll
                    for (int ni = 0; ni < 8; ni++) {
                        int col = dh*64 + ni*8 + g;
                        uint2 bH = Bh[ch*1024 + (col << 3) + ph];
                        mma_tf32(oacc[ni], afH, bH.x, bH.y);
                    }
                }
            }
        }
        __syncthreads();
    }

    {
        int rl1 = mtP*16 + g, rl2 = rl1 + 8;
        float i1 = 1.f / lS[rl1], i2 = 1.f / lS[rl2];
        size_t b1 = ((size_t)(qtile0 + rl1)*HQ + h)*D;
        size_t b2 = ((size_t)(qtile0 + rl2)*HQ + h)*D;
#pragma unroll
        for (int ni = 0; ni < 8; ni++) {
            int d = dh*64 + ni*8 + tg*2;
            *(float2*)&out[b1 + d] = make_float2(oacc[ni][0]*i1, oacc[ni][1]*i1);
            *(float2*)&out[b2 + d] = make_float2(oacc[ni][2]*i2, oacc[ni][3]*i2);
        }
    }
}

// ---------------- launcher with stream fork/join -----------------------------
extern "C" void kernel_launch(void* const* d_in, const int* in_sizes, int n_in,
                              void* d_out, int out_size)
{
    const float* x  = (const float*)d_in[0];
    const float* Wq = (const float*)d_in[2];
    const float* Wk = (const float*)d_in[3];
    const float* Wv = (const float*)d_in[4];
    const float* Wo = (const float*)d_in[5];
    const float* Wg = (const float*)d_in[6];
    const float* pe = (const float*)d_in[7];
    float* out = (float*)d_out;

    float *q, *k, *v, *ck, *ckT, *cv, *blks, *cmp, *sp, *sw, *gate, *part, *partG;
    int* tk;
    cudaGetSymbolAddress((void**)&q,    g_q);
    cudaGetSymbolAddress((void**)&k,    g_k);
    cudaGetSymbolAddress((void**)&v,    g_v);
    cudaGetSymbolAddress((void**)&ck,   g_ck);
    cudaGetSymbolAddress((void**)&ckT,  g_ckT);
    cudaGetSymbolAddress((void**)&cv,   g_cv);
    cudaGetSymbolAddress((void**)&blks, g_blks);
    cudaGetSymbolAddress((void**)&tk,   g_topk);
    cudaGetSymbolAddress((void**)&cmp,  g_cmp);
    cudaGetSymbolAddress((void**)&sp,   g_sp);
    cudaGetSymbolAddress((void**)&sw,   g_sw);
    cudaGetSymbolAddress((void**)&gate, g_gate);
    cudaGetSymbolAddress((void**)&part, g_part);
    cudaGetSymbolAddress((void**)&partG,g_partG);

    const int SMEM3 = 65536;
    const int SMEM1 = 32768;
    const int SMEMW = 10240*8 + 448*4;
    const int SMEMSEL = (HQ*D + 2*64*KVP + HQ*64 + 3*HQ)*4 + 256*4;  // 81088 B
    cudaFuncSetAttribute(gemm_kernel<3>, cudaFuncAttributeMaxDynamicSharedMemorySize, SMEM3);
    cudaFuncSetAttribute(gemm_kernel<1>, cudaFuncAttributeMaxDynamicSharedMemorySize, SMEM1);
    cudaFuncSetAttribute(gemm_out_kernel, cudaFuncAttributeMaxDynamicSharedMemorySize, SMEM1);
    cudaFuncSetAttribute(win_mma_kernel, cudaFuncAttributeMaxDynamicSharedMemorySize, SMEMW);
    cudaFuncSetAttribute(sel_attn_kernel, cudaFuncAttributeMaxDynamicSharedMemorySize, SMEMSEL);

    static cudaStream_t sB = nullptr, sC = nullptr;
    static cudaEvent_t evRoot = nullptr, evQ = nullptr, evKV = nullptr,
                       evTK = nullptr, evCMP = nullptr, evSEL = nullptr;
    if (!sB) {
        cudaStreamCreateWithFlags(&sB, cudaStreamNonBlocking);
        cudaStreamCreateWithFlags(&sC, cudaStreamNonBlocking);
        cudaEventCreateWithFlags(&evRoot, cudaEventDisableTiming);
        cudaEventCreateWithFlags(&evQ,    cudaEventDisableTiming);
        cudaEventCreateWithFlags(&evKV,   cudaEventDisableTiming);
        cudaEventCreateWithFlags(&evTK,   cudaEventDisableTiming);
        cudaEventCreateWithFlags(&evCMP,  cudaEventDisableTiming);
        cudaEventCreateWithFlags(&evSEL,  cudaEventDisableTiming);
    }

    cudaEventRecord(evRoot, 0);
    cudaStreamWaitEvent(sB, evRoot, 0);
    cudaStreamWaitEvent(sC, evRoot, 0);

    // --- spine A (default): Wq -> ropeQ ------------------------------------
    gemm_kernel<3><<<dim3(16, 16, 1), 256, SMEM3>>>(x, Wq, q, nullptr, HID, HQ*D);
    rope_kernel<<<N_TOK, 64>>>(q, HQ, 1);
    cudaEventRecord(evQ, 0);

    // --- spine B: k/v chain -> cmp scores -> topk ---------------------------
    gemm_kernel<3><<<dim3(1, 16, 8), 256, SMEM3, sB>>>(x, Wk, k, part, HID, D);
    splitk_reduce_kernel<<<(N_TOK*D + 255)/256, 256, 0, sB>>>(part, k, N_TOK*D, 8);
    gemm_kernel<1><<<dim3(1, 16, 8), 256, SMEM1, sB>>>(x, Wv, v, part, HID, D);
    splitk_reduce_kernel<<<(N_TOK*D + 255)/256, 256, 0, sB>>>(part, v, N_TOK*D, 8);
    compress_kernel<<<NC, D, 0, sB>>>(k, v, pe, ck, cv);
    rope_kernel<<<N_TOK, 64, 0, sB>>>(k, 1, 1);
    rope_kernel<<<NC, 64, 0, sB>>>(ck, 1, STRIDE);
    transpose_ck_kernel<<<32, 256, 0, sB>>>(ck, ckT);
    cudaEventRecord(evKV, sB);

    cudaStreamWaitEvent(sB, evQ, 0);
    gemm_kernel<3><<<dim3(1, 256, 1), 256, SMEM3, sB>>>(q, ckT, part, nullptr, D, NC);
    cmp_softmax_kernel<<<N_TOK, 256, 0, sB>>>(part, blks);
    topk_kernel<<<N_TOK/256, 256, 0, sB>>>(blks, tk);
    cudaEventRecord(evTK, sB);
    gemm_kernel<1><<<dim3(1, 256, 1), 256, SMEM1, sB>>>(part, cv, cmp, nullptr, NC, D);
    cudaEventRecord(evCMP, sB);

    // --- spine C: gate projection + sigmoid, then sel after topk ------------
    gemm_kernel<1><<<dim3(1, 16, 8), 256, SMEM1, sC>>>(x, Wg, gate, partG, HID, HQ*3);
    splitk_reduce_kernel<<<(N_TOK*HQ*3 + 255)/256, 256, 0, sC>>>(partG, gate, N_TOK*HQ*3, 8);
    sigmoid_kernel<<<(N_TOK*HQ*3 + 255)/256, 256, 0, sC>>>(gate, N_TOK*HQ*3);
    cudaStreamWaitEvent(sC, evTK, 0);
    sel_attn_kernel<<<N_TOK, 256, SMEMSEL, sC>>>(q, k, v, tk, sp);
    cudaEventRecord(evSEL, sC);

    // --- spine A continues: win after k/v ready -----------------------------
    cudaStreamWaitEvent(0, evKV, 0);
    win_mma_kernel<<<dim3(32, HQ), 256, SMEMW>>>(q, k, v, sw);

    // join: fused gated-combine + output projection
    cudaStreamWaitEvent(0, evSEL, 0);
    cudaStreamWaitEvent(0, evCMP, 0);
    gemm_out_kernel<<<dim3(16, 16, 1), 256, SMEM1>>>(cmp, sp, sw, gate, Wo, out);
}

// round 13
// speedup vs baseline: 1.0261x; 1.0261x over previous
#include <cuda_runtime.h>
#include <cuda_bf16.h>
#include <math.h>
#include <float.h>
#include <stdint.h>

#define N_TOK 2048
#define HID   2048
#define HQ    16
#define D     128
#define NC    64
#define KS    32
#define STRIDE 32
#define BSZ   32
#define TOPK  8
#define WIN   512
#define SCALE 0.08838834764831845f  /* 1/sqrt(128) */
#define NEGF  -1e30f

// ---------------- scratch (device globals) ---------------------------------
__device__ float g_q   [N_TOK*HQ*D];
__device__ float g_k   [N_TOK*D];
__device__ float g_v   [N_TOK*D];
__device__ float g_ck  [NC*D];
__device__ float g_ckT [D*NC];
__device__ float g_cv  [NC*D];
__device__ float g_blks[N_TOK*NC];
__device__ int   g_topk[N_TOK*TOPK];
__device__ float g_cmp [N_TOK*HQ*D];
__device__ float g_sp  [N_TOK*HQ*D];
__device__ float g_sw  [N_TOK*HQ*D];
__device__ float g_gate[N_TOK*HQ*3];
__device__ float g_att [N_TOK*HID];
__device__ float g_part [8 * N_TOK * 128];   // split-K partials (k,v); later cmp scores
__device__ float g_partG[8 * N_TOK * 48];    // split-K partials for gate
__device__ float g_partQ[2 * N_TOK * HQ*D];  // split-K partials for q (34 MB)

// ---------------- tf32 helpers ----------------------------------------------
__device__ __forceinline__ uint32_t f2tf32(float f) {
    uint32_t u;
    asm("cvt.rna.tf32.f32 %0, %1;" : "=r"(u) : "f"(f));
    return u;
}
__device__ __forceinline__ void mma_tf32(float* c, const uint32_t* a,
                                         uint32_t b0, uint32_t b1) {
    asm volatile(
        "mma.sync.aligned.m16n8k8.row.col.f32.tf32.tf32.f32 "
        "{%0,%1,%2,%3}, {%4,%5,%6,%7}, {%8,%9}, {%0,%1,%2,%3};"
        : "+f"(c[0]), "+f"(c[1]), "+f"(c[2]), "+f"(c[3])
        : "r"(a[0]), "r"(a[1]), "r"(a[2]), "r"(a[3]), "r"(b0), "r"(b1));
}

// ---------------- tf32 GEMM: C[rows,M]=A[rows,K]@B[K,M] ----------------------
template<int TERMS>
__global__ void __launch_bounds__(256, 2)
gemm_kernel(const float* __restrict__ A, const float* __restrict__ B,
            float* __restrict__ C, float* __restrict__ Cpart, int K, int M)
{
    extern __shared__ uint2 sm[];
    uint2* AsH = sm;
    uint2* BsH = sm + 2048;
    uint2* AsL = sm + 4096;
    uint2* BsL = sm + 6144;

    const int tid = threadIdx.x;
    const int wid = tid >> 5, lane = tid & 31;
    const int row0 = blockIdx.y * 128, col0 = blockIdx.x * 128;
    const int wr = (wid & 1) * 64, wc = (wid >> 1) * 32;
    const int g = lane >> 2, tg = lane & 3;
    const int S = gridDim.z, Kc = K / S, kbeg = blockIdx.z * Kc;

    const int arow = tid >> 1, akb = (tid & 1) * 8;
    const int bkrow = tid >> 4, bcol = (tid & 15) * 8;
    const bool bval0 = (col0 + bcol + 4) <= M;
    const bool bval1 = (col0 + bcol + 8) <= M;

    const float* Ag = A + (size_t)(row0 + arow) * K + akb;
    const float* Bg = B + (size_t)bkrow * M + col0 + bcol;

    float acc[4][4][4];
#pragma unroll
    for (int mt = 0; mt < 4; mt++)
#pragma unroll
        for (int ni = 0; ni < 4; ni++)
#pragma unroll
            for (int r = 0; r < 4; r++) acc[mt][ni][r] = 0.f;

    float av[8], bb[8];

    auto loadG = [&](int k0) {
        float4 t0 = *(const float4*)(Ag + k0);
        float4 t1 = *(const float4*)(Ag + k0 + 4);
        av[0]=t0.x; av[1]=t0.y; av[2]=t0.z; av[3]=t0.w;
        av[4]=t1.x; av[5]=t1.y; av[6]=t1.z; av[7]=t1.w;
        const float* bp = Bg + (size_t)k0 * M;
        float4 u0 = bval0 ? *(const float4*)bp       : make_float4(0,0,0,0);
        float4 u1 = bval1 ? *(const float4*)(bp + 4) : make_float4(0,0,0,0);
        bb[0]=u0.x; bb[1]=u0.y; bb[2]=u0.z; bb[3]=u0.w;
        bb[4]=u1.x; bb[5]=u1.y; bb[6]=u1.z; bb[7]=u1.w;
    };

    auto storeS = [&](int st) {
        const int sbase = st << 10;
#pragma unroll
        for (int u = 0; u < 8; u++) {
            int k = akb + u;
            int p = ((k >> 3) << 2) | (k & 3);
            int c = (k >> 2) & 1;
            int ph = p ^ ((arow & 3) << 1);
            uint32_t hi = f2tf32(av[u]);
            ((uint32_t*)&AsH[sbase + (arow << 3) + ph])[c] = hi;
            if (TERMS == 3) {
                uint32_t lo = f2tf32(av[u] - __uint_as_float(hi));
                ((uint32_t*)&AsL[sbase + (arow << 3) + ph])[c] = lo;
            }
        }
        {
            int k = bkrow;
            int p = ((k >> 3) << 2) | (k & 3);
            int c = (k >> 2) & 1;
#pragma unroll
            for (int u = 0; u < 8; u++) {
                int col = bcol + u;
                int ph = p ^ ((col & 3) << 1);
                uint32_t hi = f2tf32(bb[u]);
                ((uint32_t*)&BsH[sbase + (col << 3) + ph])[c] = hi;
                if (TERMS == 3) {
                    uint32_t lo = f2tf32(bb[u] - __uint_as_float(hi));
                    ((uint32_t*)&BsL[sbase + (col << 3) + ph])[c] = lo;
                }
            }
        }
    };

    auto compute = [&](int st) {
        const int sbase = st << 10;
#pragma unroll
        for (int hb = 0; hb < 2; hb++) {
            const int ph = (hb * 4 + tg) ^ ((g & 3) << 1);
            uint32_t afH[4][4];
            uint2 bH[4];
#pragma unroll
            for (int mt = 0; mt < 4; mt++) {
                int r = wr + mt * 16 + g;
                uint2 p0 = AsH[sbase + (r << 3) + ph];
                uint2 p1 = AsH[sbase + ((r + 8) << 3) + ph];
                afH[mt][0] = p0.x; afH[mt][1] = p1.x;
                afH[mt][2] = p0.y; afH[mt][3] = p1.y;
            }
#pragma unroll
            for (int ni = 0; ni < 4; ni++) {
                int cc = wc + ni * 8 + g;
                bH[ni] = BsH[sbase + (cc << 3) + ph];
            }
#pragma unroll
            for (int ni = 0; ni < 4; ni++)
#pragma unroll
                for (int mt = 0; mt < 4; mt++)
                    mma_tf32(acc[mt][ni], afH[mt], bH[ni].x, bH[ni].y);
            if (TERMS == 3) {
                uint2 bL[4];
#pragma unroll
                for (int ni = 0; ni < 4; ni++) {
                    int cc = wc + ni * 8 + g;
                    bL[ni] = BsL[sbase + (cc << 3) + ph];
                }
#pragma unroll
                for (int ni = 0; ni < 4; ni++)
#pragma unroll
                    for (int mt = 0; mt < 4; mt++)
                        mma_tf32(acc[mt][ni], afH[mt], bL[ni].x, bL[ni].y);
#pragma unroll
                for (int mt = 0; mt < 4; mt++) {
                    int r = wr + mt * 16 + g;
                    uint2 p0 = AsL[sbase + (r << 3) + ph];
                    uint2 p1 = AsL[sbase + ((r + 8) << 3) + ph];
                    uint32_t afL[4] = {p0.x, p1.x, p0.y, p1.y};
#pragma unroll
                    for (int ni = 0; ni < 4; ni++)
                        mma_tf32(acc[mt][ni], afL, bH[ni].x, bH[ni].y);
                }
            }
        }
    };

    loadG(kbeg);
    storeS(0);
    __syncthreads();

    const int nIter = Kc >> 4;
    for (int it = 0; it < nIter; it++) {
        int st = it & 1;
        bool hasNext = (it + 1 < nIter);
        if (hasNext) loadG(kbeg + (it + 1) * 16);
        compute(st);
        if (hasNext) storeS(st ^ 1);
        __syncthreads();
    }

    float* Cout = (S == 1) ? C : (Cpart + (size_t)blockIdx.z * N_TOK * M);
#pragma unroll
    for (int mt = 0; mt < 4; mt++) {
#pragma unroll
        for (int ni = 0; ni < 4; ni++) {
            int r = row0 + wr + mt * 16 + g;
            int c = col0 + wc + ni * 8 + tg * 2;
            if (c + 2 <= M) {
                *(float2*)&Cout[(size_t)r * M + c] =
                    make_float2(acc[mt][ni][0], acc[mt][ni][1]);
                *(float2*)&Cout[(size_t)(r + 8) * M + c] =
                    make_float2(acc[mt][ni][2], acc[mt][ni][3]);
            }
        }
    }
}

__global__ void splitk_reduce_kernel(const float* __restrict__ part,
                                     float* __restrict__ out, int len, int S)
{
    int i = blockIdx.x * 256 + threadIdx.x;
    if (i >= len) return;
    float s = 0.f;
    for (int z = 0; z < S; z++) s += part[(size_t)z * len + i];
    out[i] = s;
}

// ---------------- compressed k/v (pre-RoPE) --------------------------------
__global__ void compress_kernel(const float* __restrict__ k,
                                const float* __restrict__ v,
                                const float* __restrict__ pe,
                                float* __restrict__ ck,
                                float* __restrict__ cv)
{
    int m = blockIdx.x;
    int d = threadIdx.x;
    float sk = 0.f, sv = 0.f;
#pragma unroll 8
    for (int i = 0; i < KS; i++) {
        sk += k[(m*KS + i)*D + d] + pe[i*D + d];
        sv += v[(m*KS + i)*D + d];
    }
    ck[m*D + d] = sk * (1.f/KS);
    cv[m*D + d] = sv * (1.f/KS);
}

// ---------------- RoPE (in place) ------------------------------------------
__global__ void rope_kernel(float* __restrict__ x, int heads, int pos_stride)
{
    int row = blockIdx.x;
    int d   = threadIdx.x;
    float inv = powf(10000.f, -(float)d / 64.f);
    float ang = (float)(row * pos_stride) * inv;
    float c = cosf(ang), s = sinf(ang);
    for (int h = 0; h < heads; h++) {
        float* p = x + ((size_t)row*heads + h) * D;
        float x1 = p[d], x2 = p[d + 64];
        p[d]      = x1 * c - x2 * s;
        p[d + 64] = x2 * c + x1 * s;
    }
}

// ---------------- ck transpose ----------------------------------------------
__global__ void transpose_ck_kernel(const float* __restrict__ ck,
                                    float* __restrict__ ckT)
{
    int i = blockIdx.x * 256 + threadIdx.x;
    int m = i >> 7, d = i & 127;
    ckT[d*NC + m] = ck[m*D + d];
}

// ---------------- cmp softmax / mask / block-score --------------------------
__global__ void cmp_softmax_kernel(float* __restrict__ sc,
                                   float* __restrict__ blks)
{
    int n = blockIdx.x;
    __shared__ float pcs[HQ][NC];
    int tid = threadIdx.x;

    float* base = sc + (size_t)n * HQ * NC;
    {
        int h = tid >> 4, m4 = (tid & 15) * 4;
        float4 vv = *(float4*)&base[h*NC + m4];
        float s[4] = {vv.x, vv.y, vv.z, vv.w};
#pragma unroll
        for (int u = 0; u < 4; u++) {
            int m = m4 + u;
            bool valid = (n >= m*STRIDE + KS - 1);
            s[u] = valid ? s[u] * SCALE : NEGF;
        }
        pcs[h][m4+0] = s[0]; pcs[h][m4+1] = s[1];
        pcs[h][m4+2] = s[2]; pcs[h][m4+3] = s[3];
    }
    __syncthreads();

    {
        int w = tid >> 5, l = tid & 31;
        for (int h = w; h < HQ; h += 8) {
            float a = pcs[h][l], b = pcs[h][l + 32];
            float mx = fmaxf(a, b);
#pragma unroll
            for (int o = 16; o > 0; o >>= 1) mx = fmaxf(mx, __shfl_xor_sync(0xffffffff, mx, o));
            float ea = __expf(a - mx), eb = __expf(b - mx);
            float s = ea + eb;
#pragma unroll
            for (int o = 16; o > 0; o >>= 1) s += __shfl_xor_sync(0xffffffff, s, o);
            float inv = 1.f / s;
            bool va = (n >= l*STRIDE + KS - 1);
            bool vb = (n >= (l+32)*STRIDE + KS - 1);
            pcs[h][l]      = va ? ea * inv : 0.f;
            pcs[h][l + 32] = vb ? eb * inv : 0.f;
        }
    }
    __syncthreads();

    for (int m = tid; m < NC; m += 256) {
        float s = 0.f;
        for (int h = 0; h < HQ; h++) s += pcs[h][m];
        blks[(size_t)n*NC + m] = s;
    }
    {
        int h = tid >> 4, m4 = (tid & 15) * 4;
        *(float4*)&base[h*NC + m4] =
            make_float4(pcs[h][m4], pcs[h][m4+1], pcs[h][m4+2], pcs[h][m4+3]);
    }
}

// ---------------- top-k selection ------------------------------------------
__global__ void topk_kernel(const float* __restrict__ blks, int* __restrict__ topk)
{
    int n = blockIdx.x * blockDim.x + threadIdx.x;
    if (n >= N_TOK) return;
    float sel[NC];
    int tb = n / BSZ;
    for (int m = 0; m < NC; m++) {
        float s = blks[(size_t)n*NC + m];
        if (m > tb) s = NEGF;
        if (m < 1 || (m <= tb && m > tb - 2)) s = 1e30f;
        sel[m] = s;
    }
    for (int j = 0; j < TOPK; j++) {
        int bi = 0; float bv = sel[0];
        for (int m = 1; m < NC; m++) if (sel[m] > bv) { bv = sel[m]; bi = m; }
        topk[n*TOPK + j] = bi;
        sel[bi] = -FLT_MAX;
    }
}

// ============ SIMT helpers (sel attention) ==================================
#define KVP 132

__device__ __forceinline__ void attn_softmax_update(
    float* sc, float* mS, float* lS, float* fS, int tid)
{
    int h = tid >> 4, t = tid & 15;
    float4 sv = *(float4*)&sc[h*64 + t*4];
    float pm = fmaxf(fmaxf(sv.x, sv.y), fmaxf(sv.z, sv.w));
#pragma unroll
    for (int o = 1; o < 16; o <<= 1) pm = fmaxf(pm, __shfl_xor_sync(0xffffffff, pm, o));
    float mOld = mS[h];
    float mNew = fmaxf(mOld, pm);
    float4 p;
    p.x = __expf(sv.x - mNew); p.y = __expf(sv.y - mNew);
    p.z = __expf(sv.z - mNew); p.w = __expf(sv.w - mNew);
    *(float4*)&sc[h*64 + t*4] = p;
    float ps = p.x + p.y + p.z + p.w;
#pragma unroll
    for (int o = 1; o < 16; o <<= 1) ps += __shfl_xor_sync(0xffffffff, ps, o);
    if (t == 0) {
        float f = __expf(mOld - mNew);
        fS[h] = f;
        lS[h] = lS[h] * f + ps;
        mS[h] = mNew;
    }
}

__device__ __forceinline__ void attn_pv(
    const float* kv, const float* sc, float* acc, float f, int h, int d0, int tl)
{
#pragma unroll
    for (int i = 0; i < 8; i++) acc[i] *= f;
    for (int j = 0; j < tl; j++) {
        float p = sc[h*64 + j];
        float4 v0 = *(const float4*)&kv[j*KVP + d0];
        float4 v1 = *(const float4*)&kv[j*KVP + d0 + 4];
        acc[0] += p*v0.x; acc[1] += p*v0.y; acc[2] += p*v0.z; acc[3] += p*v0.w;
        acc[4] += p*v1.x; acc[5] += p*v1.y; acc[6] += p*v1.z; acc[7] += p*v1.w;
    }
}

// ---------------- selected (top-k) attention (SIMT, round-10 form) ----------
__global__ void __launch_bounds__(256, 2)
sel_attn_kernel(const float* __restrict__ q, const float* __restrict__ k,
                const float* __restrict__ v, const int* __restrict__ topk,
                float* __restrict__ out)
{
    int n = blockIdx.x;
    int tid = threadIdx.x;
    __shared__ float qs[HQ*D];
    __shared__ float kv[64*KVP];
    __shared__ float sc[HQ*64];
    __shared__ int   posA[TOPK*BSZ];
    __shared__ float mS[HQ], lS[HQ], fS[HQ];

    for (int e = tid; e < HQ*D/4; e += 256)
        ((float4*)qs)[e] = ((const float4*)(q + (size_t)n*HQ*D))[e];
    if (tid < HQ) { mS[tid] = -FLT_MAX; lS[tid] = 0.f; }
    posA[tid] = topk[n*TOPK + (tid >> 5)] * BSZ + (tid & 31);

    int h  = tid >> 4;
    int d0 = (tid & 15) * 8;
    float acc[8];
#pragma unroll
    for (int i = 0; i < 8; i++) acc[i] = 0.f;
    __syncthreads();

    for (int t0 = 0; t0 < TOPK*BSZ; t0 += 64) {
        for (int e = tid; e < 64*32; e += 256) {
            int row = e >> 5, c = e & 31;
            *(float4*)&kv[row*KVP + c*4] = ((const float4*)(k + (size_t)posA[t0 + row]*D))[c];
        }
        __syncthreads();
        {
            int jj = tid & 63;
            int hb = (tid >> 6) * 4;
            bool valid = posA[t0 + jj] <= n;
            float s0=0.f,s1=0.f,s2=0.f,s3=0.f;
            if (valid) {
                const float4* kr = (const float4*)(kv + jj*KVP);
                const float4* q0 = (const float4*)(qs + (hb+0)*D);
                const float4* q1 = (const float4*)(qs + (hb+1)*D);
                const float4* q2 = (const float4*)(qs + (hb+2)*D);
                const float4* q3 = (const float4*)(qs + (hb+3)*D);
#pragma unroll
                for (int c = 0; c < 32; c++) {
                    float4 kk = kr[c];
                    float4 a;
                    a = q0[c]; s0 += a.x*kk.x + a.y*kk.y + a.z*kk.z + a.w*kk.w;
                    a = q1[c]; s1 += a.x*kk.x + a.y*kk.y + a.z*kk.z + a.w*kk.w;
                    a = q2[c]; s2 += a.x*kk.x + a.y*kk.y + a.z*kk.z + a.w*kk.w;
                    a = q3[c]; s3 += a.x*kk.x + a.y*kk.y + a.z*kk.z + a.w*kk.w;
                }
                sc[(hb+0)*64+jj]=s0*SCALE; sc[(hb+1)*64+jj]=s1*SCALE;
                sc[(hb+2)*64+jj]=s2*SCALE; sc[(hb+3)*64+jj]=s3*SCALE;
            } else {
                sc[(hb+0)*64+jj]=NEGF; sc[(hb+1)*64+jj]=NEGF;
                sc[(hb+2)*64+jj]=NEGF; sc[(hb+3)*64+jj]=NEGF;
            }
        }
        __syncthreads();
        attn_softmax_update(sc, mS, lS, fS, tid);
        __syncthreads();
        for (int e = tid; e < 64*32; e += 256) {
            int row = e >> 5, c = e & 31;
            *(float4*)&kv[row*KVP + c*4] = ((const float4*)(v + (size_t)posA[t0 + row]*D))[c];
        }
        __syncthreads();
        attn_pv(kv, sc, acc, fS[h], h, d0, 64);
        __syncthreads();
    }
    float inv = 1.f / lS[h];
    float4 o0 = make_float4(acc[0]*inv, acc[1]*inv, acc[2]*inv, acc[3]*inv);
    float4 o1 = make_float4(acc[4]*inv, acc[5]*inv, acc[6]*inv, acc[7]*inv);
    *(float4*)&out[((size_t)n*HQ + h)*D + d0]     = o0;
    *(float4*)&out[((size_t)n*HQ + h)*D + d0 + 4] = o1;
}

// ================= window attention via 1-term tf32 tensor cores ============
__global__ void __launch_bounds__(256, 2)
win_mma_kernel(const float* __restrict__ q, const float* __restrict__ k,
               const float* __restrict__ v, float* __restrict__ out)
{
    extern __shared__ uint2 smw[];
    uint2* Qh = smw;
    uint2* Bh = smw + 4096;
    uint2* Ph = smw + 8192;
    float* stats = (float*)(smw + 10240);
    float* mS   = stats;
    float* lS   = stats + 64;
    float* fS   = stats + 128;
    float* pmax = stats + 192;
    float* psum = stats + 320;

    const int tid = threadIdx.x;
    const int wid = tid >> 5, lane = tid & 31;
    const int g = lane >> 2, tg = lane & 3;
    const int qtile0 = blockIdx.x * 64;
    const int h = blockIdx.y;

    for (int e = tid; e < 64*32; e += 256) {
        int row = e >> 5, c4 = e & 31;
        float4 vq = *(const float4*)&q[(((size_t)(qtile0 + row))*HQ + h)*D + c4*4];
        float qv[4] = {vq.x, vq.y, vq.z, vq.w};
#pragma unroll
        for (int u = 0; u < 4; u++) {
            int d = c4*4 + u;
            int ch = d >> 4, kk = d & 15;
            int p = ((kk >> 3) << 2) | (kk & 3);
            int cc = (kk >> 2) & 1;
            int ph = p ^ ((row & 3) << 1);
            ((uint32_t*)&Qh[ch*512 + (row << 3) + ph])[cc] = f2tf32(qv[u]);
        }
    }
    if (tid < 64) { mS[tid] = -3.0e38f; lS[tid] = 0.f; }

    const int mtS = wid & 3, cg = wid >> 2;
    const int mtP = wid & 3, dh = wid >> 2;

    float oacc[8][4];
#pragma unroll
    for (int ni = 0; ni < 8; ni++)
#pragma unroll
        for (int r = 0; r < 4; r++) oacc[ni][r] = 0.f;

    int klo = qtile0 - WIN; if (klo < 0) klo = 0;
    __syncthreads();

    for (int kt = klo; kt < qtile0 + 64; kt += 64) {
        for (int e = tid; e < 64*32; e += 256) {
            int key = e >> 5, c4 = e & 31;
            float4 vk = *(const float4*)&k[((size_t)(kt + key))*D + c4*4];
            float kv4[4] = {vk.x, vk.y, vk.z, vk.w};
#pragma unroll
            for (int u = 0; u < 4; u++) {
                int d = c4*4 + u;
                int ch = d >> 4, kk = d & 15;
                int p = ((kk >> 3) << 2) | (kk & 3);
                int cc = (kk >> 2) & 1;
                int ph = p ^ ((key & 3) << 1);
                ((uint32_t*)&Bh[ch*512 + (key << 3) + ph])[cc] = f2tf32(kv4[u]);
            }
        }
        __syncthreads();

        float sacc[4][4];
#pragma unroll
        for (int ni = 0; ni < 4; ni++)
#pragma unroll
            for (int r = 0; r < 4; r++) sacc[ni][r] = 0.f;

#pragma unroll
        for (int ch = 0; ch < 8; ch++) {
#pragma unroll
            for (int hb = 0; hb < 2; hb++) {
                const int ph = (hb*4 + tg) ^ ((g & 3) << 1);
                int r = mtS*16 + g;
                uint2 a0 = Qh[ch*512 + (r << 3) + ph];
                uint2 a1 = Qh[ch*512 + ((r + 8) << 3) + ph];
                uint32_t afH[4] = {a0.x, a1.x, a0.y, a1.y};
#pragma unroll
                for (int ni = 0; ni < 4; ni++) {
                    int col = cg*32 + ni*8 + g;
                    uint2 bH = Bh[ch*512 + (col << 3) + ph];
                    mma_tf32(sacc[ni], afH, bH.x, bH.y);
                }
            }
        }

        const int rA = qtile0 + mtS*16 + g;
        const int rB = rA + 8;
        float m1 = -3.0e38f, m2 = -3.0e38f;
#pragma unroll
        for (int ni = 0; ni < 4; ni++) {
            int key0 = kt + cg*32 + ni*8 + tg*2;
#pragma unroll
            for (int i = 0; i < 4; i++) {
                int key = key0 + (i & 1);
                int qp = (i < 2) ? rA : rB;
                float s = sacc[ni][i] * SCALE;
                bool valid = (key <= qp) && (key >= qp - WIN);
                s = valid ? s : NEGF;
                sacc[ni][i] = s;
                if (i < 2) m1 = fmaxf(m1, s); else m2 = fmaxf(m2, s);
            }
        }
#pragma unroll
        for (int o = 1; o < 4; o <<= 1) {
            m1 = fmaxf(m1, __shfl_xor_sync(0xffffffff, m1, o));
            m2 = fmaxf(m2, __shfl_xor_sync(0xffffffff, m2, o));
        }
        int rlA = mtS*16 + g, rlB = rlA + 8;
        if (tg == 0) { pmax[rlA*2 + cg] = m1; pmax[rlB*2 + cg] = m2; }
        __syncthreads();

        float mnA = fmaxf(mS[rlA], fmaxf(pmax[rlA*2], pmax[rlA*2+1]));
        float mnB = fmaxf(mS[rlB], fmaxf(pmax[rlB*2], pmax[rlB*2+1]));
        float sumA = 0.f, sumB = 0.f;
#pragma unroll
        for (int ni = 0; ni < 4; ni++) {
#pragma unroll
            for (int i = 0; i < 4; i++) {
                float s = sacc[ni][i];
                float mn = (i < 2) ? mnA : mnB;
                float p = (s <= -1e29f) ? 0.f : __expf(s - mn);
                if (i < 2) sumA += p; else sumB += p;
                int cloc = cg*32 + ni*8 + tg*2 + (i & 1);
                int ch = cloc >> 4, kk = cloc & 15;
                int pp = ((kk >> 3) << 2) | (kk & 3);
                int cc = (kk >> 2) & 1;
                int rl = (i < 2) ? rlA : rlB;
                int ph = pp ^ ((rl & 3) << 1);
                ((uint32_t*)&Ph[ch*512 + (rl << 3) + ph])[cc] = f2tf32(p);
            }
        }
#pragma unroll
        for (int o = 1; o < 4; o <<= 1) {
            sumA += __shfl_xor_sync(0xffffffff, sumA, o);
            sumB += __shfl_xor_sync(0xffffffff, sumB, o);
        }
        if (tg == 0) { psum[rlA*2 + cg] = sumA; psum[rlB*2 + cg] = sumB; }

        for (int e = tid; e < 64*32; e += 256) {
            int key = e >> 5, c4 = e & 31;
            float4 vv = *(const float4*)&v[((size_t)(kt + key))*D + c4*4];
            float v4[4] = {vv.x, vv.y, vv.z, vv.w};
            int chv = key >> 4, kkv = key & 15;
            int pv = ((kkv >> 3) << 2) | (kkv & 3);
            int ccv = (kkv >> 2) & 1;
#pragma unroll
            for (int u = 0; u < 4; u++) {
                int d = c4*4 + u;
                int phv = pv ^ ((d & 3) << 1);
                ((uint32_t*)&Bh[chv*1024 + (d << 3) + phv])[ccv] = f2tf32(v4[u]);
            }
        }
        __syncthreads();

        if (tid < 64) {
            float mo = mS[tid];
            float mn = fmaxf(mo, fmaxf(pmax[tid*2], pmax[tid*2+1]));
            float f = __expf(mo - mn);
            lS[tid] = lS[tid] * f + psum[tid*2] + psum[tid*2+1];
            mS[tid] = mn;
            fS[tid] = f;
        }
        __syncthreads();

        {
            int rl1 = mtP*16 + g, rl2 = rl1 + 8;
            float f1 = fS[rl1], f2 = fS[rl2];
#pragma unroll
            for (int ni = 0; ni < 8; ni++) {
                oacc[ni][0] *= f1; oacc[ni][1] *= f1;
                oacc[ni][2] *= f2; oacc[ni][3] *= f2;
            }
#pragma unroll
            for (int ch = 0; ch < 4; ch++) {
#pragma unroll
                for (int hb = 0; hb < 2; hb++) {
                    const int ph = (hb*4 + tg) ^ ((g & 3) << 1);
                    int r = mtP*16 + g;
                    uint2 a0 = Ph[ch*512 + (r << 3) + ph];
                    uint2 a1 = Ph[ch*512 + ((r + 8) << 3) + ph];
                    uint32_t afH[4] = {a0.x, a1.x, a0.y, a1.y};
#pragma unroll
                    for (int ni = 0; ni < 8; ni++) {
                        int col = dh*64 + ni*8 + g;
                        uint2 bH = Bh[ch*1024 + (col << 3) + ph];
                        mma_tf32(oacc[ni], afH, bH.x, bH.y);
                    }
                }
            }
        }
        __syncthreads();
    }

    {
        int rl1 = mtP*16 + g, rl2 = rl1 + 8;
        float i1 = 1.f / lS[rl1], i2 = 1.f / lS[rl2];
        size_t b1 = ((size_t)(qtile0 + rl1)*HQ + h)*D;
        size_t b2 = ((size_t)(qtile0 + rl2)*HQ + h)*D;
#pragma unroll
        for (int ni = 0; ni < 8; ni++) {
            int d = dh*64 + ni*8 + tg*2;
            *(float2*)&out[b1 + d] = make_float2(oacc[ni][0]*i1, oacc[ni][1]*i1);
            *(float2*)&out[b2 + d] = make_float2(oacc[ni][2]*i2, oacc[ni][3]*i2);
        }
    }
}

// ---------------- gate combine ---------------------------------------------
__global__ void combine_kernel(const float* __restrict__ gbuf,
                               const float* __restrict__ cmp,
                               const float* __restrict__ sp,
                               const float* __restrict__ sw,
                               float* __restrict__ att)
{
    size_t idx = (size_t)blockIdx.x * 256 + threadIdx.x;
    int n = (int)(idx >> 11);
    int hd = (int)(idx & 2047);
    int h = hd >> 7;
    const float* g = gbuf + (size_t)n*HQ*3 + h*3;
    float g0 = 1.f / (1.f + __expf(-g[0]));
    float g1 = 1.f / (1.f + __expf(-g[1]));
    float g2 = 1.f / (1.f + __expf(-g[2]));
    att[idx] = g0 * cmp[idx] + g1 * sp[idx] + g2 * sw[idx];
}

// ---------------- launcher with stream fork/join -----------------------------
extern "C" void kernel_launch(void* const* d_in, const int* in_sizes, int n_in,
                              void* d_out, int out_size)
{
    const float* x  = (const float*)d_in[0];
    const float* Wq = (const float*)d_in[2];
    const float* Wk = (const float*)d_in[3];
    const float* Wv = (const float*)d_in[4];
    const float* Wo = (const float*)d_in[5];
    const float* Wg = (const float*)d_in[6];
    const float* pe = (const float*)d_in[7];
    float* out = (float*)d_out;

    float *q, *k, *v, *ck, *ckT, *cv, *blks, *cmp, *sp, *sw, *gate, *att;
    float *part, *partG, *partQ;
    int* tk;
    cudaGetSymbolAddress((void**)&q,    g_q);
    cudaGetSymbolAddress((void**)&k,    g_k);
    cudaGetSymbolAddress((void**)&v,    g_v);
    cudaGetSymbolAddress((void**)&ck,   g_ck);
    cudaGetSymbolAddress((void**)&ckT,  g_ckT);
    cudaGetSymbolAddress((void**)&cv,   g_cv);
    cudaGetSymbolAddress((void**)&blks, g_blks);
    cudaGetSymbolAddress((void**)&tk,   g_topk);
    cudaGetSymbolAddress((void**)&cmp,  g_cmp);
    cudaGetSymbolAddress((void**)&sp,   g_sp);
    cudaGetSymbolAddress((void**)&sw,   g_sw);
    cudaGetSymbolAddress((void**)&gate, g_gate);
    cudaGetSymbolAddress((void**)&att,  g_att);
    cudaGetSymbolAddress((void**)&part, g_part);
    cudaGetSymbolAddress((void**)&partG,g_partG);
    cudaGetSymbolAddress((void**)&partQ,g_partQ);

    const int SMEM3 = 65536;
    const int SMEM1 = 32768;
    const int SMEMW = 10240*8 + 448*4;
    cudaFuncSetAttribute(gemm_kernel<3>, cudaFuncAttributeMaxDynamicSharedMemorySize, SMEM3);
    cudaFuncSetAttribute(gemm_kernel<1>, cudaFuncAttributeMaxDynamicSharedMemorySize, SMEM1);
    cudaFuncSetAttribute(win_mma_kernel, cudaFuncAttributeMaxDynamicSharedMemorySize, SMEMW);

    static cudaStream_t sB = nullptr, sC = nullptr;
    static cudaEvent_t evRoot = nullptr, evQ = nullptr, evKV = nullptr,
                       evTK = nullptr, evCMP = nullptr, evSEL = nullptr;
    if (!sB) {
        cudaStreamCreateWithFlags(&sB, cudaStreamNonBlocking);
        cudaStreamCreateWithFlags(&sC, cudaStreamNonBlocking);
        cudaEventCreateWithFlags(&evRoot, cudaEventDisableTiming);
        cudaEventCreateWithFlags(&evQ,    cudaEventDisableTiming);
        cudaEventCreateWithFlags(&evKV,   cudaEventDisableTiming);
        cudaEventCreateWithFlags(&evTK,   cudaEventDisableTiming);
        cudaEventCreateWithFlags(&evCMP,  cudaEventDisableTiming);
        cudaEventCreateWithFlags(&evSEL,  cudaEventDisableTiming);
    }

    cudaEventRecord(evRoot, 0);
    cudaStreamWaitEvent(sB, evRoot, 0);
    cudaStreamWaitEvent(sC, evRoot, 0);

    // --- spine A (default): Wq split-K=2 -> reduce -> ropeQ -----------------
    gemm_kernel<3><<<dim3(16, 16, 2), 256, SMEM3>>>(x, Wq, q, partQ, HID, HQ*D);
    splitk_reduce_kernel<<<(N_TOK*HQ*D + 255)/256, 256>>>(partQ, q, N_TOK*HQ*D, 2);
    rope_kernel<<<N_TOK, 64>>>(q, HQ, 1);
    cudaEventRecord(evQ, 0);

    // --- spine B: k/v chain -> cmp scores -> topk ---------------------------
    gemm_kernel<3><<<dim3(1, 16, 8), 256, SMEM3, sB>>>(x, Wk, k, part, HID, D);
    splitk_reduce_kernel<<<(N_TOK*D + 255)/256, 256, 0, sB>>>(part, k, N_TOK*D, 8);
    gemm_kernel<1><<<dim3(1, 16, 8), 256, SMEM1, sB>>>(x, Wv, v, part, HID, D);
    splitk_reduce_kernel<<<(N_TOK*D + 255)/256, 256, 0, sB>>>(part, v, N_TOK*D, 8);
    compress_kernel<<<NC, D, 0, sB>>>(k, v, pe, ck, cv);
    rope_kernel<<<N_TOK, 64, 0, sB>>>(k, 1, 1);
    rope_kernel<<<NC, 64, 0, sB>>>(ck, 1, STRIDE);
    transpose_ck_kernel<<<32, 256, 0, sB>>>(ck, ckT);
    cudaEventRecord(evKV, sB);

    cudaStreamWaitEvent(sB, evQ, 0);
    gemm_kernel<3><<<dim3(1, 256, 1), 256, SMEM3, sB>>>(q, ckT, part, nullptr, D, NC);
    cmp_softmax_kernel<<<N_TOK, 256, 0, sB>>>(part, blks);
    topk_kernel<<<N_TOK/256, 256, 0, sB>>>(blks, tk);
    cudaEventRecord(evTK, sB);
    gemm_kernel<1><<<dim3(1, 256, 1), 256, SMEM1, sB>>>(part, cv, cmp, nullptr, NC, D);
    cudaEventRecord(evCMP, sB);

    // --- spine C: gate projection, then sel after topk ----------------------
    gemm_kernel<1><<<dim3(1, 16, 8), 256, SMEM1, sC>>>(x, Wg, gate, partG, HID, HQ*3);
    splitk_reduce_kernel<<<(N_TOK*HQ*3 + 255)/256, 256, 0, sC>>>(partG, gate, N_TOK*HQ*3, 8);
    cudaStreamWaitEvent(sC, evTK, 0);
    sel_attn_kernel<<<N_TOK, 256, 0, sC>>>(q, k, v, tk, sp);
    cudaEventRecord(evSEL, sC);

    // --- spine A continues: win after k/v ready -----------------------------
    cudaStreamWaitEvent(0, evKV, 0);
    win_mma_kernel<<<dim3(32, HQ), 256, SMEMW>>>(q, k, v, sw);

    // join
    cudaStreamWaitEvent(0, evSEL, 0);
    cudaStreamWaitEvent(0, evCMP, 0);
    combine_kernel<<<(N_TOK*HQ*D)/256, 256>>>(gate, cmp, sp, sw, att);
    gemm_kernel<1><<<dim3(16, 16, 1), 256, SMEM1>>>(att, Wo, out, nullptr, HID, HID);
}

// round 14
// speedup vs baseline: 1.0384x; 1.0120x over previous
#include <cuda_runtime.h>
#include <cuda_bf16.h>
#include <math.h>
#include <float.h>
#include <stdint.h>

#define N_TOK 2048
#define HID   2048
#define HQ    16
#define D     128
#define NC    64
#define KS    32
#define STRIDE 32
#define BSZ   32
#define TOPK  8
#define WIN   512
#define SCALE 0.08838834764831845f  /* 1/sqrt(128) */
#define NEGF  -1e30f

// ---------------- scratch (device globals) ---------------------------------
__device__ float g_q   [N_TOK*HQ*D];
__device__ float g_k   [N_TOK*D];
__device__ float g_v   [N_TOK*D];
__device__ float g_ck  [NC*D];
__device__ float g_ckT [D*NC];
__device__ float g_cv  [NC*D];
__device__ float g_blks[N_TOK*NC];
__device__ int   g_topk[N_TOK*TOPK];
__device__ float g_cmp [N_TOK*HQ*D];
__device__ float g_sp  [N_TOK*HQ*D];
__device__ float g_sw  [N_TOK*HQ*D];
__device__ float g_gate[N_TOK*HQ*3];
__device__ float g_att [N_TOK*HID];
__device__ float g_part [8 * N_TOK * 128];
__device__ float g_partG[8 * N_TOK * 48];

// ---------------- tf32 helpers ----------------------------------------------
__device__ __forceinline__ uint32_t f2tf32(float f) {
    uint32_t u;
    asm("cvt.rna.tf32.f32 %0, %1;" : "=r"(u) : "f"(f));
    return u;
}
__device__ __forceinline__ void mma_tf32(float* c, const uint32_t* a,
                                         uint32_t b0, uint32_t b1) {
    asm volatile(
        "mma.sync.aligned.m16n8k8.row.col.f32.tf32.tf32.f32 "
        "{%0,%1,%2,%3}, {%4,%5,%6,%7}, {%8,%9}, {%0,%1,%2,%3};"
        : "+f"(c[0]), "+f"(c[1]), "+f"(c[2]), "+f"(c[3])
        : "r"(a[0]), "r"(a[1]), "r"(a[2]), "r"(a[3]), "r"(b0), "r"(b1));
}

// ---------------- tf32 GEMM: C[rows,M]=A[rows,K]@B[K,M] ----------------------
template<int TERMS>
__global__ void __launch_bounds__(256, 2)
gemm_kernel(const float* __restrict__ A, const float* __restrict__ B,
            float* __restrict__ C, float* __restrict__ Cpart, int K, int M)
{
    extern __shared__ uint2 sm[];
    uint2* AsH = sm;
    uint2* BsH = sm + 2048;
    uint2* AsL = sm + 4096;
    uint2* BsL = sm + 6144;

    const int tid = threadIdx.x;
    const int wid = tid >> 5, lane = tid & 31;
    const int row0 = blockIdx.y * 128, col0 = blockIdx.x * 128;
    const int wr = (wid & 1) * 64, wc = (wid >> 1) * 32;
    const int g = lane >> 2, tg = lane & 3;
    const int S = gridDim.z, Kc = K / S, kbeg = blockIdx.z * Kc;

    const int arow = tid >> 1, akb = (tid & 1) * 8;
    const int bkrow = tid >> 4, bcol = (tid & 15) * 8;
    const bool bval0 = (col0 + bcol + 4) <= M;
    const bool bval1 = (col0 + bcol + 8) <= M;

    const float* Ag = A + (size_t)(row0 + arow) * K + akb;
    const float* Bg = B + (size_t)bkrow * M + col0 + bcol;

    float acc[4][4][4];
#pragma unroll
    for (int mt = 0; mt < 4; mt++)
#pragma unroll
        for (int ni = 0; ni < 4; ni++)
#pragma unroll
            for (int r = 0; r < 4; r++) acc[mt][ni][r] = 0.f;

    float av[8], bb[8];

    auto loadG = [&](int k0) {
        float4 t0 = *(const float4*)(Ag + k0);
        float4 t1 = *(const float4*)(Ag + k0 + 4);
        av[0]=t0.x; av[1]=t0.y; av[2]=t0.z; av[3]=t0.w;
        av[4]=t1.x; av[5]=t1.y; av[6]=t1.z; av[7]=t1.w;
        const float* bp = Bg + (size_t)k0 * M;
        float4 u0 = bval0 ? *(const float4*)bp       : make_float4(0,0,0,0);
        float4 u1 = bval1 ? *(const float4*)(bp + 4) : make_float4(0,0,0,0);
        bb[0]=u0.x; bb[1]=u0.y; bb[2]=u0.z; bb[3]=u0.w;
        bb[4]=u1.x; bb[5]=u1.y; bb[6]=u1.z; bb[7]=u1.w;
    };

    auto storeS = [&](int st) {
        const int sbase = st << 10;
#pragma unroll
        for (int u = 0; u < 8; u++) {
            int k = akb + u;
            int p = ((k >> 3) << 2) | (k & 3);
            int c = (k >> 2) & 1;
            int ph = p ^ ((arow & 3) << 1);
            uint32_t hi = f2tf32(av[u]);
            ((uint32_t*)&AsH[sbase + (arow << 3) + ph])[c] = hi;
            if (TERMS == 3) {
                uint32_t lo = f2tf32(av[u] - __uint_as_float(hi));
                ((uint32_t*)&AsL[sbase + (arow << 3) + ph])[c] = lo;
            }
        }
        {
            int k = bkrow;
            int p = ((k >> 3) << 2) | (k & 3);
            int c = (k >> 2) & 1;
#pragma unroll
            for (int u = 0; u < 8; u++) {
                int col = bcol + u;
                int ph = p ^ ((col & 3) << 1);
                uint32_t hi = f2tf32(bb[u]);
                ((uint32_t*)&BsH[sbase + (col << 3) + ph])[c] = hi;
                if (TERMS == 3) {
                    uint32_t lo = f2tf32(bb[u] - __uint_as_float(hi));
                    ((uint32_t*)&BsL[sbase + (col << 3) + ph])[c] = lo;
                }
            }
        }
    };

    auto compute = [&](int st) {
        const int sbase = st << 10;
#pragma unroll
        for (int hb = 0; hb < 2; hb++) {
            const int ph = (hb * 4 + tg) ^ ((g & 3) << 1);
            uint32_t afH[4][4];
            uint2 bH[4];
#pragma unroll
            for (int mt = 0; mt < 4; mt++) {
                int r = wr + mt * 16 + g;
                uint2 p0 = AsH[sbase + (r << 3) + ph];
                uint2 p1 = AsH[sbase + ((r + 8) << 3) + ph];
                afH[mt][0] = p0.x; afH[mt][1] = p1.x;
                afH[mt][2] = p0.y; afH[mt][3] = p1.y;
            }
#pragma unroll
            for (int ni = 0; ni < 4; ni++) {
                int cc = wc + ni * 8 + g;
                bH[ni] = BsH[sbase + (cc << 3) + ph];
            }
#pragma unroll
            for (int ni = 0; ni < 4; ni++)
#pragma unroll
                for (int mt = 0; mt < 4; mt++)
                    mma_tf32(acc[mt][ni], afH[mt], bH[ni].x, bH[ni].y);
            if (TERMS == 3) {
                uint2 bL[4];
#pragma unroll
                for (int ni = 0; ni < 4; ni++) {
                    int cc = wc + ni * 8 + g;
                    bL[ni] = BsL[sbase + (cc << 3) + ph];
                }
#pragma unroll
                for (int ni = 0; ni < 4; ni++)
#pragma unroll
                    for (int mt = 0; mt < 4; mt++)
                        mma_tf32(acc[mt][ni], afH[mt], bL[ni].x, bL[ni].y);
#pragma unroll
                for (int mt = 0; mt < 4; mt++) {
                    int r = wr + mt * 16 + g;
                    uint2 p0 = AsL[sbase + (r << 3) + ph];
                    uint2 p1 = AsL[sbase + ((r + 8) << 3) + ph];
                    uint32_t afL[4] = {p0.x, p1.x, p0.y, p1.y};
#pragma unroll
                    for (int ni = 0; ni < 4; ni++)
                        mma_tf32(acc[mt][ni], afL, bH[ni].x, bH[ni].y);
                }
            }
        }
    };

    loadG(kbeg);
    storeS(0);
    __syncthreads();

    const int nIter = Kc >> 4;
    for (int it = 0; it < nIter; it++) {
        int st = it & 1;
        bool hasNext = (it + 1 < nIter);
        if (hasNext) loadG(kbeg + (it + 1) * 16);
        compute(st);
        if (hasNext) storeS(st ^ 1);
        __syncthreads();
    }

    float* Cout = (S == 1) ? C : (Cpart + (size_t)blockIdx.z * N_TOK * M);
#pragma unroll
    for (int mt = 0; mt < 4; mt++) {
#pragma unroll
        for (int ni = 0; ni < 4; ni++) {
            int r = row0 + wr + mt * 16 + g;
            int c = col0 + wc + ni * 8 + tg * 2;
            if (c + 2 <= M) {
                *(float2*)&Cout[(size_t)r * M + c] =
                    make_float2(acc[mt][ni][0], acc[mt][ni][1]);
                *(float2*)&Cout[(size_t)(r + 8) * M + c] =
                    make_float2(acc[mt][ni][2], acc[mt][ni][3]);
            }
        }
    }
}

__global__ void splitk_reduce_kernel(const float* __restrict__ part,
                                     float* __restrict__ out, int len, int S)
{
    int i = blockIdx.x * 256 + threadIdx.x;
    if (i >= len) return;
    float s = 0.f;
    for (int z = 0; z < S; z++) s += part[(size_t)z * len + i];
    out[i] = s;
}

// ---------------- compressed k/v (pre-RoPE) --------------------------------
__global__ void compress_kernel(const float* __restrict__ k,
                                const float* __restrict__ v,
                                const float* __restrict__ pe,
                                float* __restrict__ ck,
                                float* __restrict__ cv)
{
    int m = blockIdx.x;
    int d = threadIdx.x;
    float sk = 0.f, sv = 0.f;
#pragma unroll 8
    for (int i = 0; i < KS; i++) {
        sk += k[(m*KS + i)*D + d] + pe[i*D + d];
        sv += v[(m*KS + i)*D + d];
    }
    ck[m*D + d] = sk * (1.f/KS);
    cv[m*D + d] = sv * (1.f/KS);
}

// ---------------- RoPE (in place) ------------------------------------------
__global__ void rope_kernel(float* __restrict__ x, int heads, int pos_stride)
{
    int row = blockIdx.x;
    int d   = threadIdx.x;
    float inv = powf(10000.f, -(float)d / 64.f);
    float ang = (float)(row * pos_stride) * inv;
    float c = cosf(ang), s = sinf(ang);
    for (int h = 0; h < heads; h++) {
        float* p = x + ((size_t)row*heads + h) * D;
        float x1 = p[d], x2 = p[d + 64];
        p[d]      = x1 * c - x2 * s;
        p[d + 64] = x2 * c + x1 * s;
    }
}

// ---------------- ck transpose ----------------------------------------------
__global__ void transpose_ck_kernel(const float* __restrict__ ck,
                                    float* __restrict__ ckT)
{
    int i = blockIdx.x * 256 + threadIdx.x;
    int m = i >> 7, d = i & 127;
    ckT[d*NC + m] = ck[m*D + d];
}

// ---------------- cmp softmax / mask / block-score --------------------------
__global__ void cmp_softmax_kernel(float* __restrict__ sc,
                                   float* __restrict__ blks)
{
    int n = blockIdx.x;
    __shared__ float pcs[HQ][NC];
    int tid = threadIdx.x;

    float* base = sc + (size_t)n * HQ * NC;
    {
        int h = tid >> 4, m4 = (tid & 15) * 4;
        float4 vv = *(float4*)&base[h*NC + m4];
        float s[4] = {vv.x, vv.y, vv.z, vv.w};
#pragma unroll
        for (int u = 0; u < 4; u++) {
            int m = m4 + u;
            bool valid = (n >= m*STRIDE + KS - 1);
            s[u] = valid ? s[u] * SCALE : NEGF;
        }
        pcs[h][m4+0] = s[0]; pcs[h][m4+1] = s[1];
        pcs[h][m4+2] = s[2]; pcs[h][m4+3] = s[3];
    }
    __syncthreads();

    {
        int w = tid >> 5, l = tid & 31;
        for (int h = w; h < HQ; h += 8) {
            float a = pcs[h][l], b = pcs[h][l + 32];
            float mx = fmaxf(a, b);
#pragma unroll
            for (int o = 16; o > 0; o >>= 1) mx = fmaxf(mx, __shfl_xor_sync(0xffffffff, mx, o));
            float ea = __expf(a - mx), eb = __expf(b - mx);
            float s = ea + eb;
#pragma unroll
            for (int o = 16; o > 0; o >>= 1) s += __shfl_xor_sync(0xffffffff, s, o);
            float inv = 1.f / s;
            bool va = (n >= l*STRIDE + KS - 1);
            bool vb = (n >= (l+32)*STRIDE + KS - 1);
            pcs[h][l]      = va ? ea * inv : 0.f;
            pcs[h][l + 32] = vb ? eb * inv : 0.f;
        }
    }
    __syncthreads();

    for (int m = tid; m < NC; m += 256) {
        float s = 0.f;
        for (int h = 0; h < HQ; h++) s += pcs[h][m];
        blks[(size_t)n*NC + m] = s;
    }
    {
        int h = tid >> 4, m4 = (tid & 15) * 4;
        *(float4*)&base[h*NC + m4] =
            make_float4(pcs[h][m4], pcs[h][m4+1], pcs[h][m4+2], pcs[h][m4+3]);
    }
}

// ---------------- top-k selection (warp per token) --------------------------
__global__ void topk_kernel(const float* __restrict__ blks, int* __restrict__ topk)
{
    int gidx = blockIdx.x * blockDim.x + threadIdx.x;
    int n = gidx >> 5;
    int lane = threadIdx.x & 31;
    if (n >= N_TOK) return;
    int tb = n / BSZ;
    int m0 = lane, m1 = lane + 32;
    float s0 = blks[(size_t)n*NC + m0];
    float s1 = blks[(size_t)n*NC + m1];
    if (m0 > tb) s0 = NEGF;
    if (m0 < 1 || (m0 <= tb && m0 > tb - 2)) s0 = 1e30f;
    if (m1 > tb) s1 = NEGF;
    if (m1 < 1 || (m1 <= tb && m1 > tb - 2)) s1 = 1e30f;
#pragma unroll
    for (int j = 0; j < TOPK; j++) {
        float bv; int bi;
        if (s0 >= s1) { bv = s0; bi = m0; } else { bv = s1; bi = m1; }
#pragma unroll
        for (int o = 16; o > 0; o >>= 1) {
            float ov = __shfl_down_sync(0xffffffff, bv, o);
            int   oi = __shfl_down_sync(0xffffffff, bi, o);
            if (ov > bv || (ov == bv && oi < bi)) { bv = ov; bi = oi; }
        }
        bi = __shfl_sync(0xffffffff, bi, 0);
        if (lane == 0) topk[n*TOPK + j] = bi;
        if (bi == m0) s0 = -FLT_MAX;
        if (bi == m1) s1 = -FLT_MAX;
    }
}

// ============ SIMT helpers (sel attention) ==================================
#define KVP 132

__device__ __forceinline__ void attn_softmax_update(
    float* sc, float* mS, float* lS, float* fS, int tid)
{
    int h = tid >> 4, t = tid & 15;
    float4 sv = *(float4*)&sc[h*64 + t*4];
    float pm = fmaxf(fmaxf(sv.x, sv.y), fmaxf(sv.z, sv.w));
#pragma unroll
    for (int o = 1; o < 16; o <<= 1) pm = fmaxf(pm, __shfl_xor_sync(0xffffffff, pm, o));
    float mOld = mS[h];
    float mNew = fmaxf(mOld, pm);
    float4 p;
    p.x = __expf(sv.x - mNew); p.y = __expf(sv.y - mNew);
    p.z = __expf(sv.z - mNew); p.w = __expf(sv.w - mNew);
    *(float4*)&sc[h*64 + t*4] = p;
    float ps = p.x + p.y + p.z + p.w;
#pragma unroll
    for (int o = 1; o < 16; o <<= 1) ps += __shfl_xor_sync(0xffffffff, ps, o);
    if (t == 0) {
        float f = __expf(mOld - mNew);
        fS[h] = f;
        lS[h] = lS[h] * f + ps;
        mS[h] = mNew;
    }
}

__device__ __forceinline__ void attn_pv(
    const float* kv, const float* sc, float* acc, float f, int h, int d0, int tl)
{
#pragma unroll
    for (int i = 0; i < 8; i++) acc[i] *= f;
    for (int j = 0; j < tl; j++) {
        float p = sc[h*64 + j];
        float4 v0 = *(const float4*)&kv[j*KVP + d0];
        float4 v1 = *(const float4*)&kv[j*KVP + d0 + 4];
        acc[0] += p*v0.x; acc[1] += p*v0.y; acc[2] += p*v0.z; acc[3] += p*v0.w;
        acc[4] += p*v1.x; acc[5] += p*v1.y; acc[6] += p*v1.z; acc[7] += p*v1.w;
    }
}

// ---------------- selected (top-k) attention (SIMT) -------------------------
__global__ void __launch_bounds__(256, 2)
sel_attn_kernel(const float* __restrict__ q, const float* __restrict__ k,
                const float* __restrict__ v, const int* __restrict__ topk,
                float* __restrict__ out)
{
    int n = blockIdx.x;
    int tid = threadIdx.x;
    __shared__ float qs[HQ*D];
    __shared__ float kv[64*KVP];
    __shared__ float sc[HQ*64];
    __shared__ int   posA[TOPK*BSZ];
    __shared__ float mS[HQ], lS[HQ], fS[HQ];

    for (int e = tid; e < HQ*D/4; e += 256)
        ((float4*)qs)[e] = ((const float4*)(q + (size_t)n*HQ*D))[e];
    if (tid < HQ) { mS[tid] = -FLT_MAX; lS[tid] = 0.f; }
    posA[tid] = topk[n*TOPK + (tid >> 5)] * BSZ + (tid & 31);

    int h  = tid >> 4;
    int d0 = (tid & 15) * 8;
    float acc[8];
#pragma unroll
    for (int i = 0; i < 8; i++) acc[i] = 0.f;
    __syncthreads();

    for (int t0 = 0; t0 < TOPK*BSZ; t0 += 64) {
        for (int e = tid; e < 64*32; e += 256) {
            int row = e >> 5, c = e & 31;
            *(float4*)&kv[row*KVP + c*4] = ((const float4*)(k + (size_t)posA[t0 + row]*D))[c];
        }
        __syncthreads();
        {
            int jj = tid & 63;
            int hb = (tid >> 6) * 4;
            bool valid = posA[t0 + jj] <= n;
            float s0=0.f,s1=0.f,s2=0.f,s3=0.f;
            if (valid) {
                const float4* kr = (const float4*)(kv + jj*KVP);
                const float4* q0 = (const float4*)(qs + (hb+0)*D);
                const float4* q1 = (const float4*)(qs + (hb+1)*D);
                const float4* q2 = (const float4*)(qs + (hb+2)*D);
                const float4* q3 = (const float4*)(qs + (hb+3)*D);
#pragma unroll
                for (int c = 0; c < 32; c++) {
                    float4 kk = kr[c];
                    float4 a;
                    a = q0[c]; s0 += a.x*kk.x + a.y*kk.y + a.z*kk.z + a.w*kk.w;
                    a = q1[c]; s1 += a.x*kk.x + a.y*kk.y + a.z*kk.z + a.w*kk.w;
                    a = q2[c]; s2 += a.x*kk.x + a.y*kk.y + a.z*kk.z + a.w*kk.w;
                    a = q3[c]; s3 += a.x*kk.x + a.y*kk.y + a.z*kk.z + a.w*kk.w;
                }
                sc[(hb+0)*64+jj]=s0*SCALE; sc[(hb+1)*64+jj]=s1*SCALE;
                sc[(hb+2)*64+jj]=s2*SCALE; sc[(hb+3)*64+jj]=s3*SCALE;
            } else {
                sc[(hb+0)*64+jj]=NEGF; sc[(hb+1)*64+jj]=NEGF;
                sc[(hb+2)*64+jj]=NEGF; sc[(hb+3)*64+jj]=NEGF;
            }
        }
        __syncthreads();
        attn_softmax_update(sc, mS, lS, fS, tid);
        __syncthreads();
        for (int e = tid; e < 64*32; e += 256) {
            int row = e >> 5, c = e & 31;
            *(float4*)&kv[row*KVP + c*4] = ((const float4*)(v + (size_t)posA[t0 + row]*D))[c];
        }
        __syncthreads();
        attn_pv(kv, sc, acc, fS[h], h, d0, 64);
        __syncthreads();
    }
    float inv = 1.f / lS[h];
    float4 o0 = make_float4(acc[0]*inv, acc[1]*inv, acc[2]*inv, acc[3]*inv);
    float4 o1 = make_float4(acc[4]*inv, acc[5]*inv, acc[6]*inv, acc[7]*inv);
    *(float4*)&out[((size_t)n*HQ + h)*D + d0]     = o0;
    *(float4*)&out[((size_t)n*HQ + h)*D + d0 + 4] = o1;
}

// ================= window attention via 1-term tf32 tensor cores ============
// blockIdx.x is REVERSED onto qtiles: largest-work tiles launch first.
__global__ void __launch_bounds__(256, 2)
win_mma_kernel(const float* __restrict__ q, const float* __restrict__ k,
               const float* __restrict__ v, float* __restrict__ out)
{
    extern __shared__ uint2 smw[];
    uint2* Qh = smw;
    uint2* Bh = smw + 4096;
    uint2* Ph = smw + 8192;
    float* stats = (float*)(smw + 10240);
    float* mS   = stats;
    float* lS   = stats + 64;
    float* fS   = stats + 128;
    float* pmax = stats + 192;
    float* psum = stats + 320;

    const int tid = threadIdx.x;
    const int wid = tid >> 5, lane = tid & 31;
    const int g = lane >> 2, tg = lane & 3;
    const int qtile0 = (gridDim.x - 1 - blockIdx.x) * 64;   // biggest first
    const int h = blockIdx.y;

    for (int e = tid; e < 64*32; e += 256) {
        int row = e >> 5, c4 = e & 31;
        float4 vq = *(const float4*)&q[(((size_t)(qtile0 + row))*HQ + h)*D + c4*4];
        float qv[4] = {vq.x, vq.y, vq.z, vq.w};
#pragma unroll
        for (int u = 0; u < 4; u++) {
            int d = c4*4 + u;
            int ch = d >> 4, kk = d & 15;
            int p = ((kk >> 3) << 2) | (kk & 3);
            int cc = (kk >> 2) & 1;
            int ph = p ^ ((row & 3) << 1);
            ((uint32_t*)&Qh[ch*512 + (row << 3) + ph])[cc] = f2tf32(qv[u]);
        }
    }
    if (tid < 64) { mS[tid] = -3.0e38f; lS[tid] = 0.f; }

    const int mtS = wid & 3, cg = wid >> 2;
    const int mtP = wid & 3, dh = wid >> 2;

    float oacc[8][4];
#pragma unroll
    for (int ni = 0; ni < 8; ni++)
#pragma unroll
        for (int r = 0; r < 4; r++) oacc[ni][r] = 0.f;

    int klo = qtile0 - WIN; if (klo < 0) klo = 0;
    __syncthreads();

    for (int kt = klo; kt < qtile0 + 64; kt += 64) {
        for (int e = tid; e < 64*32; e += 256) {
            int key = e >> 5, c4 = e & 31;
            float4 vk = *(const float4*)&k[((size_t)(kt + key))*D + c4*4];
            float kv4[4] = {vk.x, vk.y, vk.z, vk.w};
#pragma unroll
            for (int u = 0; u < 4; u++) {
                int d = c4*4 + u;
                int ch = d >> 4, kk = d & 15;
                int p = ((kk >> 3) << 2) | (kk & 3);
                int cc = (kk >> 2) & 1;
                int ph = p ^ ((key & 3) << 1);
                ((uint32_t*)&Bh[ch*512 + (key << 3) + ph])[cc] = f2tf32(kv4[u]);
            }
        }
        __syncthreads();

        float sacc[4][4];
#pragma unroll
        for (int ni = 0; ni < 4; ni++)
#pragma unroll
            for (int r = 0; r < 4; r++) sacc[ni][r] = 0.f;

#pragma unroll
        for (int ch = 0; ch < 8; ch++) {
#pragma unroll
            for (int hb = 0; hb < 2; hb++) {
                const int ph = (hb*4 + tg) ^ ((g & 3) << 1);
                int r = mtS*16 + g;
                uint2 a0 = Qh[ch*512 + (r << 3) + ph];
                uint2 a1 = Qh[ch*512 + ((r + 8) << 3) + ph];
                uint32_t afH[4] = {a0.x, a1.x, a0.y, a1.y};
#pragma unroll
                for (int ni = 0; ni < 4; ni++) {
                    int col = cg*32 + ni*8 + g;
                    uint2 bH = Bh[ch*512 + (col << 3) + ph];
                    mma_tf32(sacc[ni], afH, bH.x, bH.y);
                }
            }
        }

        const int rA = qtile0 + mtS*16 + g;
        const int rB = rA + 8;
        float m1 = -3.0e38f, m2 = -3.0e38f;
#pragma unroll
        for (int ni = 0; ni < 4; ni++) {
            int key0 = kt + cg*32 + ni*8 + tg*2;
#pragma unroll
            for (int i = 0; i < 4; i++) {
                int key = key0 + (i & 1);
                int qp = (i < 2) ? rA : rB;
                float s = sacc[ni][i] * SCALE;
                bool valid = (key <= qp) && (key >= qp - WIN);
                s = valid ? s : NEGF;
                sacc[ni][i] = s;
                if (i < 2) m1 = fmaxf(m1, s); else m2 = fmaxf(m2, s);
            }
        }
#pragma unroll
        for (int o = 1; o < 4; o <<= 1) {
            m1 = fmaxf(m1, __shfl_xor_sync(0xffffffff, m1, o));
            m2 = fmaxf(m2, __shfl_xor_sync(0xffffffff, m2, o));
        }
        int rlA = mtS*16 + g, rlB = rlA + 8;
        if (tg == 0) { pmax[rlA*2 + cg] = m1; pmax[rlB*2 + cg] = m2; }
        __syncthreads();

        float mnA = fmaxf(mS[rlA], fmaxf(pmax[rlA*2], pmax[rlA*2+1]));
        float mnB = fmaxf(mS[rlB], fmaxf(pmax[rlB*2], pmax[rlB*2+1]));
        float sumA = 0.f, sumB = 0.f;
#pragma unroll
        for (int ni = 0; ni < 4; ni++) {
#pragma unroll
            for (int i = 0; i < 4; i++) {
                float s = sacc[ni][i];
                float mn = (i < 2) ? mnA : mnB;
                float p = (s <= -1e29f) ? 0.f : __expf(s - mn);
                if (i < 2) sumA += p; else sumB += p;
                int cloc = cg*32 + ni*8 + tg*2 + (i & 1);
                int ch = cloc >> 4, kk = cloc & 15;
                int pp = ((kk >> 3) << 2) | (kk & 3);
                int cc = (kk >> 2) & 1;
                int rl = (i < 2) ? rlA : rlB;
                int ph = pp ^ ((rl & 3) << 1);
                ((uint32_t*)&Ph[ch*512 + (rl << 3) + ph])[cc] = f2tf32(p);
            }
        }
#pragma unroll
        for (int o = 1; o < 4; o <<= 1) {
            sumA += __shfl_xor_sync(0xffffffff, sumA, o);
            sumB += __shfl_xor_sync(0xffffffff, sumB, o);
        }
        if (tg == 0) { psum[rlA*2 + cg] = sumA; psum[rlB*2 + cg] = sumB; }

        for (int e = tid; e < 64*32; e += 256) {
            int key = e >> 5, c4 = e & 31;
            float4 vv = *(const float4*)&v[((size_t)(kt + key))*D + c4*4];
            float v4[4] = {vv.x, vv.y, vv.z, vv.w};
            int chv = key >> 4, kkv = key & 15;
            int pv = ((kkv >> 3) << 2) | (kkv & 3);
            int ccv = (kkv >> 2) & 1;
#pragma unroll
            for (int u = 0; u < 4; u++) {
                int d = c4*4 + u;
                int phv = pv ^ ((d & 3) << 1);
                ((uint32_t*)&Bh[chv*1024 + (d << 3) + phv])[ccv] = f2tf32(v4[u]);
            }
        }
        __syncthreads();

        if (tid < 64) {
            float mo = mS[tid];
            float mn = fmaxf(mo, fmaxf(pmax[tid*2], pmax[tid*2+1]));
            float f = __expf(mo - mn);
            lS[tid] = lS[tid] * f + psum[tid*2] + psum[tid*2+1];
            mS[tid] = mn;
            fS[tid] = f;
        }
        __syncthreads();

        {
            int rl1 = mtP*16 + g, rl2 = rl1 + 8;
            float f1 = fS[rl1], f2 = fS[rl2];
#pragma unroll
            for (int ni = 0; ni < 8; ni++) {
                oacc[ni][0] *= f1; oacc[ni][1] *= f1;
                oacc[ni][2] *= f2; oacc[ni][3] *= f2;
            }
#pragma unroll
            for (int ch = 0; ch < 4; ch++) {
#pragma unroll
                for (int hb = 0; hb < 2; hb++) {
                    const int ph = (hb*4 + tg) ^ ((g & 3) << 1);
                    int r = mtP*16 + g;
                    uint2 a0 = Ph[ch*512 + (r << 3) + ph];
                    uint2 a1 = Ph[ch*512 + ((r + 8) << 3) + ph];
                    uint32_t afH[4] = {a0.x, a1.x, a0.y, a1.y};
#pragma unroll
                    for (int ni = 0; ni < 8; ni++) {
                        int col = dh*64 + ni*8 + g;
                        uint2 bH = Bh[ch*1024 + (col << 3) + ph];
                        mma_tf32(oacc[ni], afH, bH.x, bH.y);
                    }
                }
            }
        }
        __syncthreads();
    }

    {
        int rl1 = mtP*16 + g, rl2 = rl1 + 8;
        float i1 = 1.f / lS[rl1], i2 = 1.f / lS[rl2];
        size_t b1 = ((size_t)(qtile0 + rl1)*HQ + h)*D;
        size_t b2 = ((size_t)(qtile0 + rl2)*HQ + h)*D;
#pragma unroll
        for (int ni = 0; ni < 8; ni++) {
            int d = dh*64 + ni*8 + tg*2;
            *(float2*)&out[b1 + d] = make_float2(oacc[ni][0]*i1, oacc[ni][1]*i1);
            *(float2*)&out[b2 + d] = make_float2(oacc[ni][2]*i2, oacc[ni][3]*i2);
        }
    }
}

// ---------------- gate combine ---------------------------------------------
__global__ void combine_kernel(const float* __restrict__ gbuf,
                               const float* __restrict__ cmp,
                               const float* __restrict__ sp,
                               const float* __restrict__ sw,
                               float* __restrict__ att)
{
    size_t idx = (size_t)blockIdx.x * 256 + threadIdx.x;
    int n = (int)(idx >> 11);
    int hd = (int)(idx & 2047);
    int h = hd >> 7;
    const float* g = gbuf + (size_t)n*HQ*3 + h*3;
    float g0 = 1.f / (1.f + __expf(-g[0]));
    float g1 = 1.f / (1.f + __expf(-g[1]));
    float g2 = 1.f / (1.f + __expf(-g[2]));
    att[idx] = g0 * cmp[idx] + g1 * sp[idx] + g2 * sw[idx];
}

// ---------------- launcher with stream fork/join -----------------------------
extern "C" void kernel_launch(void* const* d_in, const int* in_sizes, int n_in,
                              void* d_out, int out_size)
{
    const float* x  = (const float*)d_in[0];
    const float* Wq = (const float*)d_in[2];
    const float* Wk = (const float*)d_in[3];
    const float* Wv = (const float*)d_in[4];
    const float* Wo = (const float*)d_in[5];
    const float* Wg = (const float*)d_in[6];
    const float* pe = (const float*)d_in[7];
    float* out = (float*)d_out;

    float *q, *k, *v, *ck, *ckT, *cv, *blks, *cmp, *sp, *sw, *gate, *att, *part, *partG;
    int* tk;
    cudaGetSymbolAddress((void**)&q,    g_q);
    cudaGetSymbolAddress((void**)&k,    g_k);
    cudaGetSymbolAddress((void**)&v,    g_v);
    cudaGetSymbolAddress((void**)&ck,   g_ck);
    cudaGetSymbolAddress((void**)&ckT,  g_ckT);
    cudaGetSymbolAddress((void**)&cv,   g_cv);
    cudaGetSymbolAddress((void**)&blks, g_blks);
    cudaGetSymbolAddress((void**)&tk,   g_topk);
    cudaGetSymbolAddress((void**)&cmp,  g_cmp);
    cudaGetSymbolAddress((void**)&sp,   g_sp);
    cudaGetSymbolAddress((void**)&sw,   g_sw);
    cudaGetSymbolAddress((void**)&gate, g_gate);
    cudaGetSymbolAddress((void**)&att,  g_att);
    cudaGetSymbolAddress((void**)&part, g_part);
    cudaGetSymbolAddress((void**)&partG,g_partG);

    const int SMEM3 = 65536;
    const int SMEM1 = 32768;
    const int SMEMW = 10240*8 + 448*4;
    cudaFuncSetAttribute(gemm_kernel<3>, cudaFuncAttributeMaxDynamicSharedMemorySize, SMEM3);
    cudaFuncSetAttribute(gemm_kernel<1>, cudaFuncAttributeMaxDynamicSharedMemorySize, SMEM1);
    cudaFuncSetAttribute(win_mma_kernel, cudaFuncAttributeMaxDynamicSharedMemorySize, SMEMW);

    static cudaStream_t sB = nullptr, sC = nullptr;
    static cudaEvent_t evRoot = nullptr, evQ = nullptr, evKV = nullptr,
                       evTK = nullptr, evCMP = nullptr, evSEL = nullptr;
    if (!sB) {
        cudaStreamCreateWithFlags(&sB, cudaStreamNonBlocking);
        cudaStreamCreateWithFlags(&sC, cudaStreamNonBlocking);
        cudaEventCreateWithFlags(&evRoot, cudaEventDisableTiming);
        cudaEventCreateWithFlags(&evQ,    cudaEventDisableTiming);
        cudaEventCreateWithFlags(&evKV,   cudaEventDisableTiming);
        cudaEventCreateWithFlags(&evTK,   cudaEventDisableTiming);
        cudaEventCreateWithFlags(&evCMP,  cudaEventDisableTiming);
        cudaEventCreateWithFlags(&evSEL,  cudaEventDisableTiming);
    }

    cudaEventRecord(evRoot, 0);
    cudaStreamWaitEvent(sB, evRoot, 0);
    cudaStreamWaitEvent(sC, evRoot, 0);

    // --- spine A (default): Wq -> ropeQ ------------------------------------
    gemm_kernel<3><<<dim3(16, 16, 1), 256, SMEM3>>>(x, Wq, q, nullptr, HID, HQ*D);
    rope_kernel<<<N_TOK, 64>>>(q, HQ, 1);
    cudaEventRecord(evQ, 0);

    // --- spine B: k/v chain -> cmp scores -> topk ---------------------------
    gemm_kernel<3><<<dim3(1, 16, 8), 256, SMEM3, sB>>>(x, Wk, k, part, HID, D);
    splitk_reduce_kernel<<<(N_TOK*D + 255)/256, 256, 0, sB>>>(part, k, N_TOK*D, 8);
    gemm_kernel<1><<<dim3(1, 16, 8), 256, SMEM1, sB>>>(x, Wv, v, part, HID, D);
    splitk_reduce_kernel<<<(N_TOK*D + 255)/256, 256, 0, sB>>>(part, v, N_TOK*D, 8);
    compress_kernel<<<NC, D, 0, sB>>>(k, v, pe, ck, cv);
    rope_kernel<<<N_TOK, 64, 0, sB>>>(k, 1, 1);
    rope_kernel<<<NC, 64, 0, sB>>>(ck, 1, STRIDE);
    transpose_ck_kernel<<<32, 256, 0, sB>>>(ck, ckT);
    cudaEventRecord(evKV, sB);

    cudaStreamWaitEvent(sB, evQ, 0);
    gemm_kernel<3><<<dim3(1, 256, 1), 256, SMEM3, sB>>>(q, ckT, part, nullptr, D, NC);
    cmp_softmax_kernel<<<N_TOK, 256, 0, sB>>>(part, blks);
    topk_kernel<<<(N_TOK*32 + 255)/256, 256, 0, sB>>>(blks, tk);
    cudaEventRecord(evTK, sB);
    gemm_kernel<1><<<dim3(1, 256, 1), 256, SMEM1, sB>>>(part, cv, cmp, nullptr, NC, D);
    cudaEventRecord(evCMP, sB);

    // --- spine C: gate projection, then sel after topk ----------------------
    gemm_kernel<1><<<dim3(1, 16, 8), 256, SMEM1, sC>>>(x, Wg, gate, partG, HID, HQ*3);
    splitk_reduce_kernel<<<(N_TOK*HQ*3 + 255)/256, 256, 0, sC>>>(partG, gate, N_TOK*HQ*3, 8);
    cudaStreamWaitEvent(sC, evTK, 0);
    sel_attn_kernel<<<N_TOK, 256, 0, sC>>>(q, k, v, tk, sp);
    cudaEventRecord(evSEL, sC);

    // --- spine A continues: win after k/v ready -----------------------------
    cudaStreamWaitEvent(0, evKV, 0);
    win_mma_kernel<<<dim3(32, HQ), 256, SMEMW>>>(q, k, v, sw);

    // join
    cudaStreamWaitEvent(0, evSEL, 0);
    cudaStreamWaitEvent(0, evCMP, 0);
    combine_kernel<<<(N_TOK*HQ*D)/256, 256>>>(gate, cmp, sp, sw, att);
    gemm_kernel<1><<<dim3(16, 16, 1), 256, SMEM1>>>(att, Wo, out, nullptr, HID, HID);
}

// round 15
// speedup vs baseline: 1.1947x; 1.1505x over previous
#include <cuda_runtime.h>
#include <cuda_bf16.h>
#include <math.h>
#include <float.h>
#include <stdint.h>

#define N_TOK 2048
#define HID   2048
#define HQ    16
#define D     128
#define NC    64
#define KS    32
#define STRIDE 32
#define BSZ   32
#define TOPK  8
#define WIN   512
#define SCALE 0.08838834764831845f  /* 1/sqrt(128) */
#define NEGF  -1e30f

// ---------------- scratch (device globals) ---------------------------------
__device__ float g_q   [N_TOK*HQ*D];
__device__ float g_k   [N_TOK*D];
__device__ float g_v   [N_TOK*D];
__device__ float g_ck  [NC*D];
__device__ float g_ckT [D*NC];
__device__ float g_cv  [NC*D];
__device__ float g_blks[N_TOK*NC];
__device__ int   g_topk[N_TOK*TOPK];
__device__ float g_cmp [N_TOK*HQ*D];
__device__ float g_sp  [N_TOK*HQ*D];
__device__ float g_sw  [N_TOK*HQ*D];
__device__ float g_gate[N_TOK*HQ*3];
__device__ float g_att [N_TOK*HID];
__device__ float g_part [8 * N_TOK * 128];
__device__ float g_partG[8 * N_TOK * 48];

// ---------------- tf32 helpers ----------------------------------------------
__device__ __forceinline__ uint32_t f2tf32(float f) {
    uint32_t u;
    asm("cvt.rna.tf32.f32 %0, %1;" : "=r"(u) : "f"(f));
    return u;
}
__device__ __forceinline__ void mma_tf32(float* c, const uint32_t* a,
                                         uint32_t b0, uint32_t b1) {
    asm volatile(
        "mma.sync.aligned.m16n8k8.row.col.f32.tf32.tf32.f32 "
        "{%0,%1,%2,%3}, {%4,%5,%6,%7}, {%8,%9}, {%0,%1,%2,%3};"
        : "+f"(c[0]), "+f"(c[1]), "+f"(c[2]), "+f"(c[3])
        : "r"(a[0]), "r"(a[1]), "r"(a[2]), "r"(a[3]), "r"(b0), "r"(b1));
}
__device__ __forceinline__ void mma_bf16(float* c, const uint32_t* a,
                                         uint32_t b0, uint32_t b1) {
    asm volatile(
        "mma.sync.aligned.m16n8k16.row.col.f32.bf16.bf16.f32 "
        "{%0,%1,%2,%3}, {%4,%5,%6,%7}, {%8,%9}, {%0,%1,%2,%3};"
        : "+f"(c[0]), "+f"(c[1]), "+f"(c[2]), "+f"(c[3])
        : "r"(a[0]), "r"(a[1]), "r"(a[2]), "r"(a[3]), "r"(b0), "r"(b1));
}
__device__ __forceinline__ void split_bf16_pair(float f0, float f1,
                                                uint32_t& hw, uint32_t& lw) {
    __nv_bfloat162 h2 = __floats2bfloat162_rn(f0, f1);
    float h0 = __bfloat162float(__low2bfloat16(h2));
    float h1 = __bfloat162float(__high2bfloat16(h2));
    __nv_bfloat162 l2 = __floats2bfloat162_rn(f0 - h0, f1 - h1);
    hw = *reinterpret_cast<uint32_t*>(&h2);
    lw = *reinterpret_cast<uint32_t*>(&l2);
}

// ================= 3xBF16 GEMM (fp32-grade): C = A @ B ======================
// Block tile 128x128x16 (one k16 chunk per stage), 8 warps (2m x 4n),
// warp tile 64x32 via m16n8k16 bf16. smem: uint2 pairs {w, w+4}, j^(row&3).
__global__ void __launch_bounds__(256, 2)
gemm_bf3_kernel(const float* __restrict__ A, const float* __restrict__ B,
                float* __restrict__ C, float* __restrict__ Cpart, int K, int M)
{
    extern __shared__ uint2 smb[];
    uint2* AsH = smb;            // [2][128][4]
    uint2* AsL = smb + 1024;
    uint2* BsH = smb + 2048;
    uint2* BsL = smb + 3072;     // total 4096 uint2 = 32 KB

    const int tid = threadIdx.x;
    const int wid = tid >> 5, lane = tid & 31;
    const int row0 = blockIdx.y * 128, col0 = blockIdx.x * 128;
    const int wr = (wid & 1) * 64, wc = (wid >> 1) * 32;
    const int g = lane >> 2, tg = lane & 3;
    const int S = gridDim.z, Kc = K / S, kbeg = blockIdx.z * Kc;

    const int arow = tid >> 1, akb = (tid & 1) * 8;
    const int bkrow = tid >> 4, bcol = (tid & 15) * 8;
    const bool bval0 = (col0 + bcol + 4) <= M;
    const bool bval1 = (col0 + bcol + 8) <= M;

    const float* Ag = A + (size_t)(row0 + arow) * K + akb;
    const float* Bg = B + (size_t)bkrow * M + col0 + bcol;

    float acc[4][4][4];
#pragma unroll
    for (int mt = 0; mt < 4; mt++)
#pragma unroll
        for (int ni = 0; ni < 4; ni++)
#pragma unroll
            for (int r = 0; r < 4; r++) acc[mt][ni][r] = 0.f;

    float av[8], bb[8];

    auto loadG = [&](int k0) {
        float4 t0 = *(const float4*)(Ag + k0);
        float4 t1 = *(const float4*)(Ag + k0 + 4);
        av[0]=t0.x; av[1]=t0.y; av[2]=t0.z; av[3]=t0.w;
        av[4]=t1.x; av[5]=t1.y; av[6]=t1.z; av[7]=t1.w;
        const float* bp = Bg + (size_t)k0 * M;
        float4 u0 = bval0 ? *(const float4*)bp       : make_float4(0,0,0,0);
        float4 u1 = bval1 ? *(const float4*)(bp + 4) : make_float4(0,0,0,0);
        bb[0]=u0.x; bb[1]=u0.y; bb[2]=u0.z; bb[3]=u0.w;
        bb[4]=u1.x; bb[5]=u1.y; bb[6]=u1.z; bb[7]=u1.w;
    };

    auto storeS = [&](int st) {
        const int sbase = st << 9;   // 512 uint2 per stage
        // A: thread owns 4 complete k-pair words
#pragma unroll
        for (int u = 0; u < 4; u++) {
            uint32_t hw, lw;
            split_bf16_pair(av[2*u], av[2*u+1], hw, lw);
            int w = (akb >> 1) + u;                 // 0..7
            int j = (w & 3) ^ (arow & 3);
            int c = w >> 2;
            ((uint32_t*)&AsH[sbase + (arow << 2) + j])[c] = hw;
            ((uint32_t*)&AsL[sbase + (arow << 2) + j])[c] = lw;
        }
        // B: thread owns ONE bf16 (k=bkrow) of each word, for 8 cols
        {
            int w = bkrow >> 1;                     // 0..7
            int half = bkrow & 1;
            int c = w >> 2;
            int jb = w & 3;
#pragma unroll
            for (int u = 0; u < 8; u++) {
                int col = bcol + u;
                int j = jb ^ (col & 3);
                __nv_bfloat16 h = __float2bfloat16(bb[u]);
                __nv_bfloat16 l = __float2bfloat16(bb[u] - __bfloat162float(h));
                ((__nv_bfloat16*)&BsH[sbase + (col << 2) + j])[c*2 + half] = h;
                ((__nv_bfloat16*)&BsL[sbase + (col << 2) + j])[c*2 + half] = l;
            }
        }
    };

    auto compute = [&](int st) {
        const int sbase = st << 9;
        uint32_t afH[4][4];
        uint2 bH[4], bL[4];
#pragma unroll
        for (int mt = 0; mt < 4; mt++) {
            int r = wr + mt * 16 + g;
            int j = tg ^ (r & 3);
            uint2 p0 = AsH[sbase + (r << 2) + j];
            uint2 p1 = AsH[sbase + ((r + 8) << 2) + j];
            afH[mt][0] = p0.x; afH[mt][1] = p1.x;
            afH[mt][2] = p0.y; afH[mt][3] = p1.y;
        }
#pragma unroll
        for (int ni = 0; ni < 4; ni++) {
            int cc = wc + ni * 8 + g;
            int j = tg ^ (cc & 3);
            bH[ni] = BsH[sbase + (cc << 2) + j];
            bL[ni] = BsL[sbase + (cc << 2) + j];
        }
        // term 1: hi*hi
#pragma unroll
        for (int ni = 0; ni < 4; ni++)
#pragma unroll
            for (int mt = 0; mt < 4; mt++)
                mma_bf16(acc[mt][ni], afH[mt], bH[ni].x, bH[ni].y);
        // term 2: hi * loB
#pragma unroll
        for (int ni = 0; ni < 4; ni++)
#pragma unroll
            for (int mt = 0; mt < 4; mt++)
                mma_bf16(acc[mt][ni], afH[mt], bL[ni].x, bL[ni].y);
        // term 3: loA * hi
#pragma unroll
        for (int mt = 0; mt < 4; mt++) {
            int r = wr + mt * 16 + g;
            int j = tg ^ (r & 3);
            uint2 p0 = AsL[sbase + (r << 2) + j];
            uint2 p1 = AsL[sbase + ((r + 8) << 2) + j];
            uint32_t afL[4] = {p0.x, p1.x, p0.y, p1.y};
#pragma unroll
            for (int ni = 0; ni < 4; ni++)
                mma_bf16(acc[mt][ni], afL, bH[ni].x, bH[ni].y);
        }
    };

    loadG(kbeg);
    storeS(0);
    __syncthreads();

    const int nIter = Kc >> 4;
    for (int it = 0; it < nIter; it++) {
        int st = it & 1;
        bool hasNext = (it + 1 < nIter);
        if (hasNext) loadG(kbeg + (it + 1) * 16);
        compute(st);
        if (hasNext) storeS(st ^ 1);
        __syncthreads();
    }

    float* Cout = (S == 1) ? C : (Cpart + (size_t)blockIdx.z * N_TOK * M);
#pragma unroll
    for (int mt = 0; mt < 4; mt++) {
#pragma unroll
        for (int ni = 0; ni < 4; ni++) {
            int r = row0 + wr + mt * 16 + g;
            int c = col0 + wc + ni * 8 + tg * 2;
            if (c + 2 <= M) {
                *(float2*)&Cout[(size_t)r * M + c] =
                    make_float2(acc[mt][ni][0], acc[mt][ni][1]);
                *(float2*)&Cout[(size_t)(r + 8) * M + c] =
                    make_float2(acc[mt][ni][2], acc[mt][ni][3]);
            }
        }
    }
}

// ---------------- 1-term tf32 GEMM (continuous paths) ------------------------
template<int TERMS>
__global__ void __launch_bounds__(256, 2)
gemm_kernel(const float* __restrict__ A, const float* __restrict__ B,
            float* __restrict__ C, float* __restrict__ Cpart, int K, int M)
{
    extern __shared__ uint2 sm[];
    uint2* AsH = sm;
    uint2* BsH = sm + 2048;

    const int tid = threadIdx.x;
    const int wid = tid >> 5, lane = tid & 31;
    const int row0 = blockIdx.y * 128, col0 = blockIdx.x * 128;
    const int wr = (wid & 1) * 64, wc = (wid >> 1) * 32;
    const int g = lane >> 2, tg = lane & 3;
    const int S = gridDim.z, Kc = K / S, kbeg = blockIdx.z * Kc;

    const int arow = tid >> 1, akb = (tid & 1) * 8;
    const int bkrow = tid >> 4, bcol = (tid & 15) * 8;
    const bool bval0 = (col0 + bcol + 4) <= M;
    const bool bval1 = (col0 + bcol + 8) <= M;

    const float* Ag = A + (size_t)(row0 + arow) * K + akb;
    const float* Bg = B + (size_t)bkrow * M + col0 + bcol;

    float acc[4][4][4];
#pragma unroll
    for (int mt = 0; mt < 4; mt++)
#pragma unroll
        for (int ni = 0; ni < 4; ni++)
#pragma unroll
            for (int r = 0; r < 4; r++) acc[mt][ni][r] = 0.f;

    float av[8], bb[8];

    auto loadG = [&](int k0) {
        float4 t0 = *(const float4*)(Ag + k0);
        float4 t1 = *(const float4*)(Ag + k0 + 4);
        av[0]=t0.x; av[1]=t0.y; av[2]=t0.z; av[3]=t0.w;
        av[4]=t1.x; av[5]=t1.y; av[6]=t1.z; av[7]=t1.w;
        const float* bp = Bg + (size_t)k0 * M;
        float4 u0 = bval0 ? *(const float4*)bp       : make_float4(0,0,0,0);
        float4 u1 = bval1 ? *(const float4*)(bp + 4) : make_float4(0,0,0,0);
        bb[0]=u0.x; bb[1]=u0.y; bb[2]=u0.z; bb[3]=u0.w;
        bb[4]=u1.x; bb[5]=u1.y; bb[6]=u1.z; bb[7]=u1.w;
    };

    auto storeS = [&](int st) {
        const int sbase = st << 10;
#pragma unroll
        for (int u = 0; u < 8; u++) {
            int k = akb + u;
            int p = ((k >> 3) << 2) | (k & 3);
            int c = (k >> 2) & 1;
            int ph = p ^ ((arow & 3) << 1);
            ((uint32_t*)&AsH[sbase + (arow << 3) + ph])[c] = f2tf32(av[u]);
        }
        {
            int k = bkrow;
            int p = ((k >> 3) << 2) | (k & 3);
            int c = (k >> 2) & 1;
#pragma unroll
            for (int u = 0; u < 8; u++) {
                int col = bcol + u;
                int ph = p ^ ((col & 3) << 1);
                ((uint32_t*)&BsH[sbase + (col << 3) + ph])[c] = f2tf32(bb[u]);
            }
        }
    };

    auto compute = [&](int st) {
        const int sbase = st << 10;
#pragma unroll
        for (int hb = 0; hb < 2; hb++) {
            const int ph = (hb * 4 + tg) ^ ((g & 3) << 1);
            uint32_t afH[4][4];
            uint2 bH[4];
#pragma unroll
            for (int mt = 0; mt < 4; mt++) {
                int r = wr + mt * 16 + g;
                uint2 p0 = AsH[sbase + (r << 3) + ph];
                uint2 p1 = AsH[sbase + ((r + 8) << 3) + ph];
                afH[mt][0] = p0.x; afH[mt][1] = p1.x;
                afH[mt][2] = p0.y; afH[mt][3] = p1.y;
            }
#pragma unroll
            for (int ni = 0; ni < 4; ni++) {
                int cc = wc + ni * 8 + g;
                bH[ni] = BsH[sbase + (cc << 3) + ph];
            }
#pragma unroll
            for (int ni = 0; ni < 4; ni++)
#pragma unroll
                for (int mt = 0; mt < 4; mt++)
                    mma_tf32(acc[mt][ni], afH[mt], bH[ni].x, bH[ni].y);
        }
    };

    loadG(kbeg);
    storeS(0);
    __syncthreads();

    const int nIter = Kc >> 4;
    for (int it = 0; it < nIter; it++) {
        int st = it & 1;
        bool hasNext = (it + 1 < nIter);
        if (hasNext) loadG(kbeg + (it + 1) * 16);
        compute(st);
        if (hasNext) storeS(st ^ 1);
        __syncthreads();
    }

    float* Cout = (S == 1) ? C : (Cpart + (size_t)blockIdx.z * N_TOK * M);
#pragma unroll
    for (int mt = 0; mt < 4; mt++) {
#pragma unroll
        for (int ni = 0; ni < 4; ni++) {
            int r = row0 + wr + mt * 16 + g;
            int c = col0 + wc + ni * 8 + tg * 2;
            if (c + 2 <= M) {
                *(float2*)&Cout[(size_t)r * M + c] =
                    make_float2(acc[mt][ni][0], acc[mt][ni][1]);
                *(float2*)&Cout[(size_t)(r + 8) * M + c] =
                    make_float2(acc[mt][ni][2], acc[mt][ni][3]);
            }
        }
    }
}

__global__ void splitk_reduce_kernel(const float* __restrict__ part,
                                     float* __restrict__ out, int len, int S)
{
    int i = blockIdx.x * 256 + threadIdx.x;
    if (i >= len) return;
    float s = 0.f;
    for (int z = 0; z < S; z++) s += part[(size_t)z * len + i];
    out[i] = s;
}

// ---------------- compressed k/v (pre-RoPE) --------------------------------
__global__ void compress_kernel(const float* __restrict__ k,
                                const float* __restrict__ v,
                                const float* __restrict__ pe,
                                float* __restrict__ ck,
                                float* __restrict__ cv)
{
    int m = blockIdx.x;
    int d = threadIdx.x;
    float sk = 0.f, sv = 0.f;
#pragma unroll 8
    for (int i = 0; i < KS; i++) {
        sk += k[(m*KS + i)*D + d] + pe[i*D + d];
        sv += v[(m*KS + i)*D + d];
    }
    ck[m*D + d] = sk * (1.f/KS);
    cv[m*D + d] = sv * (1.f/KS);
}

// ---------------- RoPE (in place) ------------------------------------------
__global__ void rope_kernel(float* __restrict__ x, int heads, int pos_stride)
{
    int row = blockIdx.x;
    int d   = threadIdx.x;
    float inv = powf(10000.f, -(float)d / 64.f);
    float ang = (float)(row * pos_stride) * inv;
    float c = cosf(ang), s = sinf(ang);
    for (int h = 0; h < heads; h++) {
        float* p = x + ((size_t)row*heads + h) * D;
        float x1 = p[d], x2 = p[d + 64];
        p[d]      = x1 * c - x2 * s;
        p[d + 64] = x2 * c + x1 * s;
    }
}

// ---------------- ck transpose ----------------------------------------------
__global__ void transpose_ck_kernel(const float* __restrict__ ck,
                                    float* __restrict__ ckT)
{
    int i = blockIdx.x * 256 + threadIdx.x;
    int m = i >> 7, d = i & 127;
    ckT[d*NC + m] = ck[m*D + d];
}

// ---------------- cmp softmax / mask / block-score --------------------------
__global__ void cmp_softmax_kernel(float* __restrict__ sc,
                                   float* __restrict__ blks)
{
    int n = blockIdx.x;
    __shared__ float pcs[HQ][NC];
    int tid = threadIdx.x;

    float* base = sc + (size_t)n * HQ * NC;
    {
        int h = tid >> 4, m4 = (tid & 15) * 4;
        float4 vv = *(float4*)&base[h*NC + m4];
        float s[4] = {vv.x, vv.y, vv.z, vv.w};
#pragma unroll
        for (int u = 0; u < 4; u++) {
            int m = m4 + u;
            bool valid = (n >= m*STRIDE + KS - 1);
            s[u] = valid ? s[u] * SCALE : NEGF;
        }
        pcs[h][m4+0] = s[0]; pcs[h][m4+1] = s[1];
        pcs[h][m4+2] = s[2]; pcs[h][m4+3] = s[3];
    }
    __syncthreads();

    {
        int w = tid >> 5, l = tid & 31;
        for (int h = w; h < HQ; h += 8) {
            float a = pcs[h][l], b = pcs[h][l + 32];
            float mx = fmaxf(a, b);
#pragma unroll
            for (int o = 16; o > 0; o >>= 1) mx = fmaxf(mx, __shfl_xor_sync(0xffffffff, mx, o));
            float ea = __expf(a - mx), eb = __expf(b - mx);
            float s = ea + eb;
#pragma unroll
            for (int o = 16; o > 0; o >>= 1) s += __shfl_xor_sync(0xffffffff, s, o);
            float inv = 1.f / s;
            bool va = (n >= l*STRIDE + KS - 1);
            bool vb = (n >= (l+32)*STRIDE + KS - 1);
            pcs[h][l]      = va ? ea * inv : 0.f;
            pcs[h][l + 32] = vb ? eb * inv : 0.f;
        }
    }
    __syncthreads();

    for (int m = tid; m < NC; m += 256) {
        float s = 0.f;
        for (int h = 0; h < HQ; h++) s += pcs[h][m];
        blks[(size_t)n*NC + m] = s;
    }
    {
        int h = tid >> 4, m4 = (tid & 15) * 4;
        *(float4*)&base[h*NC + m4] =
            make_float4(pcs[h][m4], pcs[h][m4+1], pcs[h][m4+2], pcs[h][m4+3]);
    }
}

// ---------------- top-k selection (warp per token) --------------------------
__global__ void topk_kernel(const float* __restrict__ blks, int* __restrict__ topk)
{
    int gidx = blockIdx.x * blockDim.x + threadIdx.x;
    int n = gidx >> 5;
    int lane = threadIdx.x & 31;
    if (n >= N_TOK) return;
    int tb = n / BSZ;
    int m0 = lane, m1 = lane + 32;
    float s0 = blks[(size_t)n*NC + m0];
    float s1 = blks[(size_t)n*NC + m1];
    if (m0 > tb) s0 = NEGF;
    if (m0 < 1 || (m0 <= tb && m0 > tb - 2)) s0 = 1e30f;
    if (m1 > tb) s1 = NEGF;
    if (m1 < 1 || (m1 <= tb && m1 > tb - 2)) s1 = 1e30f;
#pragma unroll
    for (int j = 0; j < TOPK; j++) {
        float bv; int bi;
        if (s0 >= s1) { bv = s0; bi = m0; } else { bv = s1; bi = m1; }
#pragma unroll
        for (int o = 16; o > 0; o >>= 1) {
            float ov = __shfl_down_sync(0xffffffff, bv, o);
            int   oi = __shfl_down_sync(0xffffffff, bi, o);
            if (ov > bv || (ov == bv && oi < bi)) { bv = ov; bi = oi; }
        }
        bi = __shfl_sync(0xffffffff, bi, 0);
        if (lane == 0) topk[n*TOPK + j] = bi;
        if (bi == m0) s0 = -FLT_MAX;
        if (bi == m1) s1 = -FLT_MAX;
    }
}

// ============ SIMT helpers (sel attention) ==================================
#define KVP 132

__device__ __forceinline__ void attn_softmax_update(
    float* sc, float* mS, float* lS, float* fS, int tid)
{
    int h = tid >> 4, t = tid & 15;
    float4 sv = *(float4*)&sc[h*64 + t*4];
    float pm = fmaxf(fmaxf(sv.x, sv.y), fmaxf(sv.z, sv.w));
#pragma unroll
    for (int o = 1; o < 16; o <<= 1) pm = fmaxf(pm, __shfl_xor_sync(0xffffffff, pm, o));
    float mOld = mS[h];
    float mNew = fmaxf(mOld, pm);
    float4 p;
    p.x = __expf(sv.x - mNew); p.y = __expf(sv.y - mNew);
    p.z = __expf(sv.z - mNew); p.w = __expf(sv.w - mNew);
    *(float4*)&sc[h*64 + t*4] = p;
    float ps = p.x + p.y + p.z + p.w;
#pragma unroll
    for (int o = 1; o < 16; o <<= 1) ps += __shfl_xor_sync(0xffffffff, ps, o);
    if (t == 0) {
        float f = __expf(mOld - mNew);
        fS[h] = f;
        lS[h] = lS[h] * f + ps;
        mS[h] = mNew;
    }
}

__device__ __forceinline__ void attn_pv(
    const float* kv, const float* sc, float* acc, float f, int h, int d0, int tl)
{
#pragma unroll
    for (int i = 0; i < 8; i++) acc[i] *= f;
    for (int j = 0; j < tl; j++) {
        float p = sc[h*64 + j];
        float4 v0 = *(const float4*)&kv[j*KVP + d0];
        float4 v1 = *(const float4*)&kv[j*KVP + d0 + 4];
        acc[0] += p*v0.x; acc[1] += p*v0.y; acc[2] += p*v0.z; acc[3] += p*v0.w;
        acc[4] += p*v1.x; acc[5] += p*v1.y; acc[6] += p*v1.z; acc[7] += p*v1.w;
    }
}

// ---------------- selected (top-k) attention (SIMT) -------------------------
__global__ void __launch_bounds__(256, 2)
sel_attn_kernel(const float* __restrict__ q, const float* __restrict__ k,
                const float* __restrict__ v, const int* __restrict__ topk,
                float* __restrict__ out)
{
    int n = blockIdx.x;
    int tid = threadIdx.x;
    __shared__ float qs[HQ*D];
    __shared__ float kv[64*KVP];
    __shared__ float sc[HQ*64];
    __shared__ int   posA[TOPK*BSZ];
    __shared__ float mS[HQ], lS[HQ], fS[HQ];

    for (int e = tid; e < HQ*D/4; e += 256)
        ((float4*)qs)[e] = ((const float4*)(q + (size_t)n*HQ*D))[e];
    if (tid < HQ) { mS[tid] = -FLT_MAX; lS[tid] = 0.f; }
    posA[tid] = topk[n*TOPK + (tid >> 5)] * BSZ + (tid & 31);

    int h  = tid >> 4;
    int d0 = (tid & 15) * 8;
    float acc[8];
#pragma unroll
    for (int i = 0; i < 8; i++) acc[i] = 0.f;
    __syncthreads();

    for (int t0 = 0; t0 < TOPK*BSZ; t0 += 64) {
        for (int e = tid; e < 64*32; e += 256) {
            int row = e >> 5, c = e & 31;
            *(float4*)&kv[row*KVP + c*4] = ((const float4*)(k + (size_t)posA[t0 + row]*D))[c];
        }
        __syncthreads();
        {
            int jj = tid & 63;
            int hb = (tid >> 6) * 4;
            bool valid = posA[t0 + jj] <= n;
            float s0=0.f,s1=0.f,s2=0.f,s3=0.f;
            if (valid) {
                const float4* kr = (const float4*)(kv + jj*KVP);
                const float4* q0 = (const float4*)(qs + (hb+0)*D);
                const float4* q1 = (const float4*)(qs + (hb+1)*D);
                const float4* q2 = (const float4*)(qs + (hb+2)*D);
                const float4* q3 = (const float4*)(qs + (hb+3)*D);
#pragma unroll
                for (int c = 0; c < 32; c++) {
                    float4 kk = kr[c];
                    float4 a;
                    a = q0[c]; s0 += a.x*kk.x + a.y*kk.y + a.z*kk.z + a.w*kk.w;
                    a = q1[c]; s1 += a.x*kk.x + a.y*kk.y + a.z*kk.z + a.w*kk.w;
                    a = q2[c]; s2 += a.x*kk.x + a.y*kk.y + a.z*kk.z + a.w*kk.w;
                    a = q3[c]; s3 += a.x*kk.x + a.y*kk.y + a.z*kk.z + a.w*kk.w;
                }
                sc[(hb+0)*64+jj]=s0*SCALE; sc[(hb+1)*64+jj]=s1*SCALE;
                sc[(hb+2)*64+jj]=s2*SCALE; sc[(hb+3)*64+jj]=s3*SCALE;
            } else {
                sc[(hb+0)*64+jj]=NEGF; sc[(hb+1)*64+jj]=NEGF;
                sc[(hb+2)*64+jj]=NEGF; sc[(hb+3)*64+jj]=NEGF;
            }
        }
        __syncthreads();
        attn_softmax_update(sc, mS, lS, fS, tid);
        __syncthreads();
        for (int e = tid; e < 64*32; e += 256) {
            int row = e >> 5, c = e & 31;
            *(float4*)&kv[row*KVP + c*4] = ((const float4*)(v + (size_t)posA[t0 + row]*D))[c];
        }
        __syncthreads();
        attn_pv(kv, sc, acc, fS[h], h, d0, 64);
        __syncthreads();
    }
    float inv = 1.f / lS[h];
    float4 o0 = make_float4(acc[0]*inv, acc[1]*inv, acc[2]*inv, acc[3]*inv);
    float4 o1 = make_float4(acc[4]*inv, acc[5]*inv, acc[6]*inv, acc[7]*inv);
    *(float4*)&out[((size_t)n*HQ + h)*D + d0]     = o0;
    *(float4*)&out[((size_t)n*HQ + h)*D + d0 + 4] = o1;
}

// ================= window attention via 1-term tf32 tensor cores ============
__global__ void __launch_bounds__(256, 2)
win_mma_kernel(const float* __restrict__ q, const float* __restrict__ k,
               const float* __restrict__ v, float* __restrict__ out)
{
    extern __shared__ uint2 smw[];
    uint2* Qh = smw;
    uint2* Bh = smw + 4096;
    uint2* Ph = smw + 8192;
    float* stats = (float*)(smw + 10240);
    float* mS   = stats;
    float* lS   = stats + 64;
    float* fS   = stats + 128;
    float* pmax = stats + 192;
    float* psum = stats + 320;

    const int tid = threadIdx.x;
    const int wid = tid >> 5, lane = tid & 31;
    const int g = lane >> 2, tg = lane & 3;
    const int qtile0 = (gridDim.x - 1 - blockIdx.x) * 64;
    const int h = blockIdx.y;

    for (int e = tid; e < 64*32; e += 256) {
        int row = e >> 5, c4 = e & 31;
        float4 vq = *(const float4*)&q[(((size_t)(qtile0 + row))*HQ + h)*D + c4*4];
        float qv[4] = {vq.x, vq.y, vq.z, vq.w};
#pragma unroll
        for (int u = 0; u < 4; u++) {
            int d = c4*4 + u;
            int ch = d >> 4, kk = d & 15;
            int p = ((kk >> 3) << 2) | (kk & 3);
            int cc = (kk >> 2) & 1;
            int ph = p ^ ((row & 3) << 1);
            ((uint32_t*)&Qh[ch*512 + (row << 3) + ph])[cc] = f2tf32(qv[u]);
        }
    }
    if (tid < 64) { mS[tid] = -3.0e38f; lS[tid] = 0.f; }

    const int mtS = wid & 3, cg = wid >> 2;
    const int mtP = wid & 3, dh = wid >> 2;

    float oacc[8][4];
#pragma unroll
    for (int ni = 0; ni < 8; ni++)
#pragma unroll
        for (int r = 0; r < 4; r++) oacc[ni][r] = 0.f;

    int klo = qtile0 - WIN; if (klo < 0) klo = 0;
    __syncthreads();

    for (int kt = klo; kt < qtile0 + 64; kt += 64) {
        for (int e = tid; e < 64*32; e += 256) {
            int key = e >> 5, c4 = e & 31;
            float4 vk = *(const float4*)&k[((size_t)(kt + key))*D + c4*4];
            float kv4[4] = {vk.x, vk.y, vk.z, vk.w};
#pragma unroll
            for (int u = 0; u < 4; u++) {
                int d = c4*4 + u;
                int ch = d >> 4, kk = d & 15;
                int p = ((kk >> 3) << 2) | (kk & 3);
                int cc = (kk >> 2) & 1;
                int ph = p ^ ((key & 3) << 1);
                ((uint32_t*)&Bh[ch*512 + (key << 3) + ph])[cc] = f2tf32(kv4[u]);
            }
        }
        __syncthreads();

        float sacc[4][4];
#pragma unroll
        for (int ni = 0; ni < 4; ni++)
#pragma unroll
            for (int r = 0; r < 4; r++) sacc[ni][r] = 0.f;

#pragma unroll
        for (int ch = 0; ch < 8; ch++) {
#pragma unroll
            for (int hb = 0; hb < 2; hb++) {
                const int ph = (hb*4 + tg) ^ ((g & 3) << 1);
                int r = mtS*16 + g;
                uint2 a0 = Qh[ch*512 + (r << 3) + ph];
                uint2 a1 = Qh[ch*512 + ((r + 8) << 3) + ph];
                uint32_t afH[4] = {a0.x, a1.x, a0.y, a1.y};
#pragma unroll
                for (int ni = 0; ni < 4; ni++) {
                    int col = cg*32 + ni*8 + g;
                    uint2 bH = Bh[ch*512 + (col << 3) + ph];
                    mma_tf32(sacc[ni], afH, bH.x, bH.y);
                }
            }
        }

        const int rA = qtile0 + mtS*16 + g;
        const int rB = rA + 8;
        float m1 = -3.0e38f, m2 = -3.0e38f;
#pragma unroll
        for (int ni = 0; ni < 4; ni++) {
            int key0 = kt + cg*32 + ni*8 + tg*2;
#pragma unroll
            for (int i = 0; i < 4; i++) {
                int key = key0 + (i & 1);
                int qp = (i < 2) ? rA : rB;
                float s = sacc[ni][i] * SCALE;
                bool valid = (key <= qp) && (key >= qp - WIN);
                s = valid ? s : NEGF;
                sacc[ni][i] = s;
                if (i < 2) m1 = fmaxf(m1, s); else m2 = fmaxf(m2, s);
            }
        }
#pragma unroll
        for (int o = 1; o < 4; o <<= 1) {
            m1 = fmaxf(m1, __shfl_xor_sync(0xffffffff, m1, o));
            m2 = fmaxf(m2, __shfl_xor_sync(0xffffffff, m2, o));
        }
        int rlA = mtS*16 + g, rlB = rlA + 8;
        if (tg == 0) { pmax[rlA*2 + cg] = m1; pmax[rlB*2 + cg] = m2; }
        __syncthreads();

        float mnA = fmaxf(mS[rlA], fmaxf(pmax[rlA*2], pmax[rlA*2+1]));
        float mnB = fmaxf(mS[rlB], fmaxf(pmax[rlB*2], pmax[rlB*2+1]));
        float sumA = 0.f, sumB = 0.f;
#pragma unroll
        for (int ni = 0; ni < 4; ni++) {
#pragma unroll
            for (int i = 0; i < 4; i++) {
                float s = sacc[ni][i];
                float mn = (i < 2) ? mnA : mnB;
                float p = (s <= -1e29f) ? 0.f : __expf(s - mn);
                if (i < 2) sumA += p; else sumB += p;
                int cloc = cg*32 + ni*8 + tg*2 + (i & 1);
                int ch = cloc >> 4, kk = cloc & 15;
                int pp = ((kk >> 3) << 2) | (kk & 3);
                int cc = (kk >> 2) & 1;
                int rl = (i < 2) ? rlA : rlB;
                int ph = pp ^ ((rl & 3) << 1);
                ((uint32_t*)&Ph[ch*512 + (rl << 3) + ph])[cc] = f2tf32(p);
            }
        }
#pragma unroll
        for (int o = 1; o < 4; o <<= 1) {
            sumA += __shfl_xor_sync(0xffffffff, sumA, o);
            sumB += __shfl_xor_sync(0xffffffff, sumB, o);
        }
        if (tg == 0) { psum[rlA*2 + cg] = sumA; psum[rlB*2 + cg] = sumB; }

        for (int e = tid; e < 64*32; e += 256) {
            int key = e >> 5, c4 = e & 31;
            float4 vv = *(const float4*)&v[((size_t)(kt + key))*D + c4*4];
            float v4[4] = {vv.x, vv.y, vv.z, vv.w};
            int chv = key >> 4, kkv = key & 15;
            int pv = ((kkv >> 3) << 2) | (kkv & 3);
            int ccv = (kkv >> 2) & 1;
#pragma unroll
            for (int u = 0; u < 4; u++) {
                int d = c4*4 + u;
                int phv = pv ^ ((d & 3) << 1);
                ((uint32_t*)&Bh[chv*1024 + (d << 3) + phv])[ccv] = f2tf32(v4[u]);
            }
        }
        __syncthreads();

        if (tid < 64) {
            float mo = mS[tid];
            float mn = fmaxf(mo, fmaxf(pmax[tid*2], pmax[tid*2+1]));
            float f = __expf(mo - mn);
            lS[tid] = lS[tid] * f + psum[tid*2] + psum[tid*2+1];
            mS[tid] = mn;
            fS[tid] = f;
        }
        __syncthreads();

        {
            int rl1 = mtP*16 + g, rl2 = rl1 + 8;
            float f1 = fS[rl1], f2 = fS[rl2];
#pragma unroll
            for (int ni = 0; ni < 8; ni++) {
                oacc[ni][0] *= f1; oacc[ni][1] *= f1;
                oacc[ni][2] *= f2; oacc[ni][3] *= f2;
            }
#pragma unroll
            for (int ch = 0; ch < 4; ch++) {
#pragma unroll
                for (int hb = 0; hb < 2; hb++) {
                    const int ph = (hb*4 + tg) ^ ((g & 3) << 1);
                    int r = mtP*16 + g;
                    uint2 a0 = Ph[ch*512 + (r << 3) + ph];
                    uint2 a1 = Ph[ch*512 + ((r + 8) << 3) + ph];
                    uint32_t afH[4] = {a0.x, a1.x, a0.y, a1.y};
#pragma unroll
                    for (int ni = 0; ni < 8; ni++) {
                        int col = dh*64 + ni*8 + g;
                        uint2 bH = Bh[ch*1024 + (col << 3) + ph];
                        mma_tf32(oacc[ni], afH, bH.x, bH.y);
                    }
                }
            }
        }
        __syncthreads();
    }

    {
        int rl1 = mtP*16 + g, rl2 = rl1 + 8;
        float i1 = 1.f / lS[rl1], i2 = 1.f / lS[rl2];
        size_t b1 = ((size_t)(qtile0 + rl1)*HQ + h)*D;
        size_t b2 = ((size_t)(qtile0 + rl2)*HQ + h)*D;
#pragma unroll
        for (int ni = 0; ni < 8; ni++) {
            int d = dh*64 + ni*8 + tg*2;
            *(float2*)&out[b1 + d] = make_float2(oacc[ni][0]*i1, oacc[ni][1]*i1);
            *(float2*)&out[b2 + d] = make_float2(oacc[ni][2]*i2, oacc[ni][3]*i2);
        }
    }
}

// ---------------- gate combine ---------------------------------------------
__global__ void combine_kernel(const float* __restrict__ gbuf,
                               const float* __restrict__ cmp,
                               const float* __restrict__ sp,
                               const float* __restrict__ sw,
                               float* __restrict__ att)
{
    size_t idx = (size_t)blockIdx.x * 256 + threadIdx.x;
    int n = (int)(idx >> 11);
    int hd = (int)(idx & 2047);
    int h = hd >> 7;
    const float* g = gbuf + (size_t)n*HQ*3 + h*3;
    float g0 = 1.f / (1.f + __expf(-g[0]));
    float g1 = 1.f / (1.f + __expf(-g[1]));
    float g2 = 1.f / (1.f + __expf(-g[2]));
    att[idx] = g0 * cmp[idx] + g1 * sp[idx] + g2 * sw[idx];
}

// ---------------- launcher with stream fork/join -----------------------------
extern "C" void kernel_launch(void* const* d_in, const int* in_sizes, int n_in,
                              void* d_out, int out_size)
{
    const float* x  = (const float*)d_in[0];
    const float* Wq = (const float*)d_in[2];
    const float* Wk = (const float*)d_in[3];
    const float* Wv = (const float*)d_in[4];
    const float* Wo = (const float*)d_in[5];
    const float* Wg = (const float*)d_in[6];
    const float* pe = (const float*)d_in[7];
    float* out = (float*)d_out;

    float *q, *k, *v, *ck, *ckT, *cv, *blks, *cmp, *sp, *sw, *gate, *att, *part, *partG;
    int* tk;
    cudaGetSymbolAddress((void**)&q,    g_q);
    cudaGetSymbolAddress((void**)&k,    g_k);
    cudaGetSymbolAddress((void**)&v,    g_v);
    cudaGetSymbolAddress((void**)&ck,   g_ck);
    cudaGetSymbolAddress((void**)&ckT,  g_ckT);
    cudaGetSymbolAddress((void**)&cv,   g_cv);
    cudaGetSymbolAddress((void**)&blks, g_blks);
    cudaGetSymbolAddress((void**)&tk,   g_topk);
    cudaGetSymbolAddress((void**)&cmp,  g_cmp);
    cudaGetSymbolAddress((void**)&sp,   g_sp);
    cudaGetSymbolAddress((void**)&sw,   g_sw);
    cudaGetSymbolAddress((void**)&gate, g_gate);
    cudaGetSymbolAddress((void**)&att,  g_att);
    cudaGetSymbolAddress((void**)&part, g_part);
    cudaGetSymbolAddress((void**)&partG,g_partG);

    const int SMEMB3 = 32768;   // bf16 3-term
    const int SMEM1  = 32768;   // tf32 1-term
    const int SMEMW  = 10240*8 + 448*4;
    cudaFuncSetAttribute(gemm_bf3_kernel, cudaFuncAttributeMaxDynamicSharedMemorySize, SMEMB3);
    cudaFuncSetAttribute(gemm_kernel<1>, cudaFuncAttributeMaxDynamicSharedMemorySize, SMEM1);
    cudaFuncSetAttribute(win_mma_kernel, cudaFuncAttributeMaxDynamicSharedMemorySize, SMEMW);

    static cudaStream_t sB = nullptr, sC = nullptr;
    static cudaEvent_t evRoot = nullptr, evQ = nullptr, evKV = nullptr,
                       evTK = nullptr, evCMP = nullptr, evSEL = nullptr;
    if (!sB) {
        cudaStreamCreateWithFlags(&sB, cudaStreamNonBlocking);
        cudaStreamCreateWithFlags(&sC, cudaStreamNonBlocking);
        cudaEventCreateWithFlags(&evRoot, cudaEventDisableTiming);
        cudaEventCreateWithFlags(&evQ,    cudaEventDisableTiming);
        cudaEventCreateWithFlags(&evKV,   cudaEventDisableTiming);
        cudaEventCreateWithFlags(&evTK,   cudaEventDisableTiming);
        cudaEventCreateWithFlags(&evCMP,  cudaEventDisableTiming);
        cudaEventCreateWithFlags(&evSEL,  cudaEventDisableTiming);
    }

    cudaEventRecord(evRoot, 0);
    cudaStreamWaitEvent(sB, evRoot, 0);
    cudaStreamWaitEvent(sC, evRoot, 0);

    // --- spine A (default): Wq (3xbf16) -> ropeQ ----------------------------
    gemm_bf3_kernel<<<dim3(16, 16, 1), 256, SMEMB3>>>(x, Wq, q, nullptr, HID, HQ*D);
    rope_kernel<<<N_TOK, 64>>>(q, HQ, 1);
    cudaEventRecord(evQ, 0);

    // --- spine B: k/v chain -> cmp scores -> topk ---------------------------
    gemm_bf3_kernel<<<dim3(1, 16, 8), 256, SMEMB3, sB>>>(x, Wk, k, part, HID, D);
    splitk_reduce_kernel<<<(N_TOK*D + 255)/256, 256, 0, sB>>>(part, k, N_TOK*D, 8);
    gemm_kernel<1><<<dim3(1, 16, 8), 256, SMEM1, sB>>>(x, Wv, v, part, HID, D);
    splitk_reduce_kernel<<<(N_TOK*D + 255)/256, 256, 0, sB>>>(part, v, N_TOK*D, 8);
    compress_kernel<<<NC, D, 0, sB>>>(k, v, pe, ck, cv);
    rope_kernel<<<N_TOK, 64, 0, sB>>>(k, 1, 1);
    rope_kernel<<<NC, 64, 0, sB>>>(ck, 1, STRIDE);
    transpose_ck_kernel<<<32, 256, 0, sB>>>(ck, ckT);
    cudaEventRecord(evKV, sB);

    cudaStreamWaitEvent(sB, evQ, 0);
    gemm_bf3_kernel<<<dim3(1, 256, 1), 256, SMEMB3, sB>>>(q, ckT, part, nullptr, D, NC);
    cmp_softmax_kernel<<<N_TOK, 256, 0, sB>>>(part, blks);
    topk_kernel<<<(N_TOK*32 + 255)/256, 256, 0, sB>>>(blks, tk);
    cudaEventRecord(evTK, sB);
    gemm_kernel<1><<<dim3(1, 256, 1), 256, SMEM1, sB>>>(part, cv, cmp, nullptr, NC, D);
    cudaEventRecord(evCMP, sB);

    // --- spine C: gate projection, then sel after topk ----------------------
    gemm_kernel<1><<<dim3(1, 16, 8), 256, SMEM1, sC>>>(x, Wg, gate, partG, HID, HQ*3);
    splitk_reduce_kernel<<<(N_TOK*HQ*3 + 255)/256, 256, 0, sC>>>(partG, gate, N_TOK*HQ*3, 8);
    cudaStreamWaitEvent(sC, evTK, 0);
    sel_attn_kernel<<<N_TOK, 256, 0, sC>>>(q, k, v, tk, sp);
    cudaEventRecord(evSEL, sC);

    // --- spine A continues: win after k/v ready -----------------------------
    cudaStreamWaitEvent(0, evKV, 0);
    win_mma_kernel<<<dim3(32, HQ), 256, SMEMW>>>(q, k, v, sw);

    // join
    cudaStreamWaitEvent(0, evSEL, 0);
    cudaStreamWaitEvent(0, evCMP, 0);
    combine_kernel<<<(N_TOK*HQ*D)/256, 256>>>(gate, cmp, sp, sw, att);
    gemm_kernel<1><<<dim3(16, 16, 1), 256, SMEM1>>>(att, Wo, out, nullptr, HID, HID);
}

// round 16
// speedup vs baseline: 1.2185x; 1.0199x over previous
#include <cuda_runtime.h>
#include <cuda_bf16.h>
#include <math.h>
#include <float.h>
#include <stdint.h>

#define N_TOK 2048
#define HID   2048
#define HQ    16
#define D     128
#define NC    64
#define KS    32
#define STRIDE 32
#define BSZ   32
#define TOPK  8
#define WIN   512
#define SCALE 0.08838834764831845f  /* 1/sqrt(128) */
#define NEGF  -1e30f

// ---------------- scratch (device globals) ---------------------------------
__device__ float g_q   [N_TOK*HQ*D];
__device__ float g_k   [N_TOK*D];
__device__ float g_v   [N_TOK*D];
__device__ float g_ck  [NC*D];
__device__ float g_ckT [D*NC];
__device__ float g_cv  [NC*D];
__device__ float g_blks[N_TOK*NC];
__device__ int   g_topk[N_TOK*TOPK];
__device__ float g_cmp [N_TOK*HQ*D];
__device__ float g_sp  [N_TOK*HQ*D];
__device__ float g_sw  [N_TOK*HQ*D];
__device__ float g_gate[N_TOK*HQ*3];
__device__ float g_att [N_TOK*HID];
__device__ float g_part [8 * N_TOK * 128];

// ---------------- tf32 / bf16 helpers ----------------------------------------
__device__ __forceinline__ uint32_t f2tf32(float f) {
    uint32_t u;
    asm("cvt.rna.tf32.f32 %0, %1;" : "=r"(u) : "f"(f));
    return u;
}
__device__ __forceinline__ void mma_tf32(float* c, const uint32_t* a,
                                         uint32_t b0, uint32_t b1) {
    asm volatile(
        "mma.sync.aligned.m16n8k8.row.col.f32.tf32.tf32.f32 "
        "{%0,%1,%2,%3}, {%4,%5,%6,%7}, {%8,%9}, {%0,%1,%2,%3};"
        : "+f"(c[0]), "+f"(c[1]), "+f"(c[2]), "+f"(c[3])
        : "r"(a[0]), "r"(a[1]), "r"(a[2]), "r"(a[3]), "r"(b0), "r"(b1));
}
__device__ __forceinline__ void mma_bf16(float* c, const uint32_t* a,
                                         uint32_t b0, uint32_t b1) {
    asm volatile(
        "mma.sync.aligned.m16n8k16.row.col.f32.bf16.bf16.f32 "
        "{%0,%1,%2,%3}, {%4,%5,%6,%7}, {%8,%9}, {%0,%1,%2,%3};"
        : "+f"(c[0]), "+f"(c[1]), "+f"(c[2]), "+f"(c[3])
        : "r"(a[0]), "r"(a[1]), "r"(a[2]), "r"(a[3]), "r"(b0), "r"(b1));
}
__device__ __forceinline__ void split_bf16_pair(float f0, float f1,
                                                uint32_t& hw, uint32_t& lw) {
    __nv_bfloat162 h2 = __floats2bfloat162_rn(f0, f1);
    float h0 = __bfloat162float(__low2bfloat16(h2));
    float h1 = __bfloat162float(__high2bfloat16(h2));
    __nv_bfloat162 l2 = __floats2bfloat162_rn(f0 - h0, f1 - h1);
    hw = *reinterpret_cast<uint32_t*>(&h2);
    lw = *reinterpret_cast<uint32_t*>(&l2);
}

// ================= 3xBF16 GEMM core (device) ================================
// One block computes C[row0:row0+128, colbase:colbase+128-of-Mloc] from
// A[2048,K=2048] @ B[K, Mloc]. Pairs {w,w+4} uint2, j^(row&3) swizzle.
struct BF3Args {
    const float* A; const float* B; float* C;
    int K; int Mloc; int colbase; int row0;
};

__device__ __forceinline__ void gemm_bf3_body(const BF3Args& a_, uint2* smb)
{
    uint2* AsH = smb;
    uint2* AsL = smb + 1024;
    uint2* BsH = smb + 2048;
    uint2* BsL = smb + 3072;

    const int tid = threadIdx.x;
    const int wid = tid >> 5, lane = tid & 31;
    const int wr = (wid & 1) * 64, wc = (wid >> 1) * 32;
    const int g = lane >> 2, tg = lane & 3;
    const int K = a_.K, Mloc = a_.Mloc, colbase = a_.colbase, row0 = a_.row0;

    const int arow = tid >> 1, akb = (tid & 1) * 8;
    const int bkrow = tid >> 4, bcol = (tid & 15) * 8;
    const bool bval0 = (colbase + bcol + 4) <= Mloc + colbase && (bcol + 4) <= ((Mloc < 128) ? Mloc : 128);
    // simpler: local col bound against tile width = min(128, Mloc - 0) when colbase==0 for narrow;
    // for wide (Mloc>=colbase+128) always valid.
    const bool v0 = (colbase + bcol + 4) <= (colbase + ((Mloc - colbase < 128) ? (Mloc - colbase) : 128)) && (colbase + bcol + 4) <= Mloc;
    const bool v1 = (colbase + bcol + 8) <= Mloc;
    (void)bval0; (void)v0;
    const bool b0ok = (colbase + bcol + 4) <= Mloc;
    const bool b1ok = (colbase + bcol + 8) <= Mloc;

    const float* Ag = a_.A + (size_t)(row0 + arow) * K + akb;
    const float* Bg = a_.B + (size_t)bkrow * Mloc + colbase + bcol;

    float acc[4][4][4];
#pragma unroll
    for (int mt = 0; mt < 4; mt++)
#pragma unroll
        for (int ni = 0; ni < 4; ni++)
#pragma unroll
            for (int r = 0; r < 4; r++) acc[mt][ni][r] = 0.f;

    float av[8], bb[8];

    auto loadG = [&](int k0) {
        float4 t0 = *(const float4*)(Ag + k0);
        float4 t1 = *(const float4*)(Ag + k0 + 4);
        av[0]=t0.x; av[1]=t0.y; av[2]=t0.z; av[3]=t0.w;
        av[4]=t1.x; av[5]=t1.y; av[6]=t1.z; av[7]=t1.w;
        const float* bp = Bg + (size_t)k0 * Mloc;
        float4 u0 = b0ok ? *(const float4*)bp       : make_float4(0,0,0,0);
        float4 u1 = b1ok ? *(const float4*)(bp + 4) : make_float4(0,0,0,0);
        bb[0]=u0.x; bb[1]=u0.y; bb[2]=u0.z; bb[3]=u0.w;
        bb[4]=u1.x; bb[5]=u1.y; bb[6]=u1.z; bb[7]=u1.w;
    };

    auto storeS = [&](int st) {
        const int sbase = st << 9;
#pragma unroll
        for (int u = 0; u < 4; u++) {
            uint32_t hw, lw;
            split_bf16_pair(av[2*u], av[2*u+1], hw, lw);
            int w = (akb >> 1) + u;
            int j = (w & 3) ^ (arow & 3);
            int c = w >> 2;
            ((uint32_t*)&AsH[sbase + (arow << 2) + j])[c] = hw;
            ((uint32_t*)&AsL[sbase + (arow << 2) + j])[c] = lw;
        }
        {
            int w = bkrow >> 1;
            int half = bkrow & 1;
            int c = w >> 2;
            int jb = w & 3;
#pragma unroll
            for (int u = 0; u < 8; u++) {
                int col = bcol + u;
                int j = jb ^ (col & 3);
                __nv_bfloat16 h = __float2bfloat16(bb[u]);
                __nv_bfloat16 l = __float2bfloat16(bb[u] - __bfloat162float(h));
                ((__nv_bfloat16*)&BsH[sbase + (col << 2) + j])[c*2 + half] = h;
                ((__nv_bfloat16*)&BsL[sbase + (col << 2) + j])[c*2 + half] = l;
            }
        }
    };

    auto compute = [&](int st) {
        const int sbase = st << 9;
        uint32_t afH[4][4];
        uint2 bH[4], bL[4];
#pragma unroll
        for (int mt = 0; mt < 4; mt++) {
            int r = wr + mt * 16 + g;
            int j = tg ^ (r & 3);
            uint2 p0 = AsH[sbase + (r << 2) + j];
            uint2 p1 = AsH[sbase + ((r + 8) << 2) + j];
            afH[mt][0] = p0.x; afH[mt][1] = p1.x;
            afH[mt][2] = p0.y; afH[mt][3] = p1.y;
        }
#pragma unroll
        for (int ni = 0; ni < 4; ni++) {
            int cc = wc + ni * 8 + g;
            int j = tg ^ (cc & 3);
            bH[ni] = BsH[sbase + (cc << 2) + j];
            bL[ni] = BsL[sbase + (cc << 2) + j];
        }
#pragma unroll
        for (int ni = 0; ni < 4; ni++)
#pragma unroll
            for (int mt = 0; mt < 4; mt++)
                mma_bf16(acc[mt][ni], afH[mt], bH[ni].x, bH[ni].y);
#pragma unroll
        for (int ni = 0; ni < 4; ni++)
#pragma unroll
            for (int mt = 0; mt < 4; mt++)
                mma_bf16(acc[mt][ni], afH[mt], bL[ni].x, bL[ni].y);
#pragma unroll
        for (int mt = 0; mt < 4; mt++) {
            int r = wr + mt * 16 + g;
            int j = tg ^ (r & 3);
            uint2 p0 = AsL[sbase + (r << 2) + j];
            uint2 p1 = AsL[sbase + ((r + 8) << 2) + j];
            uint32_t afL[4] = {p0.x, p1.x, p0.y, p1.y};
#pragma unroll
            for (int ni = 0; ni < 4; ni++)
                mma_bf16(acc[mt][ni], afL, bH[ni].x, bH[ni].y);
        }
    };

    loadG(0);
    storeS(0);
    __syncthreads();

    const int nIter = K >> 4;
    for (int it = 0; it < nIter; it++) {
        int st = it & 1;
        bool hasNext = (it + 1 < nIter);
        if (hasNext) loadG((it + 1) * 16);
        compute(st);
        if (hasNext) storeS(st ^ 1);
        __syncthreads();
    }

#pragma unroll
    for (int mt = 0; mt < 4; mt++) {
#pragma unroll
        for (int ni = 0; ni < 4; ni++) {
            int r = row0 + wr + mt * 16 + g;
            int c = colbase + wc + ni * 8 + tg * 2;
            if (c + 2 <= Mloc) {
                *(float2*)&a_.C[(size_t)r * Mloc + c] =
                    make_float2(acc[mt][ni][0], acc[mt][ni][1]);
                *(float2*)&a_.C[(size_t)(r + 8) * Mloc + c] =
                    make_float2(acc[mt][ni][2], acc[mt][ni][3]);
            }
        }
    }
}

// ---------------- fused QKVG projection: one launch, grid (19, 16) ----------
__global__ void __launch_bounds__(256, 2)
gemm_bf3_qkvg_kernel(const float* __restrict__ x,
                     const float* __restrict__ Wq, const float* __restrict__ Wk,
                     const float* __restrict__ Wv, const float* __restrict__ Wg,
                     float* __restrict__ q, float* __restrict__ k,
                     float* __restrict__ v, float* __restrict__ gate)
{
    extern __shared__ uint2 smb[];
    BF3Args a;
    a.A = x; a.K = HID; a.row0 = blockIdx.y * 128;
    int bx = blockIdx.x;
    if (bx < 16)      { a.B = Wq; a.C = q;    a.Mloc = HQ*D; a.colbase = bx * 128; }
    else if (bx == 16){ a.B = Wk; a.C = k;    a.Mloc = D;    a.colbase = 0; }
    else if (bx == 17){ a.B = Wv; a.C = v;    a.Mloc = D;    a.colbase = 0; }
    else              { a.B = Wg; a.C = gate; a.Mloc = HQ*3; a.colbase = 0; }
    gemm_bf3_body(a, smb);
}

// ---------------- plain 3xBF16 GEMM (cmp scores) ----------------------------
__global__ void __launch_bounds__(256, 2)
gemm_bf3_kernel(const float* __restrict__ A, const float* __restrict__ B,
                float* __restrict__ C, int K, int M)
{
    extern __shared__ uint2 smb[];
    BF3Args a;
    a.A = A; a.B = B; a.C = C; a.K = K; a.Mloc = M;
    a.colbase = blockIdx.x * 128; a.row0 = blockIdx.y * 128;
    gemm_bf3_body(a, smb);
}

// ---------------- 1-term tf32 GEMM (continuous paths) ------------------------
__global__ void __launch_bounds__(256, 2)
gemm_t1_kernel(const float* __restrict__ A, const float* __restrict__ B,
               float* __restrict__ C, int K, int M)
{
    extern __shared__ uint2 sm[];
    uint2* AsH = sm;
    uint2* BsH = sm + 2048;

    const int tid = threadIdx.x;
    const int wid = tid >> 5, lane = tid & 31;
    const int row0 = blockIdx.y * 128, col0 = blockIdx.x * 128;
    const int wr = (wid & 1) * 64, wc = (wid >> 1) * 32;
    const int g = lane >> 2, tg = lane & 3;

    const int arow = tid >> 1, akb = (tid & 1) * 8;
    const int bkrow = tid >> 4, bcol = (tid & 15) * 8;
    const bool bval0 = (col0 + bcol + 4) <= M;
    const bool bval1 = (col0 + bcol + 8) <= M;

    const float* Ag = A + (size_t)(row0 + arow) * K + akb;
    const float* Bg = B + (size_t)bkrow * M + col0 + bcol;

    float acc[4][4][4];
#pragma unroll
    for (int mt = 0; mt < 4; mt++)
#pragma unroll
        for (int ni = 0; ni < 4; ni++)
#pragma unroll
            for (int r = 0; r < 4; r++) acc[mt][ni][r] = 0.f;

    float av[8], bb[8];

    auto loadG = [&](int k0) {
        float4 t0 = *(const float4*)(Ag + k0);
        float4 t1 = *(const float4*)(Ag + k0 + 4);
        av[0]=t0.x; av[1]=t0.y; av[2]=t0.z; av[3]=t0.w;
        av[4]=t1.x; av[5]=t1.y; av[6]=t1.z; av[7]=t1.w;
        const float* bp = Bg + (size_t)k0 * M;
        float4 u0 = bval0 ? *(const float4*)bp       : make_float4(0,0,0,0);
        float4 u1 = bval1 ? *(const float4*)(bp + 4) : make_float4(0,0,0,0);
        bb[0]=u0.x; bb[1]=u0.y; bb[2]=u0.z; bb[3]=u0.w;
        bb[4]=u1.x; bb[5]=u1.y; bb[6]=u1.z; bb[7]=u1.w;
    };

    auto storeS = [&](int st) {
        const int sbase = st << 10;
#pragma unroll
        for (int u = 0; u < 8; u++) {
            int k = akb + u;
            int p = ((k >> 3) << 2) | (k & 3);
            int c = (k >> 2) & 1;
            int ph = p ^ ((arow & 3) << 1);
            ((uint32_t*)&AsH[sbase + (arow << 3) + ph])[c] = f2tf32(av[u]);
        }
        {
            int k = bkrow;
            int p = ((k >> 3) << 2) | (k & 3);
            int c = (k >> 2) & 1;
#pragma unroll
            for (int u = 0; u < 8; u++) {
                int col = bcol + u;
                int ph = p ^ ((col & 3) << 1);
                ((uint32_t*)&BsH[sbase + (col << 3) + ph])[c] = f2tf32(bb[u]);
            }
        }
    };

    auto compute = [&](int st) {
        const int sbase = st << 10;
#pragma unroll
        for (int hb = 0; hb < 2; hb++) {
            const int ph = (hb * 4 + tg) ^ ((g & 3) << 1);
            uint32_t afH[4][4];
            uint2 bH[4];
#pragma unroll
            for (int mt = 0; mt < 4; mt++) {
                int r = wr + mt * 16 + g;
                uint2 p0 = AsH[sbase + (r << 3) + ph];
                uint2 p1 = AsH[sbase + ((r + 8) << 3) + ph];
                afH[mt][0] = p0.x; afH[mt][1] = p1.x;
                afH[mt][2] = p0.y; afH[mt][3] = p1.y;
            }
#pragma unroll
            for (int ni = 0; ni < 4; ni++) {
                int cc = wc + ni * 8 + g;
                bH[ni] = BsH[sbase + (cc << 3) + ph];
            }
#pragma unroll
            for (int ni = 0; ni < 4; ni++)
#pragma unroll
                for (int mt = 0; mt < 4; mt++)
                    mma_tf32(acc[mt][ni], afH[mt], bH[ni].x, bH[ni].y);
        }
    };

    loadG(0);
    storeS(0);
    __syncthreads();

    const int nIter = K >> 4;
    for (int it = 0; it < nIter; it++) {
        int st = it & 1;
        bool hasNext = (it + 1 < nIter);
        if (hasNext) loadG((it + 1) * 16);
        compute(st);
        if (hasNext) storeS(st ^ 1);
        __syncthreads();
    }

#pragma unroll
    for (int mt = 0; mt < 4; mt++) {
#pragma unroll
        for (int ni = 0; ni < 4; ni++) {
            int r = row0 + wr + mt * 16 + g;
            int c = col0 + wc + ni * 8 + tg * 2;
            if (c + 2 <= M) {
                *(float2*)&C[(size_t)r * M + c] =
                    make_float2(acc[mt][ni][0], acc[mt][ni][1]);
                *(float2*)&C[(size_t)(r + 8) * M + c] =
                    make_float2(acc[mt][ni][2], acc[mt][ni][3]);
            }
        }
    }
}

// ---------------- compressed k/v (pre-RoPE) --------------------------------
__global__ void compress_kernel(const float* __restrict__ k,
                                const float* __restrict__ v,
                                const float* __restrict__ pe,
                                float* __restrict__ ck,
                                float* __restrict__ cv)
{
    int m = blockIdx.x;
    int d = threadIdx.x;
    float sk = 0.f, sv = 0.f;
#pragma unroll 8
    for (int i = 0; i < KS; i++) {
        sk += k[(m*KS + i)*D + d] + pe[i*D + d];
        sv += v[(m*KS + i)*D + d];
    }
    ck[m*D + d] = sk * (1.f/KS);
    cv[m*D + d] = sv * (1.f/KS);
}

// ---------------- RoPE (in place) ------------------------------------------
__global__ void rope_kernel(float* __restrict__ x, int heads, int pos_stride)
{
    int row = blockIdx.x;
    int d   = threadIdx.x;
    float inv = powf(10000.f, -(float)d / 64.f);
    float ang = (float)(row * pos_stride) * inv;
    float c = cosf(ang), s = sinf(ang);
    for (int h = 0; h < heads; h++) {
        float* p = x + ((size_t)row*heads + h) * D;
        float x1 = p[d], x2 = p[d + 64];
        p[d]      = x1 * c - x2 * s;
        p[d + 64] = x2 * c + x1 * s;
    }
}

// ---------------- ck transpose ----------------------------------------------
__global__ void transpose_ck_kernel(const float* __restrict__ ck,
                                    float* __restrict__ ckT)
{
    int i = blockIdx.x * 256 + threadIdx.x;
    int m = i >> 7, d = i & 127;
    ckT[d*NC + m] = ck[m*D + d];
}

// ---------------- cmp softmax / mask / block-score --------------------------
__global__ void cmp_softmax_kernel(float* __restrict__ sc,
                                   float* __restrict__ blks)
{
    int n = blockIdx.x;
    __shared__ float pcs[HQ][NC];
    int tid = threadIdx.x;

    float* base = sc + (size_t)n * HQ * NC;
    {
        int h = tid >> 4, m4 = (tid & 15) * 4;
        float4 vv = *(float4*)&base[h*NC + m4];
        float s[4] = {vv.x, vv.y, vv.z, vv.w};
#pragma unroll
        for (int u = 0; u < 4; u++) {
            int m = m4 + u;
            bool valid = (n >= m*STRIDE + KS - 1);
            s[u] = valid ? s[u] * SCALE : NEGF;
        }
        pcs[h][m4+0] = s[0]; pcs[h][m4+1] = s[1];
        pcs[h][m4+2] = s[2]; pcs[h][m4+3] = s[3];
    }
    __syncthreads();

    {
        int w = tid >> 5, l = tid & 31;
        for (int h = w; h < HQ; h += 8) {
            float a = pcs[h][l], b = pcs[h][l + 32];
            float mx = fmaxf(a, b);
#pragma unroll
            for (int o = 16; o > 0; o >>= 1) mx = fmaxf(mx, __shfl_xor_sync(0xffffffff, mx, o));
            float ea = __expf(a - mx), eb = __expf(b - mx);
            float s = ea + eb;
#pragma unroll
            for (int o = 16; o > 0; o >>= 1) s += __shfl_xor_sync(0xffffffff, s, o);
            float inv = 1.f / s;
            bool va = (n >= l*STRIDE + KS - 1);
            bool vb = (n >= (l+32)*STRIDE + KS - 1);
            pcs[h][l]      = va ? ea * inv : 0.f;
            pcs[h][l + 32] = vb ? eb * inv : 0.f;
        }
    }
    __syncthreads();

    for (int m = tid; m < NC; m += 256) {
        float s = 0.f;
        for (int h = 0; h < HQ; h++) s += pcs[h][m];
        blks[(size_t)n*NC + m] = s;
    }
    {
        int h = tid >> 4, m4 = (tid & 15) * 4;
        *(float4*)&base[h*NC + m4] =
            make_float4(pcs[h][m4], pcs[h][m4+1], pcs[h][m4+2], pcs[h][m4+3]);
    }
}

// ---------------- top-k selection (warp per token) --------------------------
__global__ void topk_kernel(const float* __restrict__ blks, int* __restrict__ topk)
{
    int gidx = blockIdx.x * blockDim.x + threadIdx.x;
    int n = gidx >> 5;
    int lane = threadIdx.x & 31;
    if (n >= N_TOK) return;
    int tb = n / BSZ;
    int m0 = lane, m1 = lane + 32;
    float s0 = blks[(size_t)n*NC + m0];
    float s1 = blks[(size_t)n*NC + m1];
    if (m0 > tb) s0 = NEGF;
    if (m0 < 1 || (m0 <= tb && m0 > tb - 2)) s0 = 1e30f;
    if (m1 > tb) s1 = NEGF;
    if (m1 < 1 || (m1 <= tb && m1 > tb - 2)) s1 = 1e30f;
#pragma unroll
    for (int j = 0; j < TOPK; j++) {
        float bv; int bi;
        if (s0 >= s1) { bv = s0; bi = m0; } else { bv = s1; bi = m1; }
#pragma unroll
        for (int o = 16; o > 0; o >>= 1) {
            float ov = __shfl_down_sync(0xffffffff, bv, o);
            int   oi = __shfl_down_sync(0xffffffff, bi, o);
            if (ov > bv || (ov == bv && oi < bi)) { bv = ov; bi = oi; }
        }
        bi = __shfl_sync(0xffffffff, bi, 0);
        if (lane == 0) topk[n*TOPK + j] = bi;
        if (bi == m0) s0 = -FLT_MAX;
        if (bi == m1) s1 = -FLT_MAX;
    }
}

// ============ SIMT helpers (sel attention) ==================================
#define KVP 132

__device__ __forceinline__ void attn_softmax_update(
    float* sc, float* mS, float* lS, float* fS, int tid)
{
    int h = tid >> 4, t = tid & 15;
    float4 sv = *(float4*)&sc[h*64 + t*4];
    float pm = fmaxf(fmaxf(sv.x, sv.y), fmaxf(sv.z, sv.w));
#pragma unroll
    for (int o = 1; o < 16; o <<= 1) pm = fmaxf(pm, __shfl_xor_sync(0xffffffff, pm, o));
    float mOld = mS[h];
    float mNew = fmaxf(mOld, pm);
    float4 p;
    p.x = __expf(sv.x - mNew); p.y = __expf(sv.y - mNew);
    p.z = __expf(sv.z - mNew); p.w = __expf(sv.w - mNew);
    *(float4*)&sc[h*64 + t*4] = p;
    float ps = p.x + p.y + p.z + p.w;
#pragma unroll
    for (int o = 1; o < 16; o <<= 1) ps += __shfl_xor_sync(0xffffffff, ps, o);
    if (t == 0) {
        float f = __expf(mOld - mNew);
        fS[h] = f;
        lS[h] = lS[h] * f + ps;
        mS[h] = mNew;
    }
}

__device__ __forceinline__ void attn_pv(
    const float* kv, const float* sc, float* acc, float f, int h, int d0, int tl)
{
#pragma unroll
    for (int i = 0; i < 8; i++) acc[i] *= f;
    for (int j = 0; j < tl; j++) {
        float p = sc[h*64 + j];
        float4 v0 = *(const float4*)&kv[j*KVP + d0];
        float4 v1 = *(const float4*)&kv[j*KVP + d0 + 4];
        acc[0] += p*v0.x; acc[1] += p*v0.y; acc[2] += p*v0.z; acc[3] += p*v0.w;
        acc[4] += p*v1.x; acc[5] += p*v1.y; acc[6] += p*v1.z; acc[7] += p*v1.w;
    }
}

// ---------------- selected (top-k) attention (SIMT) -------------------------
__global__ void __launch_bounds__(256, 2)
sel_attn_kernel(const float* __restrict__ q, const float* __restrict__ k,
                const float* __restrict__ v, const int* __restrict__ topk,
                float* __restrict__ out)
{
    int n = blockIdx.x;
    int tid = threadIdx.x;
    __shared__ float qs[HQ*D];
    __shared__ float kv[64*KVP];
    __shared__ float sc[HQ*64];
    __shared__ int   posA[TOPK*BSZ];
    __shared__ float mS[HQ], lS[HQ], fS[HQ];

    for (int e = tid; e < HQ*D/4; e += 256)
        ((float4*)qs)[e] = ((const float4*)(q + (size_t)n*HQ*D))[e];
    if (tid < HQ) { mS[tid] = -FLT_MAX; lS[tid] = 0.f; }
    posA[tid] = topk[n*TOPK + (tid >> 5)] * BSZ + (tid & 31);

    int h  = tid >> 4;
    int d0 = (tid & 15) * 8;
    float acc[8];
#pragma unroll
    for (int i = 0; i < 8; i++) acc[i] = 0.f;
    __syncthreads();

    for (int t0 = 0; t0 < TOPK*BSZ; t0 += 64) {
        for (int e = tid; e < 64*32; e += 256) {
            int row = e >> 5, c = e & 31;
            *(float4*)&kv[row*KVP + c*4] = ((const float4*)(k + (size_t)posA[t0 + row]*D))[c];
        }
        __syncthreads();
        {
            int jj = tid & 63;
            int hb = (tid >> 6) * 4;
            bool valid = posA[t0 + jj] <= n;
            float s0=0.f,s1=0.f,s2=0.f,s3=0.f;
            if (valid) {
                const float4* kr = (const float4*)(kv + jj*KVP);
                const float4* q0 = (const float4*)(qs + (hb+0)*D);
                const float4* q1 = (const float4*)(qs + (hb+1)*D);
                const float4* q2 = (const float4*)(qs + (hb+2)*D);
                const float4* q3 = (const float4*)(qs + (hb+3)*D);
#pragma unroll
                for (int c = 0; c < 32; c++) {
                    float4 kk = kr[c];
                    float4 a;
                    a = q0[c]; s0 += a.x*kk.x + a.y*kk.y + a.z*kk.z + a.w*kk.w;
                    a = q1[c]; s1 += a.x*kk.x + a.y*kk.y + a.z*kk.z + a.w*kk.w;
                    a = q2[c]; s2 += a.x*kk.x + a.y*kk.y + a.z*kk.z + a.w*kk.w;
                    a = q3[c]; s3 += a.x*kk.x + a.y*kk.y + a.z*kk.z + a.w*kk.w;
                }
                sc[(hb+0)*64+jj]=s0*SCALE; sc[(hb+1)*64+jj]=s1*SCALE;
                sc[(hb+2)*64+jj]=s2*SCALE; sc[(hb+3)*64+jj]=s3*SCALE;
            } else {
                sc[(hb+0)*64+jj]=NEGF; sc[(hb+1)*64+jj]=NEGF;
                sc[(hb+2)*64+jj]=NEGF; sc[(hb+3)*64+jj]=NEGF;
            }
        }
        __syncthreads();
        attn_softmax_update(sc, mS, lS, fS, tid);
        __syncthreads();
        for (int e = tid; e < 64*32; e += 256) {
            int row = e >> 5, c = e & 31;
            *(float4*)&kv[row*KVP + c*4] = ((const float4*)(v + (size_t)posA[t0 + row]*D))[c];
        }
        __syncthreads();
        attn_pv(kv, sc, acc, fS[h], h, d0, 64);
        __syncthreads();
    }
    float inv = 1.f / lS[h];
    float4 o0 = make_float4(acc[0]*inv, acc[1]*inv, acc[2]*inv, acc[3]*inv);
    float4 o1 = make_float4(acc[4]*inv, acc[5]*inv, acc[6]*inv, acc[7]*inv);
    *(float4*)&out[((size_t)n*HQ + h)*D + d0]     = o0;
    *(float4*)&out[((size_t)n*HQ + h)*D + d0 + 4] = o1;
}

// ================= window attention via 1-term tf32 tensor cores ============
__global__ void __launch_bounds__(256, 2)
win_mma_kernel(const float* __restrict__ q, const float* __restrict__ k,
               const float* __restrict__ v, float* __restrict__ out)
{
    extern __shared__ uint2 smw[];
    uint2* Qh = smw;
    uint2* Bh = smw + 4096;
    uint2* Ph = smw + 8192;
    float* stats = (float*)(smw + 10240);
    float* mS   = stats;
    float* lS   = stats + 64;
    float* fS   = stats + 128;
    float* pmax = stats + 192;
    float* psum = stats + 320;

    const int tid = threadIdx.x;
    const int wid = tid >> 5, lane = tid & 31;
    const int g = lane >> 2, tg = lane & 3;
    const int qtile0 = (gridDim.x - 1 - blockIdx.x) * 64;
    const int h = blockIdx.y;

    for (int e = tid; e < 64*32; e += 256) {
        int row = e >> 5, c4 = e & 31;
        float4 vq = *(const float4*)&q[(((size_t)(qtile0 + row))*HQ + h)*D + c4*4];
        float qv[4] = {vq.x, vq.y, vq.z, vq.w};
#pragma unroll
        for (int u = 0; u < 4; u++) {
            int d = c4*4 + u;
            int ch = d >> 4, kk = d & 15;
            int p = ((kk >> 3) << 2) | (kk & 3);
            int cc = (kk >> 2) & 1;
            int ph = p ^ ((row & 3) << 1);
            ((uint32_t*)&Qh[ch*512 + (row << 3) + ph])[cc] = f2tf32(qv[u]);
        }
    }
    if (tid < 64) { mS[tid] = -3.0e38f; lS[tid] = 0.f; }

    const int mtS = wid & 3, cg = wid >> 2;
    const int mtP = wid & 3, dh = wid >> 2;

    float oacc[8][4];
#pragma unroll
    for (int ni = 0; ni < 8; ni++)
#pragma unroll
        for (int r = 0; r < 4; r++) oacc[ni][r] = 0.f;

    int klo = qtile0 - WIN; if (klo < 0) klo = 0;
    __syncthreads();

    for (int kt = klo; kt < qtile0 + 64; kt += 64) {
        for (int e = tid; e < 64*32; e += 256) {
            int key = e >> 5, c4 = e & 31;
            float4 vk = *(const float4*)&k[((size_t)(kt + key))*D + c4*4];
            float kv4[4] = {vk.x, vk.y, vk.z, vk.w};
#pragma unroll
            for (int u = 0; u < 4; u++) {
                int d = c4*4 + u;
                int ch = d >> 4, kk = d & 15;
                int p = ((kk >> 3) << 2) | (kk & 3);
                int cc = (kk >> 2) & 1;
                int ph = p ^ ((key & 3) << 1);
                ((uint32_t*)&Bh[ch*512 + (key << 3) + ph])[cc] = f2tf32(kv4[u]);
            }
        }
        __syncthreads();

        float sacc[4][4];
#pragma unroll
        for (int ni = 0; ni < 4; ni++)
#pragma unroll
            for (int r = 0; r < 4; r++) sacc[ni][r] = 0.f;

#pragma unroll
        for (int ch = 0; ch < 8; ch++) {
#pragma unroll
            for (int hb = 0; hb < 2; hb++) {
                const int ph = (hb*4 + tg) ^ ((g & 3) << 1);
                int r = mtS*16 + g;
                uint2 a0 = Qh[ch*512 + (r << 3) + ph];
                uint2 a1 = Qh[ch*512 + ((r + 8) << 3) + ph];
                uint32_t afH[4] = {a0.x, a1.x, a0.y, a1.y};
#pragma unroll
                for (int ni = 0; ni < 4; ni++) {
                    int col = cg*32 + ni*8 + g;
                    uint2 bH = Bh[ch*512 + (col << 3) + ph];
                    mma_tf32(sacc[ni], afH, bH.x, bH.y);
                }
            }
        }

        const int rA = qtile0 + mtS*16 + g;
        const int rB = rA + 8;
        float m1 = -3.0e38f, m2 = -3.0e38f;
#pragma unroll
        for (int ni = 0; ni < 4; ni++) {
            int key0 = kt + cg*32 + ni*8 + tg*2;
#pragma unroll
            for (int i = 0; i < 4; i++) {
                int key = key0 + (i & 1);
                int qp = (i < 2) ? rA : rB;
                float s = sacc[ni][i] * SCALE;
                bool valid = (key <= qp) && (key >= qp - WIN);
                s = valid ? s : NEGF;
                sacc[ni][i] = s;
                if (i < 2) m1 = fmaxf(m1, s); else m2 = fmaxf(m2, s);
            }
        }
#pragma unroll
        for (int o = 1; o < 4; o <<= 1) {
            m1 = fmaxf(m1, __shfl_xor_sync(0xffffffff, m1, o));
            m2 = fmaxf(m2, __shfl_xor_sync(0xffffffff, m2, o));
        }
        int rlA = mtS*16 + g, rlB = rlA + 8;
        if (tg == 0) { pmax[rlA*2 + cg] = m1; pmax[rlB*2 + cg] = m2; }
        __syncthreads();

        float mnA = fmaxf(mS[rlA], fmaxf(pmax[rlA*2], pmax[rlA*2+1]));
        float mnB = fmaxf(mS[rlB], fmaxf(pmax[rlB*2], pmax[rlB*2+1]));
        float sumA = 0.f, sumB = 0.f;
#pragma unroll
        for (int ni = 0; ni < 4; ni++) {
#pragma unroll
            for (int i = 0; i < 4; i++) {
                float s = sacc[ni][i];
                float mn = (i < 2) ? mnA : mnB;
                float p = (s <= -1e29f) ? 0.f : __expf(s - mn);
                if (i < 2) sumA += p; else sumB += p;
                int cloc = cg*32 + ni*8 + tg*2 + (i & 1);
                int ch = cloc >> 4, kk = cloc & 15;
                int pp = ((kk >> 3) << 2) | (kk & 3);
                int cc = (kk >> 2) & 1;
                int rl = (i < 2) ? rlA : rlB;
                int ph = pp ^ ((rl & 3) << 1);
                ((uint32_t*)&Ph[ch*512 + (rl << 3) + ph])[cc] = f2tf32(p);
            }
        }
#pragma unroll
        for (int o = 1; o < 4; o <<= 1) {
            sumA += __shfl_xor_sync(0xffffffff, sumA, o);
            sumB += __shfl_xor_sync(0xffffffff, sumB, o);
        }
        if (tg == 0) { psum[rlA*2 + cg] = sumA; psum[rlB*2 + cg] = sumB; }

        for (int e = tid; e < 64*32; e += 256) {
            int key = e >> 5, c4 = e & 31;
            float4 vv = *(const float4*)&v[((size_t)(kt + key))*D + c4*4];
            float v4[4] = {vv.x, vv.y, vv.z, vv.w};
            int chv = key >> 4, kkv = key & 15;
            int pv = ((kkv >> 3) << 2) | (kkv & 3);
            int ccv = (kkv >> 2) & 1;
#pragma unroll
            for (int u = 0; u < 4; u++) {
                int d = c4*4 + u;
                int phv = pv ^ ((d & 3) << 1);
                ((uint32_t*)&Bh[chv*1024 + (d << 3) + phv])[ccv] = f2tf32(v4[u]);
            }
        }
        __syncthreads();

        if (tid < 64) {
            float mo = mS[tid];
            float mn = fmaxf(mo, fmaxf(pmax[tid*2], pmax[tid*2+1]));
            float f = __expf(mo - mn);
            lS[tid] = lS[tid] * f + psum[tid*2] + psum[tid*2+1];
            mS[tid] = mn;
            fS[tid] = f;
        }
        __syncthreads();

        {
            int rl1 = mtP*16 + g, rl2 = rl1 + 8;
            float f1 = fS[rl1], f2 = fS[rl2];
#pragma unroll
            for (int ni = 0; ni < 8; ni++) {
                oacc[ni][0] *= f1; oacc[ni][1] *= f1;
                oacc[ni][2] *= f2; oacc[ni][3] *= f2;
            }
#pragma unroll
            for (int ch = 0; ch < 4; ch++) {
#pragma unroll
                for (int hb = 0; hb < 2; hb++) {
                    const int ph = (hb*4 + tg) ^ ((g & 3) << 1);
                    int r = mtP*16 + g;
                    uint2 a0 = Ph[ch*512 + (r << 3) + ph];
                    uint2 a1 = Ph[ch*512 + ((r + 8) << 3) + ph];
                    uint32_t afH[4] = {a0.x, a1.x, a0.y, a1.y};
#pragma unroll
                    for (int ni = 0; ni < 8; ni++) {
                        int col = dh*64 + ni*8 + g;
                        uint2 bH = Bh[ch*1024 + (col << 3) + ph];
                        mma_tf32(oacc[ni], afH, bH.x, bH.y);
                    }
                }
            }
        }
        __syncthreads();
    }

    {
        int rl1 = mtP*16 + g, rl2 = rl1 + 8;
        float i1 = 1.f / lS[rl1], i2 = 1.f / lS[rl2];
        size_t b1 = ((size_t)(qtile0 + rl1)*HQ + h)*D;
        size_t b2 = ((size_t)(qtile0 + rl2)*HQ + h)*D;
#pragma unroll
        for (int ni = 0; ni < 8; ni++) {
            int d = dh*64 + ni*8 + tg*2;
            *(float2*)&out[b1 + d] = make_float2(oacc[ni][0]*i1, oacc[ni][1]*i1);
            *(float2*)&out[b2 + d] = make_float2(oacc[ni][2]*i2, oacc[ni][3]*i2);
        }
    }
}

// ---------------- gate combine ---------------------------------------------
__global__ void combine_kernel(const float* __restrict__ gbuf,
                               const float* __restrict__ cmp,
                               const float* __restrict__ sp,
                               const float* __restrict__ sw,
                               float* __restrict__ att)
{
    size_t idx = (size_t)blockIdx.x * 256 + threadIdx.x;
    int n = (int)(idx >> 11);
    int hd = (int)(idx & 2047);
    int h = hd >> 7;
    const float* g = gbuf + (size_t)n*HQ*3 + h*3;
    float g0 = 1.f / (1.f + __expf(-g[0]));
    float g1 = 1.f / (1.f + __expf(-g[1]));
    float g2 = 1.f / (1.f + __expf(-g[2]));
    att[idx] = g0 * cmp[idx] + g1 * sp[idx] + g2 * sw[idx];
}

// ---------------- launcher with stream fork/join -----------------------------
extern "C" void kernel_launch(void* const* d_in, const int* in_sizes, int n_in,
                              void* d_out, int out_size)
{
    const float* x  = (const float*)d_in[0];
    const float* Wq = (const float*)d_in[2];
    const float* Wk = (const float*)d_in[3];
    const float* Wv = (const float*)d_in[4];
    const float* Wo = (const float*)d_in[5];
    const float* Wg = (const float*)d_in[6];
    const float* pe = (const float*)d_in[7];
    float* out = (float*)d_out;

    float *q, *k, *v, *ck, *ckT, *cv, *blks, *cmp, *sp, *sw, *gate, *att, *part;
    int* tk;
    cudaGetSymbolAddress((void**)&q,    g_q);
    cudaGetSymbolAddress((void**)&k,    g_k);
    cudaGetSymbolAddress((void**)&v,    g_v);
    cudaGetSymbolAddress((void**)&ck,   g_ck);
    cudaGetSymbolAddress((void**)&ckT,  g_ckT);
    cudaGetSymbolAddress((void**)&cv,   g_cv);
    cudaGetSymbolAddress((void**)&blks, g_blks);
    cudaGetSymbolAddress((void**)&tk,   g_topk);
    cudaGetSymbolAddress((void**)&cmp,  g_cmp);
    cudaGetSymbolAddress((void**)&sp,   g_sp);
    cudaGetSymbolAddress((void**)&sw,   g_sw);
    cudaGetSymbolAddress((void**)&gate, g_gate);
    cudaGetSymbolAddress((void**)&att,  g_att);
    cudaGetSymbolAddress((void**)&part, g_part);

    const int SMEMB3 = 32768;
    const int SMEM1  = 32768;
    const int SMEMW  = 10240*8 + 448*4;
    cudaFuncSetAttribute(gemm_bf3_qkvg_kernel, cudaFuncAttributeMaxDynamicSharedMemorySize, SMEMB3);
    cudaFuncSetAttribute(gemm_bf3_kernel, cudaFuncAttributeMaxDynamicSharedMemorySize, SMEMB3);
    cudaFuncSetAttribute(gemm_t1_kernel, cudaFuncAttributeMaxDynamicSharedMemorySize, SMEM1);
    cudaFuncSetAttribute(win_mma_kernel, cudaFuncAttributeMaxDynamicSharedMemorySize, SMEMW);

    static cudaStream_t sB = nullptr, sC = nullptr;
    static cudaEvent_t evPROJ = nullptr, evQ = nullptr, evKV = nullptr,
                       evTK = nullptr, evCMP = nullptr, evSEL = nullptr;
    if (!sB) {
        cudaStreamCreateWithFlags(&sB, cudaStreamNonBlocking);
        cudaStreamCreateWithFlags(&sC, cudaStreamNonBlocking);
        cudaEventCreateWithFlags(&evPROJ, cudaEventDisableTiming);
        cudaEventCreateWithFlags(&evQ,    cudaEventDisableTiming);
        cudaEventCreateWithFlags(&evKV,   cudaEventDisableTiming);
        cudaEventCreateWithFlags(&evTK,   cudaEventDisableTiming);
        cudaEventCreateWithFlags(&evCMP,  cudaEventDisableTiming);
        cudaEventCreateWithFlags(&evSEL,  cudaEventDisableTiming);
    }

    // --- fused projections (default stream): q,k,v,gate in ONE launch -------
    gemm_bf3_qkvg_kernel<<<dim3(19, 16, 1), 256, SMEMB3>>>(
        x, Wq, Wk, Wv, Wg, q, k, v, gate);
    cudaEventRecord(evPROJ, 0);
    rope_kernel<<<N_TOK, 64>>>(q, HQ, 1);
    cudaEventRecord(evQ, 0);

    // --- spine B: compress/rope/transpose, then cmp scores -> topk ----------
    cudaStreamWaitEvent(sB, evPROJ, 0);
    compress_kernel<<<NC, D, 0, sB>>>(k, v, pe, ck, cv);
    rope_kernel<<<N_TOK, 64, 0, sB>>>(k, 1, 1);
    rope_kernel<<<NC, 64, 0, sB>>>(ck, 1, STRIDE);
    transpose_ck_kernel<<<32, 256, 0, sB>>>(ck, ckT);
    cudaEventRecord(evKV, sB);

    cudaStreamWaitEvent(sB, evQ, 0);
    gemm_bf3_kernel<<<dim3(1, 256, 1), 256, SMEMB3, sB>>>(q, ckT, part, D, NC);
    cmp_softmax_kernel<<<N_TOK, 256, 0, sB>>>(part, blks);
    topk_kernel<<<(N_TOK*32 + 255)/256, 256, 0, sB>>>(blks, tk);
    cudaEventRecord(evTK, sB);
    gemm_t1_kernel<<<dim3(1, 256, 1), 256, SMEM1, sB>>>(part, cv, cmp, NC, D);
    cudaEventRecord(evCMP, sB);

    // --- spine C: sel after topk --------------------------------------------
    cudaStreamWaitEvent(sC, evTK, 0);
    sel_attn_kernel<<<N_TOK, 256, 0, sC>>>(q, k, v, tk, sp);
    cudaEventRecord(evSEL, sC);

    // --- spine A continues: win after k/v ready -----------------------------
    cudaStreamWaitEvent(0, evKV, 0);
    win_mma_kernel<<<dim3(32, HQ), 256, SMEMW>>>(q, k, v, sw);

    // join
    cudaStreamWaitEvent(0, evSEL, 0);
    cudaStreamWaitEvent(0, evCMP, 0);
    combine_kernel<<<(N_TOK*HQ*D)/256, 256>>>(gate, cmp, sp, sw, att);
    gemm_t1_kernel<<<dim3(16, 16, 1), 256, SMEM1>>>(att, Wo, out, HID, HID);
}

// round 17
// speedup vs baseline: 1.2439x; 1.0209x over previous
#include <cuda_runtime.h>
#include <cuda_bf16.h>
#include <math.h>
#include <float.h>
#include <stdint.h>

#define N_TOK 2048
#define HID   2048
#define HQ    16
#define D     128
#define NC    64
#define KS    32
#define STRIDE 32
#define BSZ   32
#define TOPK  8
#define WIN   512
#define SCALE 0.08838834764831845f  /* 1/sqrt(128) */
#define NEGF  -1e30f

// ---------------- scratch (device globals) ---------------------------------
__device__ float g_q   [N_TOK*HQ*D];
__device__ float g_k   [N_TOK*D];
__device__ float g_v   [N_TOK*D];
__device__ float g_ck  [NC*D];
__device__ float g_ckT [D*NC];
__device__ float g_cv  [NC*D];
__device__ float g_blks[N_TOK*NC];
__device__ int   g_topk[N_TOK*TOPK];
__device__ float g_cmp [N_TOK*HQ*D];
__device__ float g_sp  [N_TOK*HQ*D];
__device__ float g_sw  [N_TOK*HQ*D];
__device__ float g_gate[N_TOK*HQ*3];
__device__ float g_att [N_TOK*HID];
__device__ float g_part [8 * N_TOK * 128];

// ---------------- tf32 / bf16 helpers ----------------------------------------
__device__ __forceinline__ uint32_t f2tf32(float f) {
    uint32_t u;
    asm("cvt.rna.tf32.f32 %0, %1;" : "=r"(u) : "f"(f));
    return u;
}
__device__ __forceinline__ void mma_tf32(float* c, const uint32_t* a,
                                         uint32_t b0, uint32_t b1) {
    asm volatile(
        "mma.sync.aligned.m16n8k8.row.col.f32.tf32.tf32.f32 "
        "{%0,%1,%2,%3}, {%4,%5,%6,%7}, {%8,%9}, {%0,%1,%2,%3};"
        : "+f"(c[0]), "+f"(c[1]), "+f"(c[2]), "+f"(c[3])
        : "r"(a[0]), "r"(a[1]), "r"(a[2]), "r"(a[3]), "r"(b0), "r"(b1));
}
__device__ __forceinline__ void mma_bf16(float* c, const uint32_t* a,
                                         uint32_t b0, uint32_t b1) {
    asm volatile(
        "mma.sync.aligned.m16n8k16.row.col.f32.bf16.bf16.f32 "
        "{%0,%1,%2,%3}, {%4,%5,%6,%7}, {%8,%9}, {%0,%1,%2,%3};"
        : "+f"(c[0]), "+f"(c[1]), "+f"(c[2]), "+f"(c[3])
        : "r"(a[0]), "r"(a[1]), "r"(a[2]), "r"(a[3]), "r"(b0), "r"(b1));
}
__device__ __forceinline__ void split_bf16_pair(float f0, float f1,
                                                uint32_t& hw, uint32_t& lw) {
    __nv_bfloat162 h2 = __floats2bfloat162_rn(f0, f1);
    float h0 = __bfloat162float(__low2bfloat16(h2));
    float h1 = __bfloat162float(__high2bfloat16(h2));
    __nv_bfloat162 l2 = __floats2bfloat162_rn(f0 - h0, f1 - h1);
    hw = *reinterpret_cast<uint32_t*>(&h2);
    lw = *reinterpret_cast<uint32_t*>(&l2);
}

// ================= 3xBF16 GEMM core (device) ================================
struct BF3Args {
    const float* A; const float* B; float* C;
    int K; int Mloc; int colbase; int row0;
};

__device__ __forceinline__ void gemm_bf3_body(const BF3Args& a_, uint2* smb)
{
    uint2* AsH = smb;
    uint2* AsL = smb + 1024;
    uint2* BsH = smb + 2048;
    uint2* BsL = smb + 3072;

    const int tid = threadIdx.x;
    const int wid = tid >> 5, lane = tid & 31;
    const int wr = (wid & 1) * 64, wc = (wid >> 1) * 32;
    const int g = lane >> 2, tg = lane & 3;
    const int K = a_.K, Mloc = a_.Mloc, colbase = a_.colbase, row0 = a_.row0;

    const int arow = tid >> 1, akb = (tid & 1) * 8;
    const int bkrow = tid >> 4, bcol = (tid & 15) * 8;
    const bool b0ok = (colbase + bcol + 4) <= Mloc;
    const bool b1ok = (colbase + bcol + 8) <= Mloc;

    const float* Ag = a_.A + (size_t)(row0 + arow) * K + akb;
    const float* Bg = a_.B + (size_t)bkrow * Mloc + colbase + bcol;

    float acc[4][4][4];
#pragma unroll
    for (int mt = 0; mt < 4; mt++)
#pragma unroll
        for (int ni = 0; ni < 4; ni++)
#pragma unroll
            for (int r = 0; r < 4; r++) acc[mt][ni][r] = 0.f;

    float av[8], bb[8];

    auto loadG = [&](int k0) {
        float4 t0 = *(const float4*)(Ag + k0);
        float4 t1 = *(const float4*)(Ag + k0 + 4);
        av[0]=t0.x; av[1]=t0.y; av[2]=t0.z; av[3]=t0.w;
        av[4]=t1.x; av[5]=t1.y; av[6]=t1.z; av[7]=t1.w;
        const float* bp = Bg + (size_t)k0 * Mloc;
        float4 u0 = b0ok ? *(const float4*)bp       : make_float4(0,0,0,0);
        float4 u1 = b1ok ? *(const float4*)(bp + 4) : make_float4(0,0,0,0);
        bb[0]=u0.x; bb[1]=u0.y; bb[2]=u0.z; bb[3]=u0.w;
        bb[4]=u1.x; bb[5]=u1.y; bb[6]=u1.z; bb[7]=u1.w;
    };

    auto storeS = [&](int st) {
        const int sbase = st << 9;
#pragma unroll
        for (int u = 0; u < 4; u++) {
            uint32_t hw, lw;
            split_bf16_pair(av[2*u], av[2*u+1], hw, lw);
            int w = (akb >> 1) + u;
            int j = (w & 3) ^ (arow & 3);
            int c = w >> 2;
            ((uint32_t*)&AsH[sbase + (arow << 2) + j])[c] = hw;
            ((uint32_t*)&AsL[sbase + (arow << 2) + j])[c] = lw;
        }
        {
            int w = bkrow >> 1;
            int half = bkrow & 1;
            int c = w >> 2;
            int jb = w & 3;
#pragma unroll
            for (int u = 0; u < 8; u++) {
                int col = bcol + u;
                int j = jb ^ (col & 3);
                __nv_bfloat16 h = __float2bfloat16(bb[u]);
                __nv_bfloat16 l = __float2bfloat16(bb[u] - __bfloat162float(h));
                ((__nv_bfloat16*)&BsH[sbase + (col << 2) + j])[c*2 + half] = h;
                ((__nv_bfloat16*)&BsL[sbase + (col << 2) + j])[c*2 + half] = l;
            }
        }
    };

    auto compute = [&](int st) {
        const int sbase = st << 9;
        uint32_t afH[4][4];
        uint2 bH[4], bL[4];
#pragma unroll
        for (int mt = 0; mt < 4; mt++) {
            int r = wr + mt * 16 + g;
            int j = tg ^ (r & 3);
            uint2 p0 = AsH[sbase + (r << 2) + j];
            uint2 p1 = AsH[sbase + ((r + 8) << 2) + j];
            afH[mt][0] = p0.x; afH[mt][1] = p1.x;
            afH[mt][2] = p0.y; afH[mt][3] = p1.y;
        }
#pragma unroll
        for (int ni = 0; ni < 4; ni++) {
            int cc = wc + ni * 8 + g;
            int j = tg ^ (cc & 3);
            bH[ni] = BsH[sbase + (cc << 2) + j];
            bL[ni] = BsL[sbase + (cc << 2) + j];
        }
#pragma unroll
        for (int ni = 0; ni < 4; ni++)
#pragma unroll
            for (int mt = 0; mt < 4; mt++)
                mma_bf16(acc[mt][ni], afH[mt], bH[ni].x, bH[ni].y);
#pragma unroll
        for (int ni = 0; ni < 4; ni++)
#pragma unroll
            for (int mt = 0; mt < 4; mt++)
                mma_bf16(acc[mt][ni], afH[mt], bL[ni].x, bL[ni].y);
#pragma unroll
        for (int mt = 0; mt < 4; mt++) {
            int r = wr + mt * 16 + g;
            int j = tg ^ (r & 3);
            uint2 p0 = AsL[sbase + (r << 2) + j];
            uint2 p1 = AsL[sbase + ((r + 8) << 2) + j];
            uint32_t afL[4] = {p0.x, p1.x, p0.y, p1.y};
#pragma unroll
            for (int ni = 0; ni < 4; ni++)
                mma_bf16(acc[mt][ni], afL, bH[ni].x, bH[ni].y);
        }
    };

    loadG(0);
    storeS(0);
    __syncthreads();

    const int nIter = K >> 4;
    for (int it = 0; it < nIter; it++) {
        int st = it & 1;
        bool hasNext = (it + 1 < nIter);
        if (hasNext) loadG((it + 1) * 16);
        compute(st);
        if (hasNext) storeS(st ^ 1);
        __syncthreads();
    }

#pragma unroll
    for (int mt = 0; mt < 4; mt++) {
#pragma unroll
        for (int ni = 0; ni < 4; ni++) {
            int r = row0 + wr + mt * 16 + g;
            int c = colbase + wc + ni * 8 + tg * 2;
            if (c + 2 <= Mloc) {
                *(float2*)&a_.C[(size_t)r * Mloc + c] =
                    make_float2(acc[mt][ni][0], acc[mt][ni][1]);
                *(float2*)&a_.C[(size_t)(r + 8) * Mloc + c] =
                    make_float2(acc[mt][ni][2], acc[mt][ni][3]);
            }
        }
    }
}

// ---------------- fused QKVG projection: one launch, grid (19, 16) ----------
__global__ void __launch_bounds__(256, 2)
gemm_bf3_qkvg_kernel(const float* __restrict__ x,
                     const float* __restrict__ Wq, const float* __restrict__ Wk,
                     const float* __restrict__ Wv, const float* __restrict__ Wg,
                     float* __restrict__ q, float* __restrict__ k,
                     float* __restrict__ v, float* __restrict__ gate)
{
    extern __shared__ uint2 smb[];
    BF3Args a;
    a.A = x; a.K = HID; a.row0 = blockIdx.y * 128;
    int bx = blockIdx.x;
    if (bx < 16)      { a.B = Wq; a.C = q;    a.Mloc = HQ*D; a.colbase = bx * 128; }
    else if (bx == 16){ a.B = Wk; a.C = k;    a.Mloc = D;    a.colbase = 0; }
    else if (bx == 17){ a.B = Wv; a.C = v;    a.Mloc = D;    a.colbase = 0; }
    else              { a.B = Wg; a.C = gate; a.Mloc = HQ*3; a.colbase = 0; }
    gemm_bf3_body(a, smb);
}

// ---------------- plain 3xBF16 GEMM (cmp scores) ----------------------------
__global__ void __launch_bounds__(256, 2)
gemm_bf3_kernel(const float* __restrict__ A, const float* __restrict__ B,
                float* __restrict__ C, int K, int M)
{
    extern __shared__ uint2 smb[];
    BF3Args a;
    a.A = A; a.B = B; a.C = C; a.K = K; a.Mloc = M;
    a.colbase = blockIdx.x * 128; a.row0 = blockIdx.y * 128;
    gemm_bf3_body(a, smb);
}

// ---------------- 1-term tf32 GEMM (continuous paths) ------------------------
__global__ void __launch_bounds__(256, 2)
gemm_t1_kernel(const float* __restrict__ A, const float* __restrict__ B,
               float* __restrict__ C, int K, int M)
{
    extern __shared__ uint2 sm[];
    uint2* AsH = sm;
    uint2* BsH = sm + 2048;

    const int tid = threadIdx.x;
    const int wid = tid >> 5, lane = tid & 31;
    const int row0 = blockIdx.y * 128, col0 = blockIdx.x * 128;
    const int wr = (wid & 1) * 64, wc = (wid >> 1) * 32;
    const int g = lane >> 2, tg = lane & 3;

    const int arow = tid >> 1, akb = (tid & 1) * 8;
    const int bkrow = tid >> 4, bcol = (tid & 15) * 8;
    const bool bval0 = (col0 + bcol + 4) <= M;
    const bool bval1 = (col0 + bcol + 8) <= M;

    const float* Ag = A + (size_t)(row0 + arow) * K + akb;
    const float* Bg = B + (size_t)bkrow * M + col0 + bcol;

    float acc[4][4][4];
#pragma unroll
    for (int mt = 0; mt < 4; mt++)
#pragma unroll
        for (int ni = 0; ni < 4; ni++)
#pragma unroll
            for (int r = 0; r < 4; r++) acc[mt][ni][r] = 0.f;

    float av[8], bb[8];

    auto loadG = [&](int k0) {
        float4 t0 = *(const float4*)(Ag + k0);
        float4 t1 = *(const float4*)(Ag + k0 + 4);
        av[0]=t0.x; av[1]=t0.y; av[2]=t0.z; av[3]=t0.w;
        av[4]=t1.x; av[5]=t1.y; av[6]=t1.z; av[7]=t1.w;
        const float* bp = Bg + (size_t)k0 * M;
        float4 u0 = bval0 ? *(const float4*)bp       : make_float4(0,0,0,0);
        float4 u1 = bval1 ? *(const float4*)(bp + 4) : make_float4(0,0,0,0);
        bb[0]=u0.x; bb[1]=u0.y; bb[2]=u0.z; bb[3]=u0.w;
        bb[4]=u1.x; bb[5]=u1.y; bb[6]=u1.z; bb[7]=u1.w;
    };

    auto storeS = [&](int st) {
        const int sbase = st << 10;
#pragma unroll
        for (int u = 0; u < 8; u++) {
            int k = akb + u;
            int p = ((k >> 3) << 2) | (k & 3);
            int c = (k >> 2) & 1;
            int ph = p ^ ((arow & 3) << 1);
            ((uint32_t*)&AsH[sbase + (arow << 3) + ph])[c] = f2tf32(av[u]);
        }
        {
            int k = bkrow;
            int p = ((k >> 3) << 2) | (k & 3);
            int c = (k >> 2) & 1;
#pragma unroll
            for (int u = 0; u < 8; u++) {
                int col = bcol + u;
                int ph = p ^ ((col & 3) << 1);
                ((uint32_t*)&BsH[sbase + (col << 3) + ph])[c] = f2tf32(bb[u]);
            }
        }
    };

    auto compute = [&](int st) {
        const int sbase = st << 10;
#pragma unroll
        for (int hb = 0; hb < 2; hb++) {
            const int ph = (hb * 4 + tg) ^ ((g & 3) << 1);
            uint32_t afH[4][4];
            uint2 bH[4];
#pragma unroll
            for (int mt = 0; mt < 4; mt++) {
                int r = wr + mt * 16 + g;
                uint2 p0 = AsH[sbase + (r << 3) + ph];
                uint2 p1 = AsH[sbase + ((r + 8) << 3) + ph];
                afH[mt][0] = p0.x; afH[mt][1] = p1.x;
                afH[mt][2] = p0.y; afH[mt][3] = p1.y;
            }
#pragma unroll
            for (int ni = 0; ni < 4; ni++) {
                int cc = wc + ni * 8 + g;
                bH[ni] = BsH[sbase + (cc << 3) + ph];
            }
#pragma unroll
            for (int ni = 0; ni < 4; ni++)
#pragma unroll
                for (int mt = 0; mt < 4; mt++)
                    mma_tf32(acc[mt][ni], afH[mt], bH[ni].x, bH[ni].y);
        }
    };

    loadG(0);
    storeS(0);
    __syncthreads();

    const int nIter = K >> 4;
    for (int it = 0; it < nIter; it++) {
        int st = it & 1;
        bool hasNext = (it + 1 < nIter);
        if (hasNext) loadG((it + 1) * 16);
        compute(st);
        if (hasNext) storeS(st ^ 1);
        __syncthreads();
    }

#pragma unroll
    for (int mt = 0; mt < 4; mt++) {
#pragma unroll
        for (int ni = 0; ni < 4; ni++) {
            int r = row0 + wr + mt * 16 + g;
            int c = col0 + wc + ni * 8 + tg * 2;
            if (c + 2 <= M) {
                *(float2*)&C[(size_t)r * M + c] =
                    make_float2(acc[mt][ni][0], acc[mt][ni][1]);
                *(float2*)&C[(size_t)(r + 8) * M + c] =
                    make_float2(acc[mt][ni][2], acc[mt][ni][3]);
            }
        }
    }
}

// ---------------- compressed k/v (pre-RoPE) --------------------------------
__global__ void compress_kernel(const float* __restrict__ k,
                                const float* __restrict__ v,
                                const float* __restrict__ pe,
                                float* __restrict__ ck,
                                float* __restrict__ cv)
{
    int m = blockIdx.x;
    int d = threadIdx.x;
    float sk = 0.f, sv = 0.f;
#pragma unroll 8
    for (int i = 0; i < KS; i++) {
        sk += k[(m*KS + i)*D + d] + pe[i*D + d];
        sv += v[(m*KS + i)*D + d];
    }
    ck[m*D + d] = sk * (1.f/KS);
    cv[m*D + d] = sv * (1.f/KS);
}

// ---------------- RoPE (in place) ------------------------------------------
__global__ void rope_kernel(float* __restrict__ x, int heads, int pos_stride)
{
    int row = blockIdx.x;
    int d   = threadIdx.x;
    float inv = powf(10000.f, -(float)d / 64.f);
    float ang = (float)(row * pos_stride) * inv;
    float c = cosf(ang), s = sinf(ang);
    for (int h = 0; h < heads; h++) {
        float* p = x + ((size_t)row*heads + h) * D;
        float x1 = p[d], x2 = p[d + 64];
        p[d]      = x1 * c - x2 * s;
        p[d + 64] = x2 * c + x1 * s;
    }
}

// ---------------- ck transpose ----------------------------------------------
__global__ void transpose_ck_kernel(const float* __restrict__ ck,
                                    float* __restrict__ ckT)
{
    int i = blockIdx.x * 256 + threadIdx.x;
    int m = i >> 7, d = i & 127;
    ckT[d*NC + m] = ck[m*D + d];
}

// ---------------- cmp softmax / mask / block-score --------------------------
__global__ void cmp_softmax_kernel(float* __restrict__ sc,
                                   float* __restrict__ blks)
{
    int n = blockIdx.x;
    __shared__ float pcs[HQ][NC];
    int tid = threadIdx.x;

    float* base = sc + (size_t)n * HQ * NC;
    {
        int h = tid >> 4, m4 = (tid & 15) * 4;
        float4 vv = *(float4*)&base[h*NC + m4];
        float s[4] = {vv.x, vv.y, vv.z, vv.w};
#pragma unroll
        for (int u = 0; u < 4; u++) {
            int m = m4 + u;
            bool valid = (n >= m*STRIDE + KS - 1);
            s[u] = valid ? s[u] * SCALE : NEGF;
        }
        pcs[h][m4+0] = s[0]; pcs[h][m4+1] = s[1];
        pcs[h][m4+2] = s[2]; pcs[h][m4+3] = s[3];
    }
    __syncthreads();

    {
        int w = tid >> 5, l = tid & 31;
        for (int h = w; h < HQ; h += 8) {
            float a = pcs[h][l], b = pcs[h][l + 32];
            float mx = fmaxf(a, b);
#pragma unroll
            for (int o = 16; o > 0; o >>= 1) mx = fmaxf(mx, __shfl_xor_sync(0xffffffff, mx, o));
            float ea = __expf(a - mx), eb = __expf(b - mx);
            float s = ea + eb;
#pragma unroll
            for (int o = 16; o > 0; o >>= 1) s += __shfl_xor_sync(0xffffffff, s, o);
            float inv = 1.f / s;
            bool va = (n >= l*STRIDE + KS - 1);
            bool vb = (n >= (l+32)*STRIDE + KS - 1);
            pcs[h][l]      = va ? ea * inv : 0.f;
            pcs[h][l + 32] = vb ? eb * inv : 0.f;
        }
    }
    __syncthreads();

    for (int m = tid; m < NC; m += 256) {
        float s = 0.f;
        for (int h = 0; h < HQ; h++) s += pcs[h][m];
        blks[(size_t)n*NC + m] = s;
    }
    {
        int h = tid >> 4, m4 = (tid & 15) * 4;
        *(float4*)&base[h*NC + m4] =
            make_float4(pcs[h][m4], pcs[h][m4+1], pcs[h][m4+2], pcs[h][m4+3]);
    }
}

// ---------------- top-k selection (warp per token) --------------------------
__global__ void topk_kernel(const float* __restrict__ blks, int* __restrict__ topk)
{
    int gidx = blockIdx.x * blockDim.x + threadIdx.x;
    int n = gidx >> 5;
    int lane = threadIdx.x & 31;
    if (n >= N_TOK) return;
    int tb = n / BSZ;
    int m0 = lane, m1 = lane + 32;
    float s0 = blks[(size_t)n*NC + m0];
    float s1 = blks[(size_t)n*NC + m1];
    if (m0 > tb) s0 = NEGF;
    if (m0 < 1 || (m0 <= tb && m0 > tb - 2)) s0 = 1e30f;
    if (m1 > tb) s1 = NEGF;
    if (m1 < 1 || (m1 <= tb && m1 > tb - 2)) s1 = 1e30f;
#pragma unroll
    for (int j = 0; j < TOPK; j++) {
        float bv; int bi;
        if (s0 >= s1) { bv = s0; bi = m0; } else { bv = s1; bi = m1; }
#pragma unroll
        for (int o = 16; o > 0; o >>= 1) {
            float ov = __shfl_down_sync(0xffffffff, bv, o);
            int   oi = __shfl_down_sync(0xffffffff, bi, o);
            if (ov > bv || (ov == bv && oi < bi)) { bv = ov; bi = oi; }
        }
        bi = __shfl_sync(0xffffffff, bi, 0);
        if (lane == 0) topk[n*TOPK + j] = bi;
        if (bi == m0) s0 = -FLT_MAX;
        if (bi == m1) s1 = -FLT_MAX;
    }
}

// ============ sel attention (SIMT, dual K/V buffers, 4 syncs/tile) ==========
#define KVP 132

__device__ __forceinline__ void attn_softmax_update(
    float* sc, float* mS, float* lS, float* fS, int tid)
{
    int h = tid >> 4, t = tid & 15;
    float4 sv = *(float4*)&sc[h*64 + t*4];
    float pm = fmaxf(fmaxf(sv.x, sv.y), fmaxf(sv.z, sv.w));
#pragma unroll
    for (int o = 1; o < 16; o <<= 1) pm = fmaxf(pm, __shfl_xor_sync(0xffffffff, pm, o));
    float mOld = mS[h];
    float mNew = fmaxf(mOld, pm);
    float4 p;
    p.x = __expf(sv.x - mNew); p.y = __expf(sv.y - mNew);
    p.z = __expf(sv.z - mNew); p.w = __expf(sv.w - mNew);
    *(float4*)&sc[h*64 + t*4] = p;
    float ps = p.x + p.y + p.z + p.w;
#pragma unroll
    for (int o = 1; o < 16; o <<= 1) ps += __shfl_xor_sync(0xffffffff, ps, o);
    if (t == 0) {
        float f = __expf(mOld - mNew);
        fS[h] = f;
        lS[h] = lS[h] * f + ps;
        mS[h] = mNew;
    }
}

__global__ void __launch_bounds__(256, 2)
sel_attn_kernel(const float* __restrict__ q, const float* __restrict__ k,
                const float* __restrict__ v, const int* __restrict__ topk,
                float* __restrict__ out)
{
    extern __shared__ float smem_sel[];
    float* qs = smem_sel;                  // HQ*D = 2048
    float* kb = qs + HQ*D;                 // 64*KVP
    float* vb = kb + 64*KVP;               // 64*KVP
    float* sc = vb + 64*KVP;               // HQ*64
    float* mS = sc + HQ*64;                // 16
    float* lS = mS + HQ;                   // 16
    float* fS = lS + HQ;                   // 16
    int*  posA = (int*)(fS + HQ);          // 256

    int n = blockIdx.x;
    int tid = threadIdx.x;

    for (int e = tid; e < HQ*D/4; e += 256)
        ((float4*)qs)[e] = ((const float4*)(q + (size_t)n*HQ*D))[e];
    if (tid < HQ) { mS[tid] = -FLT_MAX; lS[tid] = 0.f; }
    posA[tid] = topk[n*TOPK + (tid >> 5)] * BSZ + (tid & 31);

    int h  = tid >> 4;
    int d0 = (tid & 15) * 8;
    float acc[8];
#pragma unroll
    for (int i = 0; i < 8; i++) acc[i] = 0.f;
    __syncthreads();

    for (int t0 = 0; t0 < TOPK*BSZ; t0 += 64) {
        // gather K AND V tiles together (double MLP; V latency hidden by scores)
        for (int e = tid; e < 64*32; e += 256) {
            int row = e >> 5, c = e & 31;
            size_t pos = (size_t)posA[t0 + row];
            *(float4*)&kb[row*KVP + c*4] = ((const float4*)(k + pos*D))[c];
            *(float4*)&vb[row*KVP + c*4] = ((const float4*)(v + pos*D))[c];
        }
        __syncthreads();
        {
            int jj = tid & 63;
            int hb = (tid >> 6) * 4;
            bool valid = posA[t0 + jj] <= n;
            if (valid) {
                const float4* kr = (const float4*)(kb + jj*KVP);
                const float4* q0 = (const float4*)(qs + (hb+0)*D);
                const float4* q1 = (const float4*)(qs + (hb+1)*D);
                const float4* q2 = (const float4*)(qs + (hb+2)*D);
                const float4* q3 = (const float4*)(qs + (hb+3)*D);
                float s0=0.f,s1=0.f,s2=0.f,s3=0.f;
#pragma unroll
                for (int c = 0; c < 32; c++) {
                    float4 kk = kr[c];
                    float4 a;
                    a = q0[c]; s0 += a.x*kk.x + a.y*kk.y + a.z*kk.z + a.w*kk.w;
                    a = q1[c]; s1 += a.x*kk.x + a.y*kk.y + a.z*kk.z + a.w*kk.w;
                    a = q2[c]; s2 += a.x*kk.x + a.y*kk.y + a.z*kk.z + a.w*kk.w;
                    a = q3[c]; s3 += a.x*kk.x + a.y*kk.y + a.z*kk.z + a.w*kk.w;
                }
                sc[(hb+0)*64+jj]=s0*SCALE; sc[(hb+1)*64+jj]=s1*SCALE;
                sc[(hb+2)*64+jj]=s2*SCALE; sc[(hb+3)*64+jj]=s3*SCALE;
            } else {
                sc[(hb+0)*64+jj]=NEGF; sc[(hb+1)*64+jj]=NEGF;
                sc[(hb+2)*64+jj]=NEGF; sc[(hb+3)*64+jj]=NEGF;
            }
        }
        __syncthreads();
        attn_softmax_update(sc, mS, lS, fS, tid);
        __syncthreads();
        {
            float f = fS[h];
#pragma unroll
            for (int i = 0; i < 8; i++) acc[i] *= f;
            const float* scp = sc + h*64;
            for (int j = 0; j < 64; j++) {
                float p = scp[j];
                float4 v0 = *(const float4*)&vb[j*KVP + d0];
                float4 v1 = *(const float4*)&vb[j*KVP + d0 + 4];
                acc[0] += p*v0.x; acc[1] += p*v0.y; acc[2] += p*v0.z; acc[3] += p*v0.w;
                acc[4] += p*v1.x; acc[5] += p*v1.y; acc[6] += p*v1.z; acc[7] += p*v1.w;
            }
        }
        __syncthreads();
    }
    float inv = 1.f / lS[h];
    float4 o0 = make_float4(acc[0]*inv, acc[1]*inv, acc[2]*inv, acc[3]*inv);
    float4 o1 = make_float4(acc[4]*inv, acc[5]*inv, acc[6]*inv, acc[7]*inv);
    *(float4*)&out[((size_t)n*HQ + h)*D + d0]     = o0;
    *(float4*)&out[((size_t)n*HQ + h)*D + d0 + 4] = o1;
}

// ================= window attention via 1-term tf32 tensor cores ============
__global__ void __launch_bounds__(256, 2)
win_mma_kernel(const float* __restrict__ q, const float* __restrict__ k,
               const float* __restrict__ v, float* __restrict__ out)
{
    extern __shared__ uint2 smw[];
    uint2* Qh = smw;
    uint2* Bh = smw + 4096;
    uint2* Ph = smw + 8192;
    float* stats = (float*)(smw + 10240);
    float* mS   = stats;
    float* lS   = stats + 64;
    float* fS   = stats + 128;
    float* pmax = stats + 192;
    float* psum = stats + 320;

    const int tid = threadIdx.x;
    const int wid = tid >> 5, lane = tid & 31;
    const int g = lane >> 2, tg = lane & 3;
    const int qtile0 = (gridDim.x - 1 - blockIdx.x) * 64;
    const int h = blockIdx.y;

    for (int e = tid; e < 64*32; e += 256) {
        int row = e >> 5, c4 = e & 31;
        float4 vq = *(const float4*)&q[(((size_t)(qtile0 + row))*HQ + h)*D + c4*4];
        float qv[4] = {vq.x, vq.y, vq.z, vq.w};
#pragma unroll
        for (int u = 0; u < 4; u++) {
            int d = c4*4 + u;
            int ch = d >> 4, kk = d & 15;
            int p = ((kk >> 3) << 2) | (kk & 3);
            int cc = (kk >> 2) & 1;
            int ph = p ^ ((row & 3) << 1);
            ((uint32_t*)&Qh[ch*512 + (row << 3) + ph])[cc] = f2tf32(qv[u]);
        }
    }
    if (tid < 64) { mS[tid] = -3.0e38f; lS[tid] = 0.f; }

    const int mtS = wid & 3, cg = wid >> 2;
    const int mtP = wid & 3, dh = wid >> 2;

    float oacc[8][4];
#pragma unroll
    for (int ni = 0; ni < 8; ni++)
#pragma unroll
        for (int r = 0; r < 4; r++) oacc[ni][r] = 0.f;

    int klo = qtile0 - WIN; if (klo < 0) klo = 0;
    __syncthreads();

    for (int kt = klo; kt < qtile0 + 64; kt += 64) {
        for (int e = tid; e < 64*32; e += 256) {
            int key = e >> 5, c4 = e & 31;
            float4 vk = *(const float4*)&k[((size_t)(kt + key))*D + c4*4];
            float kv4[4] = {vk.x, vk.y, vk.z, vk.w};
#pragma unroll
            for (int u = 0; u < 4; u++) {
                int d = c4*4 + u;
                int ch = d >> 4, kk = d & 15;
                int p = ((kk >> 3) << 2) | (kk & 3);
                int cc = (kk >> 2) & 1;
                int ph = p ^ ((key & 3) << 1);
                ((uint32_t*)&Bh[ch*512 + (key << 3) + ph])[cc] = f2tf32(kv4[u]);
            }
        }
        __syncthreads();

        float sacc[4][4];
#pragma unroll
        for (int ni = 0; ni < 4; ni++)
#pragma unroll
            for (int r = 0; r < 4; r++) sacc[ni][r] = 0.f;

#pragma unroll
        for (int ch = 0; ch < 8; ch++) {
#pragma unroll
            for (int hb = 0; hb < 2; hb++) {
                const int ph = (hb*4 + tg) ^ ((g & 3) << 1);
                int r = mtS*16 + g;
                uint2 a0 = Qh[ch*512 + (r << 3) + ph];
                uint2 a1 = Qh[ch*512 + ((r + 8) << 3) + ph];
                uint32_t afH[4] = {a0.x, a1.x, a0.y, a1.y};
#pragma unroll
                for (int ni = 0; ni < 4; ni++) {
                    int col = cg*32 + ni*8 + g;
                    uint2 bH = Bh[ch*512 + (col << 3) + ph];
                    mma_tf32(sacc[ni], afH, bH.x, bH.y);
                }
            }
        }

        const int rA = qtile0 + mtS*16 + g;
        const int rB = rA + 8;
        float m1 = -3.0e38f, m2 = -3.0e38f;
#pragma unroll
        for (int ni = 0; ni < 4; ni++) {
            int key0 = kt + cg*32 + ni*8 + tg*2;
#pragma unroll
            for (int i = 0; i < 4; i++) {
                int key = key0 + (i & 1);
                int qp = (i < 2) ? rA : rB;
                float s = sacc[ni][i] * SCALE;
                bool valid = (key <= qp) && (key >= qp - WIN);
                s = valid ? s : NEGF;
                sacc[ni][i] = s;
                if (i < 2) m1 = fmaxf(m1, s); else m2 = fmaxf(m2, s);
            }
        }
#pragma unroll
        for (int o = 1; o < 4; o <<= 1) {
            m1 = fmaxf(m1, __shfl_xor_sync(0xffffffff, m1, o));
            m2 = fmaxf(m2, __shfl_xor_sync(0xffffffff, m2, o));
        }
        int rlA = mtS*16 + g, rlB = rlA + 8;
        if (tg == 0) { pmax[rlA*2 + cg] = m1; pmax[rlB*2 + cg] = m2; }
        __syncthreads();

        float mnA = fmaxf(mS[rlA], fmaxf(pmax[rlA*2], pmax[rlA*2+1]));
        float mnB = fmaxf(mS[rlB], fmaxf(pmax[rlB*2], pmax[rlB*2+1]));
        float sumA = 0.f, sumB = 0.f;
#pragma unroll
        for (int ni = 0; ni < 4; ni++) {
#pragma unroll
            for (int i = 0; i < 4; i++) {
                float s = sacc[ni][i];
                float mn = (i < 2) ? mnA : mnB;
                float p = (s <= -1e29f) ? 0.f : __expf(s - mn);
                if (i < 2) sumA += p; else sumB += p;
                int cloc = cg*32 + ni*8 + tg*2 + (i & 1);
                int ch = cloc >> 4, kk = cloc & 15;
                int pp = ((kk >> 3) << 2) | (kk & 3);
                int cc = (kk >> 2) & 1;
                int rl = (i < 2) ? rlA : rlB;
                int ph = pp ^ ((rl & 3) << 1);
                ((uint32_t*)&Ph[ch*512 + (rl << 3) + ph])[cc] = f2tf32(p);
            }
        }
#pragma unroll
        for (int o = 1; o < 4; o <<= 1) {
            sumA += __shfl_xor_sync(0xffffffff, sumA, o);
            sumB += __shfl_xor_sync(0xffffffff, sumB, o);
        }
        if (tg == 0) { psum[rlA*2 + cg] = sumA; psum[rlB*2 + cg] = sumB; }

        for (int e = tid; e < 64*32; e += 256) {
            int key = e >> 5, c4 = e & 31;
            float4 vv = *(const float4*)&v[((size_t)(kt + key))*D + c4*4];
            float v4[4] = {vv.x, vv.y, vv.z, vv.w};
            int chv = key >> 4, kkv = key & 15;
            int pv = ((kkv >> 3) << 2) | (kkv & 3);
            int ccv = (kkv >> 2) & 1;
#pragma unroll
            for (int u = 0; u < 4; u++) {
                int d = c4*4 + u;
                int phv = pv ^ ((d & 3) << 1);
                ((uint32_t*)&Bh[chv*1024 + (d << 3) + phv])[ccv] = f2tf32(v4[u]);
            }
        }
        __syncthreads();

        if (tid < 64) {
            float mo = mS[tid];
            float mn = fmaxf(mo, fmaxf(pmax[tid*2], pmax[tid*2+1]));
            float f = __expf(mo - mn);
            lS[tid] = lS[tid] * f + psum[tid*2] + psum[tid*2+1];
            mS[tid] = mn;
            fS[tid] = f;
        }
        __syncthreads();

        {
            int rl1 = mtP*16 + g, rl2 = rl1 + 8;
            float f1 = fS[rl1], f2 = fS[rl2];
#pragma unroll
            for (int ni = 0; ni < 8; ni++) {
                oacc[ni][0] *= f1; oacc[ni][1] *= f1;
                oacc[ni][2] *= f2; oacc[ni][3] *= f2;
            }
#pragma unroll
            for (int ch = 0; ch < 4; ch++) {
#pragma unroll
                for (int hb = 0; hb < 2; hb++) {
                    const int ph = (hb*4 + tg) ^ ((g & 3) << 1);
                    int r = mtP*16 + g;
                    uint2 a0 = Ph[ch*512 + (r << 3) + ph];
                    uint2 a1 = Ph[ch*512 + ((r + 8) << 3) + ph];
                    uint32_t afH[4] = {a0.x, a1.x, a0.y, a1.y};
#pragma unroll
                    for (int ni = 0; ni < 8; ni++) {
                        int col = dh*64 + ni*8 + g;
                        uint2 bH = Bh[ch*1024 + (col << 3) + ph];
                        mma_tf32(oacc[ni], afH, bH.x, bH.y);
                    }
                }
            }
        }
        __syncthreads();
    }

    {
        int rl1 = mtP*16 + g, rl2 = rl1 + 8;
        float i1 = 1.f / lS[rl1], i2 = 1.f / lS[rl2];
        size_t b1 = ((size_t)(qtile0 + rl1)*HQ + h)*D;
        size_t b2 = ((size_t)(qtile0 + rl2)*HQ + h)*D;
#pragma unroll
        for (int ni = 0; ni < 8; ni++) {
            int d = dh*64 + ni*8 + tg*2;
            *(float2*)&out[b1 + d] = make_float2(oacc[ni][0]*i1, oacc[ni][1]*i1);
            *(float2*)&out[b2 + d] = make_float2(oacc[ni][2]*i2, oacc[ni][3]*i2);
        }
    }
}

// ---------------- gate combine ---------------------------------------------
__global__ void combine_kernel(const float* __restrict__ gbuf,
                               const float* __restrict__ cmp,
                               const float* __restrict__ sp,
                               const float* __restrict__ sw,
                               float* __restrict__ att)
{
    size_t idx = (size_t)blockIdx.x * 256 + threadIdx.x;
    int n = (int)(idx >> 11);
    int hd = (int)(idx & 2047);
    int h = hd >> 7;
    const float* g = gbuf + (size_t)n*HQ*3 + h*3;
    float g0 = 1.f / (1.f + __expf(-g[0]));
    float g1 = 1.f / (1.f + __expf(-g[1]));
    float g2 = 1.f / (1.f + __expf(-g[2]));
    att[idx] = g0 * cmp[idx] + g1 * sp[idx] + g2 * sw[idx];
}

// ---------------- launcher with stream fork/join -----------------------------
extern "C" void kernel_launch(void* const* d_in, const int* in_sizes, int n_in,
                              void* d_out, int out_size)
{
    const float* x  = (const float*)d_in[0];
    const float* Wq = (const float*)d_in[2];
    const float* Wk = (const float*)d_in[3];
    const float* Wv = (const float*)d_in[4];
    const float* Wo = (const float*)d_in[5];
    const float* Wg = (const float*)d_in[6];
    const float* pe = (const float*)d_in[7];
    float* out = (float*)d_out;

    float *q, *k, *v, *ck, *ckT, *cv, *blks, *cmp, *sp, *sw, *gate, *att, *part;
    int* tk;
    cudaGetSymbolAddress((void**)&q,    g_q);
    cudaGetSymbolAddress((void**)&k,    g_k);
    cudaGetSymbolAddress((void**)&v,    g_v);
    cudaGetSymbolAddress((void**)&ck,   g_ck);
    cudaGetSymbolAddress((void**)&ckT,  g_ckT);
    cudaGetSymbolAddress((void**)&cv,   g_cv);
    cudaGetSymbolAddress((void**)&blks, g_blks);
    cudaGetSymbolAddress((void**)&tk,   g_topk);
    cudaGetSymbolAddress((void**)&cmp,  g_cmp);
    cudaGetSymbolAddress((void**)&sp,   g_sp);
    cudaGetSymbolAddress((void**)&sw,   g_sw);
    cudaGetSymbolAddress((void**)&gate, g_gate);
    cudaGetSymbolAddress((void**)&att,  g_att);
    cudaGetSymbolAddress((void**)&part, g_part);

    const int SMEMB3 = 32768;
    const int SMEM1  = 32768;
    const int SMEMW  = 10240*8 + 448*4;
    const int SMEMSEL = (HQ*D + 2*64*KVP + HQ*64 + 3*HQ)*4 + 256*4;  // 81088 B
    cudaFuncSetAttribute(gemm_bf3_qkvg_kernel, cudaFuncAttributeMaxDynamicSharedMemorySize, SMEMB3);
    cudaFuncSetAttribute(gemm_bf3_kernel, cudaFuncAttributeMaxDynamicSharedMemorySize, SMEMB3);
    cudaFuncSetAttribute(gemm_t1_kernel, cudaFuncAttributeMaxDynamicSharedMemorySize, SMEM1);
    cudaFuncSetAttribute(win_mma_kernel, cudaFuncAttributeMaxDynamicSharedMemorySize, SMEMW);
    cudaFuncSetAttribute(sel_attn_kernel, cudaFuncAttributeMaxDynamicSharedMemorySize, SMEMSEL);

    static cudaStream_t sB = nullptr, sC = nullptr;
    static cudaEvent_t evPROJ = nullptr, evQ = nullptr, evKV = nullptr,
                       evTK = nullptr, evCMP = nullptr, evSEL = nullptr;
    if (!sB) {
        cudaStreamCreateWithFlags(&sB, cudaStreamNonBlocking);
        cudaStreamCreateWithFlags(&sC, cudaStreamNonBlocking);
        cudaEventCreateWithFlags(&evPROJ, cudaEventDisableTiming);
        cudaEventCreateWithFlags(&evQ,    cudaEventDisableTiming);
        cudaEventCreateWithFlags(&evKV,   cudaEventDisableTiming);
        cudaEventCreateWithFlags(&evTK,   cudaEventDisableTiming);
        cudaEventCreateWithFlags(&evCMP,  cudaEventDisableTiming);
        cudaEventCreateWithFlags(&evSEL,  cudaEventDisableTiming);
    }

    // --- fused projections (default stream): q,k,v,gate in ONE launch -------
    gemm_bf3_qkvg_kernel<<<dim3(19, 16, 1), 256, SMEMB3>>>(
        x, Wq, Wk, Wv, Wg, q, k, v, gate);
    cudaEventRecord(evPROJ, 0);
    rope_kernel<<<N_TOK, 64>>>(q, HQ, 1);
    cudaEventRecord(evQ, 0);

    // --- spine B: compress/rope/transpose, then cmp scores -> topk ----------
    cudaStreamWaitEvent(sB, evPROJ, 0);
    compress_kernel<<<NC, D, 0, sB>>>(k, v, pe, ck, cv);
    rope_kernel<<<N_TOK, 64, 0, sB>>>(k, 1, 1);
    rope_kernel<<<NC, 64, 0, sB>>>(ck, 1, STRIDE);
    transpose_ck_kernel<<<32, 256, 0, sB>>>(ck, ckT);
    cudaEventRecord(evKV, sB);

    cudaStreamWaitEvent(sB, evQ, 0);
    gemm_bf3_kernel<<<dim3(1, 256, 1), 256, SMEMB3, sB>>>(q, ckT, part, D, NC);
    cmp_softmax_kernel<<<N_TOK, 256, 0, sB>>>(part, blks);
    topk_kernel<<<(N_TOK*32 + 255)/256, 256, 0, sB>>>(blks, tk);
    cudaEventRecord(evTK, sB);
    gemm_t1_kernel<<<dim3(1, 256, 1), 256, SMEM1, sB>>>(part, cv, cmp, NC, D);
    cudaEventRecord(evCMP, sB);

    // --- spine C: sel after topk --------------------------------------------
    cudaStreamWaitEvent(sC, evTK, 0);
    sel_attn_kernel<<<N_TOK, 256, SMEMSEL, sC>>>(q, k, v, tk, sp);
    cudaEventRecord(evSEL, sC);

    // --- spine A continues: win after k/v ready -----------------------------
    cudaStreamWaitEvent(0, evKV, 0);
    win_mma_kernel<<<dim3(32, HQ), 256, SMEMW>>>(q, k, v, sw);

    // join
    cudaStreamWaitEvent(0, evSEL, 0);
    cudaStreamWaitEvent(0, evCMP, 0);
    combine_kernel<<<(N_TOK*HQ*D)/256, 256>>>(gate, cmp, sp, sw, att);
    gemm_t1_kernel<<<dim3(16, 16, 1), 256, SMEM1>>>(att, Wo, out, HID, HID);
}